// round 1
// baseline (speedup 1.0000x reference)
#include <cuda_runtime.h>
#include <math.h>

// Problem constants
#define BB 4
#define SS 2048
#define DD 1024
#define HH 16
#define HDIM 64
#define MTOT (BB * SS)          // 8192
#define HEADTOT ((size_t)BB * HH * SS * HDIM)  // 8,388,608

// Scratch: qh (head-layout Q projection), att (head-layout attention output)
__device__ float g_qh[BB * HH * SS * HDIM];
__device__ float g_att[BB * HH * SS * HDIM];

// ---------------------------------------------------------------------------
// GEMM: Y = X @ W^T + bias.   X: [MTOT, DD] (or head-layout), W: [DD, DD] row-major,
// Y: [MTOT, DD] flat or [B,H,S,HD] head layout.
// BM=BN=64, BK=16, 256 threads, 4x4 micro-tile per thread.
// ---------------------------------------------------------------------------
template <bool IN_HEADS, bool OUT_HEADS>
__global__ void __launch_bounds__(256) gemm_bias_kernel(
    const float* __restrict__ X, const float* __restrict__ W,
    const float* __restrict__ bias, float* __restrict__ Y)
{
    __shared__ float As[16][64];
    __shared__ float Bs[16][64];

    const int m0 = blockIdx.y * 64;
    const int n0 = blockIdx.x * 64;
    const int tx = threadIdx.x;      // 0..15 (N dir)
    const int ty = threadIdx.y;      // 0..15 (M dir)
    const int tid = ty * 16 + tx;
    const int lr = tid >> 2;         // 0..63 : row within 64-row tile
    const int lc = (tid & 3) << 2;   // 0,4,8,12 : k offset

    float acc[4][4];
    #pragma unroll
    for (int i = 0; i < 4; i++)
        #pragma unroll
        for (int j = 0; j < 4; j++) acc[i][j] = 0.f;

    for (int k0 = 0; k0 < DD; k0 += 16) {
        // --- load A tile (64 rows x 16 k) ---
        float4 a4;
        {
            const int gm = m0 + lr;
            const int gk = k0 + lc;
            const float* p;
            if (IN_HEADS) {
                // X logical [m][k] lives at [b][k/64][s][k%64]
                const int bb = gm >> 11;        // / SS
                const int ss = gm & (SS - 1);
                p = X + ((((size_t)bb * HH + (gk >> 6)) * SS + ss) << 6) + (gk & 63);
            } else {
                p = X + (size_t)gm * DD + gk;
            }
            a4 = *reinterpret_cast<const float4*>(p);
        }
        // --- load B tile: Bs[k][n] = W[n0+n][k0+k] ---
        float4 b4 = *reinterpret_cast<const float4*>(W + (size_t)(n0 + lr) * DD + k0 + lc);

        As[lc + 0][lr] = a4.x; As[lc + 1][lr] = a4.y;
        As[lc + 2][lr] = a4.z; As[lc + 3][lr] = a4.w;
        Bs[lc + 0][lr] = b4.x; Bs[lc + 1][lr] = b4.y;
        Bs[lc + 2][lr] = b4.z; Bs[lc + 3][lr] = b4.w;
        __syncthreads();

        #pragma unroll
        for (int kk = 0; kk < 16; kk++) {
            float4 av = *reinterpret_cast<const float4*>(&As[kk][ty * 4]);
            float4 bv = *reinterpret_cast<const float4*>(&Bs[kk][tx * 4]);
            float a[4] = {av.x, av.y, av.z, av.w};
            float b[4] = {bv.x, bv.y, bv.z, bv.w};
            #pragma unroll
            for (int i = 0; i < 4; i++)
                #pragma unroll
                for (int j = 0; j < 4; j++)
                    acc[i][j] = fmaf(a[i], b[j], acc[i][j]);
        }
        __syncthreads();
    }

    #pragma unroll
    for (int i = 0; i < 4; i++) {
        const int gm = m0 + ty * 4 + i;
        #pragma unroll
        for (int j = 0; j < 4; j++) {
            const int gn = n0 + tx * 4 + j;
            const float v = acc[i][j] + bias[gn];
            if (OUT_HEADS) {
                const int bb = gm >> 11;
                const int ss = gm & (SS - 1);
                Y[((((size_t)bb * HH + (gn >> 6)) * SS + ss) << 6) + (gn & 63)] = v;
            } else {
                Y[(size_t)gm * DD + gn] = v;
            }
        }
    }
}

// ---------------------------------------------------------------------------
// Causal flash attention over head-layout tensors [B,H,S,HD].
// Grid (S/64, H, B). Block = 64 threads; thread t owns query row q0+t.
// K/V 64x64 tiles staged in smem; all reads are warp-broadcast LDS.128.
// Mask input is skipped: score-1e5 underflows exp to exactly 0.0 in fp32,
// identical to hard causal masking (reference uses fp32 too).
// ---------------------------------------------------------------------------
__global__ void __launch_bounds__(64) flash_kernel(
    const float* __restrict__ qh, const float* __restrict__ kh,
    const float* __restrict__ vh, float* __restrict__ oh)
{
    __shared__ float Kt[64][64];
    __shared__ float Vt[64][64];

    const int b = blockIdx.z, h = blockIdx.y, qi = blockIdx.x;
    const int t = threadIdx.x;
    const size_t hoff = ((size_t)b * HH + h) * SS * HDIM;

    // Load this thread's query row into registers
    const float* Qp = qh + hoff + (size_t)(qi * 64 + t) * HDIM;
    float q[64];
    #pragma unroll
    for (int d = 0; d < 64; d += 4) {
        float4 v4 = *reinterpret_cast<const float4*>(Qp + d);
        q[d] = v4.x; q[d + 1] = v4.y; q[d + 2] = v4.z; q[d + 3] = v4.w;
    }

    float acc[64];
    #pragma unroll
    for (int d = 0; d < 64; d++) acc[d] = 0.f;
    float mx = -INFINITY;
    float l = 0.f;

    for (int jt = 0; jt <= qi; jt++) {
        __syncthreads();  // prior iteration finished reading smem
        {
            const float* Kp = kh + hoff + (size_t)(jt * 64 + t) * HDIM;
            const float* Vp = vh + hoff + (size_t)(jt * 64 + t) * HDIM;
            #pragma unroll
            for (int d = 0; d < 64; d += 4) {
                *reinterpret_cast<float4*>(&Kt[t][d]) =
                    *reinterpret_cast<const float4*>(Kp + d);
                *reinterpret_cast<float4*>(&Vt[t][d]) =
                    *reinterpret_cast<const float4*>(Vp + d);
            }
        }
        __syncthreads();

        const int jmax = (jt == qi) ? t : 63;
        for (int j = 0; j <= jmax; j++) {
            // dot(q, K[j]) with 4 partial sums for ILP
            float s0 = 0.f, s1 = 0.f, s2 = 0.f, s3 = 0.f;
            #pragma unroll
            for (int d = 0; d < 64; d += 4) {
                float4 k4 = *reinterpret_cast<const float4*>(&Kt[j][d]);
                s0 = fmaf(q[d],     k4.x, s0);
                s1 = fmaf(q[d + 1], k4.y, s1);
                s2 = fmaf(q[d + 2], k4.z, s2);
                s3 = fmaf(q[d + 3], k4.w, s3);
            }
            const float s = ((s0 + s1) + (s2 + s3)) * 0.125f;  // 1/sqrt(64)

            float p;
            if (s > mx) {
                const float c = __expf(mx - s);   // 0 on first key (mx=-inf)
                l *= c;
                #pragma unroll
                for (int d = 0; d < 64; d++) acc[d] *= c;
                mx = s;
                p = 1.f;
            } else {
                p = __expf(s - mx);
            }
            l += p;

            #pragma unroll
            for (int d = 0; d < 64; d += 4) {
                float4 v4 = *reinterpret_cast<const float4*>(&Vt[j][d]);
                acc[d]     = fmaf(p, v4.x, acc[d]);
                acc[d + 1] = fmaf(p, v4.y, acc[d + 1]);
                acc[d + 2] = fmaf(p, v4.z, acc[d + 2]);
                acc[d + 3] = fmaf(p, v4.w, acc[d + 3]);
            }
        }
    }

    const float inv = 1.f / l;
    float* Op = oh + hoff + (size_t)(qi * 64 + t) * HDIM;
    #pragma unroll
    for (int d = 0; d < 64; d += 4) {
        float4 o4 = make_float4(acc[d] * inv, acc[d + 1] * inv,
                                acc[d + 2] * inv, acc[d + 3] * inv);
        *reinterpret_cast<float4*>(Op + d) = o4;
    }
}

// ---------------------------------------------------------------------------
// kernel_launch
// Inputs: 0=q 1=k 2=v 3=mask 4=Wq 5=bq 6=Wk 7=bk 8=Wv 9=bv 10=Wo 11=bo
// Output: [out (B,S,D)] [kh (B,H,S,HD)] [vh (B,H,S,HD)] concatenated.
// ---------------------------------------------------------------------------
extern "C" void kernel_launch(void* const* d_in, const int* in_sizes, int n_in,
                              void* d_out, int out_size)
{
    const float* q  = (const float*)d_in[0];
    const float* k  = (const float*)d_in[1];
    const float* v  = (const float*)d_in[2];
    // d_in[3] = mask : intentionally unused (hard causal masking is exact in fp32)
    const float* Wq = (const float*)d_in[4];
    const float* bq = (const float*)d_in[5];
    const float* Wk = (const float*)d_in[6];
    const float* bk = (const float*)d_in[7];
    const float* Wv = (const float*)d_in[8];
    const float* bv = (const float*)d_in[9];
    const float* Wo = (const float*)d_in[10];
    const float* bo = (const float*)d_in[11];

    float* out = (float*)d_out;
    float* khp = out + HEADTOT;        // kh output region (also attention K operand)
    float* vhp = khp + HEADTOT;        // vh output region (also attention V operand)

    float *qh_p = nullptr, *att_p = nullptr;
    cudaGetSymbolAddress((void**)&qh_p, g_qh);
    cudaGetSymbolAddress((void**)&att_p, g_att);

    dim3 blk(16, 16);
    dim3 grd(DD / 64, MTOT / 64);

    gemm_bias_kernel<false, true><<<grd, blk>>>(q, Wq, bq, qh_p);
    gemm_bias_kernel<false, true><<<grd, blk>>>(k, Wk, bk, khp);
    gemm_bias_kernel<false, true><<<grd, blk>>>(v, Wv, bv, vhp);

    flash_kernel<<<dim3(SS / 64, HH, BB), 64>>>(qh_p, khp, vhp, att_p);

    gemm_bias_kernel<true, false><<<grd, blk>>>(att_p, Wo, bo, out);
}

// round 3
// speedup vs baseline: 1.5961x; 1.5961x over previous
#include <cuda_runtime.h>
#include <math.h>
#include <stdint.h>

// Problem constants
#define BB 4
#define SS 2048
#define DD 1024
#define HH 16
#define HDIM 64
#define MTOT (BB * SS)                          // 8192
#define HEADTOT ((size_t)BB * HH * SS * HDIM)   // 8,388,608

// Scratch
__device__ float g_qh[BB * HH * SS * HDIM];
__device__ float g_att[BB * HH * SS * HDIM];

__device__ __forceinline__ uint32_t smem_u32(const void* p) {
    uint32_t a;
    asm("{ .reg .u64 t; cvta.to.shared.u64 t, %1; cvt.u32.u64 %0, t; }"
        : "=r"(a) : "l"(p));
    return a;
}

__device__ __forceinline__ uint32_t f2tf(float f) {
    uint32_t u;
    asm("cvt.rna.tf32.f32 %0, %1;" : "=r"(u) : "f"(f));
    return u;
}

// ---------------------------------------------------------------------------
// Tensor-core GEMM (mma.sync tf32): Y = X @ W^T + bias.
// X: [MTOT, DD] flat or [B,H,S,64] head layout; W: [DD, DD] row-major.
// CTA 128x128, BK=32, 256 threads = 8 warps (4m x 2n), warp tile 32x64.
// Double-buffered cp.async pipeline; smem stride 36 floats (conflict-free).
// ---------------------------------------------------------------------------
#define GSTRIDE 36
#define GTILEF (128 * GSTRIDE)
#define GSMEM_BYTES (2 * 2 * GTILEF * 4)   // 73728

template <bool IN_HEADS, bool OUT_HEADS>
__global__ void __launch_bounds__(256) gemm_mma(
    const float* __restrict__ X, const float* __restrict__ W,
    const float* __restrict__ bias, float* __restrict__ Y)
{
    extern __shared__ float sm[];
    const int tid = threadIdx.x;
    const int wid = tid >> 5, lane = tid & 31;
    const int g = lane >> 2, t = lane & 3;
    const int m0 = blockIdx.y * 128, n0 = blockIdx.x * 128;
    const int wm0 = (wid >> 1) * 32, wn0 = (wid & 1) * 64;

    float c[2][8][4];
    #pragma unroll
    for (int i = 0; i < 2; i++)
        #pragma unroll
        for (int j = 0; j < 8; j++)
            #pragma unroll
            for (int r = 0; r < 4; r++) c[i][j][r] = 0.f;

    auto issue_loads = [&](int k0, int s) {
        float* As = sm + s * 2 * GTILEF;
        float* Bs = As + GTILEF;
        #pragma unroll
        for (int it = 0; it < 4; it++) {
            const int idx = it * 256 + tid;
            const int row = idx >> 3;
            const int c4  = idx & 7;
            const int gk  = k0 + c4 * 4;
            const float* pa;
            if (IN_HEADS) {
                const int gm = m0 + row;
                const int bb_ = gm >> 11;
                const int ss_ = gm & (SS - 1);
                pa = X + ((((size_t)bb_ * HH + (gk >> 6)) * SS + ss_) << 6) + (gk & 63);
            } else {
                pa = X + (size_t)(m0 + row) * DD + gk;
            }
            const uint32_t da = smem_u32(As + row * GSTRIDE + c4 * 4);
            asm volatile("cp.async.cg.shared.global [%0], [%1], 16;"
                         :: "r"(da), "l"(pa));
            const float* pb = W + (size_t)(n0 + row) * DD + gk;
            const uint32_t db = smem_u32(Bs + row * GSTRIDE + c4 * 4);
            asm volatile("cp.async.cg.shared.global [%0], [%1], 16;"
                         :: "r"(db), "l"(pb));
        }
        asm volatile("cp.async.commit_group;" ::: "memory");
    };

    issue_loads(0, 0);
    const int NK = DD / 32;   // 32 chunks
    for (int ck = 0; ck < NK; ck++) {
        asm volatile("cp.async.wait_group 0;" ::: "memory");
        __syncthreads();
        if (ck + 1 < NK) issue_loads((ck + 1) * 32, (ck + 1) & 1);

        const float* As = sm + (ck & 1) * 2 * GTILEF;
        const float* Bs = As + GTILEF;

        #pragma unroll
        for (int ks = 0; ks < 4; ks++) {
            const int k0 = ks * 8;
            uint32_t a[2][4], b[8][2];
            #pragma unroll
            for (int i = 0; i < 2; i++) {
                const int r = wm0 + 16 * i + g;
                a[i][0] = f2tf(As[r * GSTRIDE + k0 + t]);
                a[i][1] = f2tf(As[(r + 8) * GSTRIDE + k0 + t]);
                a[i][2] = f2tf(As[r * GSTRIDE + k0 + t + 4]);
                a[i][3] = f2tf(As[(r + 8) * GSTRIDE + k0 + t + 4]);
            }
            #pragma unroll
            for (int j = 0; j < 8; j++) {
                const int cn = wn0 + 8 * j + g;
                b[j][0] = f2tf(Bs[cn * GSTRIDE + k0 + t]);
                b[j][1] = f2tf(Bs[cn * GSTRIDE + k0 + t + 4]);
            }
            #pragma unroll
            for (int i = 0; i < 2; i++)
                #pragma unroll
                for (int j = 0; j < 8; j++) {
                    asm volatile(
                        "mma.sync.aligned.m16n8k8.row.col.f32.tf32.tf32.f32 "
                        "{%0,%1,%2,%3}, {%4,%5,%6,%7}, {%8,%9}, {%0,%1,%2,%3};"
                        : "+f"(c[i][j][0]), "+f"(c[i][j][1]),
                          "+f"(c[i][j][2]), "+f"(c[i][j][3])
                        : "r"(a[i][0]), "r"(a[i][1]), "r"(a[i][2]), "r"(a[i][3]),
                          "r"(b[j][0]), "r"(b[j][1]));
                }
        }
        __syncthreads();
    }

    // Epilogue: c0,c1 -> (row, 2t),(row, 2t+1); c2,c3 -> row+8.
    #pragma unroll
    for (int i = 0; i < 2; i++) {
        const int r0 = m0 + wm0 + 16 * i + g;
        const int r1 = r0 + 8;
        #pragma unroll
        for (int j = 0; j < 8; j++) {
            const int gn = n0 + wn0 + 8 * j + 2 * t;
            const float bx = __ldg(bias + gn);
            const float by = __ldg(bias + gn + 1);
            float2 o0 = make_float2(c[i][j][0] + bx, c[i][j][1] + by);
            float2 o1 = make_float2(c[i][j][2] + bx, c[i][j][3] + by);
            if (OUT_HEADS) {
                const int hb = gn >> 6, hc = gn & 63;
                {
                    const int bb_ = r0 >> 11, ss_ = r0 & (SS - 1);
                    *reinterpret_cast<float2*>(
                        Y + ((((size_t)bb_ * HH + hb) * SS + ss_) << 6) + hc) = o0;
                }
                {
                    const int bb_ = r1 >> 11, ss_ = r1 & (SS - 1);
                    *reinterpret_cast<float2*>(
                        Y + ((((size_t)bb_ * HH + hb) * SS + ss_) << 6) + hc) = o1;
                }
            } else {
                *reinterpret_cast<float2*>(Y + (size_t)r0 * DD + gn) = o0;
                *reinterpret_cast<float2*>(Y + (size_t)r1 * DD + gn) = o1;
            }
        }
    }
}

// ---------------------------------------------------------------------------
// Causal flash attention (unchanged from R1 — passes at 2.33 ms).
// ---------------------------------------------------------------------------
__global__ void __launch_bounds__(64) flash_kernel(
    const float* __restrict__ qh, const float* __restrict__ kh,
    const float* __restrict__ vh, float* __restrict__ oh)
{
    __shared__ float Kt[64][64];
    __shared__ float Vt[64][64];

    const int b = blockIdx.z, h = blockIdx.y, qi = blockIdx.x;
    const int t = threadIdx.x;
    const size_t hoff = ((size_t)b * HH + h) * SS * HDIM;

    const float* Qp = qh + hoff + (size_t)(qi * 64 + t) * HDIM;
    float q[64];
    #pragma unroll
    for (int d = 0; d < 64; d += 4) {
        float4 v4 = *reinterpret_cast<const float4*>(Qp + d);
        q[d] = v4.x; q[d + 1] = v4.y; q[d + 2] = v4.z; q[d + 3] = v4.w;
    }

    float acc[64];
    #pragma unroll
    for (int d = 0; d < 64; d++) acc[d] = 0.f;
    float mx = -INFINITY;
    float l = 0.f;

    for (int jt = 0; jt <= qi; jt++) {
        __syncthreads();
        {
            const float* Kp = kh + hoff + (size_t)(jt * 64 + t) * HDIM;
            const float* Vp = vh + hoff + (size_t)(jt * 64 + t) * HDIM;
            #pragma unroll
            for (int d = 0; d < 64; d += 4) {
                *reinterpret_cast<float4*>(&Kt[t][d]) =
                    *reinterpret_cast<const float4*>(Kp + d);
                *reinterpret_cast<float4*>(&Vt[t][d]) =
                    *reinterpret_cast<const float4*>(Vp + d);
            }
        }
        __syncthreads();

        const int jmax = (jt == qi) ? t : 63;
        for (int j = 0; j <= jmax; j++) {
            float s0 = 0.f, s1 = 0.f, s2 = 0.f, s3 = 0.f;
            #pragma unroll
            for (int d = 0; d < 64; d += 4) {
                float4 k4 = *reinterpret_cast<const float4*>(&Kt[j][d]);
                s0 = fmaf(q[d],     k4.x, s0);
                s1 = fmaf(q[d + 1], k4.y, s1);
                s2 = fmaf(q[d + 2], k4.z, s2);
                s3 = fmaf(q[d + 3], k4.w, s3);
            }
            const float s = ((s0 + s1) + (s2 + s3)) * 0.125f;

            float p;
            if (s > mx) {
                const float c = __expf(mx - s);
                l *= c;
                #pragma unroll
                for (int d = 0; d < 64; d++) acc[d] *= c;
                mx = s;
                p = 1.f;
            } else {
                p = __expf(s - mx);
            }
            l += p;

            #pragma unroll
            for (int d = 0; d < 64; d += 4) {
                float4 v4 = *reinterpret_cast<const float4*>(&Vt[j][d]);
                acc[d]     = fmaf(p, v4.x, acc[d]);
                acc[d + 1] = fmaf(p, v4.y, acc[d + 1]);
                acc[d + 2] = fmaf(p, v4.z, acc[d + 2]);
                acc[d + 3] = fmaf(p, v4.w, acc[d + 3]);
            }
        }
    }

    const float inv = 1.f / l;
    float* Op = oh + hoff + (size_t)(qi * 64 + t) * HDIM;
    #pragma unroll
    for (int d = 0; d < 64; d += 4) {
        float4 o4 = make_float4(acc[d] * inv, acc[d + 1] * inv,
                                acc[d + 2] * inv, acc[d + 3] * inv);
        *reinterpret_cast<float4*>(Op + d) = o4;
    }
}

// ---------------------------------------------------------------------------
// kernel_launch
// Inputs: 0=q 1=k 2=v 3=mask 4=Wq 5=bq 6=Wk 7=bk 8=Wv 9=bv 10=Wo 11=bo
// Output: [out (B,S,D)] [kh (B,H,S,HD)] [vh (B,H,S,HD)]
// ---------------------------------------------------------------------------
extern "C" void kernel_launch(void* const* d_in, const int* in_sizes, int n_in,
                              void* d_out, int out_size)
{
    const float* q  = (const float*)d_in[0];
    const float* k  = (const float*)d_in[1];
    const float* v  = (const float*)d_in[2];
    const float* Wq = (const float*)d_in[4];
    const float* bq = (const float*)d_in[5];
    const float* Wk = (const float*)d_in[6];
    const float* bk = (const float*)d_in[7];
    const float* Wv = (const float*)d_in[8];
    const float* bv = (const float*)d_in[9];
    const float* Wo = (const float*)d_in[10];
    const float* bo = (const float*)d_in[11];

    float* out = (float*)d_out;
    float* khp = out + HEADTOT;
    float* vhp = khp + HEADTOT;

    float *qh_p = nullptr, *att_p = nullptr;
    cudaGetSymbolAddress((void**)&qh_p, g_qh);
    cudaGetSymbolAddress((void**)&att_p, g_att);

    cudaFuncSetAttribute(gemm_mma<false, true>,
                         cudaFuncAttributeMaxDynamicSharedMemorySize, GSMEM_BYTES);
    cudaFuncSetAttribute(gemm_mma<true, false>,
                         cudaFuncAttributeMaxDynamicSharedMemorySize, GSMEM_BYTES);

    dim3 grd(DD / 128, MTOT / 128);   // (8, 64)

    gemm_mma<false, true><<<grd, 256, GSMEM_BYTES>>>(q, Wq, bq, qh_p);
    gemm_mma<false, true><<<grd, 256, GSMEM_BYTES>>>(k, Wk, bk, khp);
    gemm_mma<false, true><<<grd, 256, GSMEM_BYTES>>>(v, Wv, bv, vhp);

    flash_kernel<<<dim3(SS / 64, HH, BB), 64>>>(qh_p, khp, vhp, att_p);

    gemm_mma<true, false><<<grd, 256, GSMEM_BYTES>>>(att_p, Wo, bo, out);
}

// round 5
// speedup vs baseline: 3.7438x; 2.3455x over previous
#include <cuda_runtime.h>
#include <math.h>
#include <stdint.h>

// Problem constants
#define BB 4
#define SS 2048
#define DD 1024
#define HH 16
#define HDIM 64
#define MTOT (BB * SS)                          // 8192
#define HEADTOT ((size_t)BB * HH * SS * HDIM)   // 8,388,608

// Scratch
__device__ float g_qh[BB * HH * SS * HDIM];
__device__ float g_att[BB * HH * SS * HDIM];
__device__ float g_vt[BB * HH * HDIM * SS];     // V transposed: [b][h][d][s]

__device__ __forceinline__ uint32_t smem_u32(const void* p) {
    uint32_t a;
    asm("{ .reg .u64 t; cvta.to.shared.u64 t, %1; cvt.u32.u64 %0, t; }"
        : "=r"(a) : "l"(p));
    return a;
}

__device__ __forceinline__ uint32_t f2tf(float f) {
    uint32_t u;
    asm("cvt.rna.tf32.f32 %0, %1;" : "=r"(u) : "f"(f));
    return u;
}

__device__ __forceinline__ void split_tf(float v, uint32_t& hi, uint32_t& lo) {
    hi = f2tf(v);
    lo = f2tf(v - __uint_as_float(hi));
}

__device__ __forceinline__ void mma8(float* c, const uint32_t* a,
                                     uint32_t b0, uint32_t b1) {
    asm volatile(
        "mma.sync.aligned.m16n8k8.row.col.f32.tf32.tf32.f32 "
        "{%0,%1,%2,%3}, {%4,%5,%6,%7}, {%8,%9}, {%0,%1,%2,%3};"
        : "+f"(c[0]), "+f"(c[1]), "+f"(c[2]), "+f"(c[3])
        : "r"(a[0]), "r"(a[1]), "r"(a[2]), "r"(a[3]), "r"(b0), "r"(b1));
}

// exp2(z) for z <= 0, FMA-pipe only (no MUFU). ~5e-5 rel err.
__device__ __forceinline__ float exp2p(float z) {
    z = fmaxf(z, -100.f);
    float k = z + 12582912.f;            // 1.5*2^23: round-to-nearest-int
    int nb = __float_as_int(k);
    float f = z - (k - 12582912.f);      // f in [-0.5, 0.5]
    float p = 0.00961813f;
    p = fmaf(p, f, 0.05550410f);
    p = fmaf(p, f, 0.24022651f);
    p = fmaf(p, f, 0.69314718f);
    p = fmaf(p, f, 1.0f);
    return p * __int_as_float((nb << 23) + 0x3F800000);
}

// ---------------------------------------------------------------------------
// Tensor-core GEMM (mma.sync tf32): Y = X @ W^T + bias. (+ optional
// transposed copy YT[b][h][d][s] for the V projection.)
// ---------------------------------------------------------------------------
#define GSTRIDE 36
#define GTILEF (128 * GSTRIDE)
#define GSMEM_BYTES (2 * 2 * GTILEF * 4)   // 73728

template <bool IN_HEADS, bool OUT_HEADS, bool HAS_YT>
__global__ void __launch_bounds__(256) gemm_mma(
    const float* __restrict__ X, const float* __restrict__ W,
    const float* __restrict__ bias, float* __restrict__ Y,
    float* __restrict__ YT)
{
    extern __shared__ float sm[];
    const int tid = threadIdx.x;
    const int wid = tid >> 5, lane = tid & 31;
    const int g = lane >> 2, t = lane & 3;
    const int m0 = blockIdx.y * 128, n0 = blockIdx.x * 128;
    const int wm0 = (wid >> 1) * 32, wn0 = (wid & 1) * 64;

    float c[2][8][4];
    #pragma unroll
    for (int i = 0; i < 2; i++)
        #pragma unroll
        for (int j = 0; j < 8; j++)
            #pragma unroll
            for (int r = 0; r < 4; r++) c[i][j][r] = 0.f;

    auto issue_loads = [&](int k0, int s) {
        float* As = sm + s * 2 * GTILEF;
        float* Bs = As + GTILEF;
        #pragma unroll
        for (int it = 0; it < 4; it++) {
            const int idx = it * 256 + tid;
            const int row = idx >> 3;
            const int c4  = idx & 7;
            const int gk  = k0 + c4 * 4;
            const float* pa;
            if (IN_HEADS) {
                const int gm = m0 + row;
                const int bb_ = gm >> 11;
                const int ss_ = gm & (SS - 1);
                pa = X + ((((size_t)bb_ * HH + (gk >> 6)) * SS + ss_) << 6) + (gk & 63);
            } else {
                pa = X + (size_t)(m0 + row) * DD + gk;
            }
            const uint32_t da = smem_u32(As + row * GSTRIDE + c4 * 4);
            asm volatile("cp.async.cg.shared.global [%0], [%1], 16;"
                         :: "r"(da), "l"(pa));
            const float* pb = W + (size_t)(n0 + row) * DD + gk;
            const uint32_t db = smem_u32(Bs + row * GSTRIDE + c4 * 4);
            asm volatile("cp.async.cg.shared.global [%0], [%1], 16;"
                         :: "r"(db), "l"(pb));
        }
        asm volatile("cp.async.commit_group;" ::: "memory");
    };

    issue_loads(0, 0);
    const int NK = DD / 32;
    for (int ck = 0; ck < NK; ck++) {
        asm volatile("cp.async.wait_group 0;" ::: "memory");
        __syncthreads();
        if (ck + 1 < NK) issue_loads((ck + 1) * 32, (ck + 1) & 1);

        const float* As = sm + (ck & 1) * 2 * GTILEF;
        const float* Bs = As + GTILEF;

        #pragma unroll
        for (int ks = 0; ks < 4; ks++) {
            const int k0 = ks * 8;
            uint32_t a[2][4], b[8][2];
            #pragma unroll
            for (int i = 0; i < 2; i++) {
                const int r = wm0 + 16 * i + g;
                a[i][0] = f2tf(As[r * GSTRIDE + k0 + t]);
                a[i][1] = f2tf(As[(r + 8) * GSTRIDE + k0 + t]);
                a[i][2] = f2tf(As[r * GSTRIDE + k0 + t + 4]);
                a[i][3] = f2tf(As[(r + 8) * GSTRIDE + k0 + t + 4]);
            }
            #pragma unroll
            for (int j = 0; j < 8; j++) {
                const int cn = wn0 + 8 * j + g;
                b[j][0] = f2tf(Bs[cn * GSTRIDE + k0 + t]);
                b[j][1] = f2tf(Bs[cn * GSTRIDE + k0 + t + 4]);
            }
            #pragma unroll
            for (int i = 0; i < 2; i++)
                #pragma unroll
                for (int j = 0; j < 8; j++)
                    mma8(c[i][j], a[i], b[j][0], b[j][1]);
        }
        __syncthreads();
    }

    #pragma unroll
    for (int i = 0; i < 2; i++) {
        const int r0 = m0 + wm0 + 16 * i + g;
        const int r1 = r0 + 8;
        #pragma unroll
        for (int j = 0; j < 8; j++) {
            const int gn = n0 + wn0 + 8 * j + 2 * t;
            const float bx = __ldg(bias + gn);
            const float by = __ldg(bias + gn + 1);
            float2 o0 = make_float2(c[i][j][0] + bx, c[i][j][1] + by);
            float2 o1 = make_float2(c[i][j][2] + bx, c[i][j][3] + by);
            if (OUT_HEADS) {
                const int hb = gn >> 6, hc = gn & 63;
                const int b0_ = r0 >> 11, s0_ = r0 & (SS - 1);
                const int b1_ = r1 >> 11, s1_ = r1 & (SS - 1);
                *reinterpret_cast<float2*>(
                    Y + ((((size_t)b0_ * HH + hb) * SS + s0_) << 6) + hc) = o0;
                *reinterpret_cast<float2*>(
                    Y + ((((size_t)b1_ * HH + hb) * SS + s1_) << 6) + hc) = o1;
                if (HAS_YT) {
                    // YT[b][h][d][s]
                    float* yt0 = YT + (((size_t)b0_ * HH + hb) * HDIM + hc) * SS + s0_;
                    float* yt1 = YT + (((size_t)b1_ * HH + hb) * HDIM + hc) * SS + s1_;
                    yt0[0] = o0.x; yt0[SS] = o0.y;
                    yt1[0] = o1.x; yt1[SS] = o1.y;
                }
            } else {
                *reinterpret_cast<float2*>(Y + (size_t)r0 * DD + gn) = o0;
                *reinterpret_cast<float2*>(Y + (size_t)r1 * DD + gn) = o1;
            }
        }
    }
}

// ---------------------------------------------------------------------------
// Tensor-core causal flash attention.
// Block 128 thr = 4 warps; q-tile 64 rows (warp = 16 rows), key-tiles of 64.
// QK: A = Q (hi+lo split in regs), B = K tile (tf32 in smem).
// PV: A = P (hi+lo split via smem), B = V^T tile (from g_vt).
// Softmax with fp32 polynomial exp2 (no MUFU).
// ---------------------------------------------------------------------------
#define FPAD 68
#define FSMEM_BYTES (3 * 64 * FPAD * 4)   // Kt + VT + Pb = 52224

__global__ void __launch_bounds__(128, 3) flash_tc(
    const float* __restrict__ qh, const float* __restrict__ kh,
    const float* __restrict__ vt, float* __restrict__ oh)
{
    extern __shared__ uint32_t fsm[];
    uint32_t* Kt = fsm;                       // [64][FPAD] tf32 K[key][d]
    uint32_t* VT = fsm + 64 * FPAD;           // [64][FPAD] tf32 V^T[d][key]
    float*    Pb = (float*)(fsm + 2 * 64 * FPAD);  // [64][FPAD]

    const int tid = threadIdx.x;
    const int w = tid >> 5, lane = tid & 31;
    const int g = lane >> 2, t = lane & 3;
    const int qi = 31 - (int)blockIdx.x;      // biggest blocks first
    const int h = blockIdx.y, b = blockIdx.z;
    const size_t hoff = ((size_t)b * HH + h) * SS * HDIM;
    const float* vtb = vt + ((size_t)b * HH + h) * HDIM * SS;
    const int q0 = qi * 64;
    const float CLOG = 0.18033688011112042f;  // 0.125 * log2(e)

    // ---- stage Q tile into Pb, pull A-fragments (hi/lo) into registers ----
    #pragma unroll
    for (int i = 0; i < 8; i++) {
        const int idx = i * 128 + tid;
        const int r = idx >> 4, c4 = idx & 15;
        float4 qv = *reinterpret_cast<const float4*>(
            qh + hoff + (size_t)(q0 + r) * HDIM + c4 * 4);
        *reinterpret_cast<float4*>(Pb + r * FPAD + c4 * 4) = qv;
    }
    __syncthreads();

    uint32_t qhi[8][4], qlo[8][4];
    const int row0 = w * 16 + g;
    #pragma unroll
    for (int ks = 0; ks < 8; ks++) {
        const int c0 = 8 * ks + t, c1 = c0 + 4;
        split_tf(Pb[row0 * FPAD + c0],       qhi[ks][0], qlo[ks][0]);
        split_tf(Pb[(row0 + 8) * FPAD + c0], qhi[ks][1], qlo[ks][1]);
        split_tf(Pb[row0 * FPAD + c1],       qhi[ks][2], qlo[ks][2]);
        split_tf(Pb[(row0 + 8) * FPAD + c1], qhi[ks][3], qlo[ks][3]);
    }

    float o[8][4];
    #pragma unroll
    for (int nt = 0; nt < 8; nt++)
        #pragma unroll
        for (int r = 0; r < 4; r++) o[nt][r] = 0.f;
    float mx0 = -1e30f, mx1 = -1e30f, l0 = 0.f, l1 = 0.f;

    const int rg0 = q0 + row0;          // global row for c0/c1
    const int rg1 = rg0 + 8;            // global row for c2/c3

    for (int jt = 0; jt <= qi; jt++) {
        const int kb = jt * 64;
        __syncthreads();   // previous tile fully consumed (also covers Q staging)

        // ---- stage K tile and V^T tile (tf32) ----
        #pragma unroll
        for (int i = 0; i < 8; i++) {
            const int idx = i * 128 + tid;
            const int r = idx >> 4, c4 = idx & 15;
            float4 kv = *reinterpret_cast<const float4*>(
                kh + hoff + (size_t)(kb + r) * HDIM + c4 * 4);
            float4 vv = *reinterpret_cast<const float4*>(
                vtb + (size_t)r * SS + kb + c4 * 4);
            uint4 ku = make_uint4(f2tf(kv.x), f2tf(kv.y), f2tf(kv.z), f2tf(kv.w));
            uint4 vu = make_uint4(f2tf(vv.x), f2tf(vv.y), f2tf(vv.z), f2tf(vv.w));
            *reinterpret_cast<uint4*>(Kt + r * FPAD + c4 * 4) = ku;
            *reinterpret_cast<uint4*>(VT + r * FPAD + c4 * 4) = vu;
        }
        __syncthreads();

        // ---- scores S = Q K^T (split-Q: 2 MMAs share b-frags) ----
        float s[8][4];
        #pragma unroll
        for (int nt = 0; nt < 8; nt++) {
            s[nt][0] = s[nt][1] = s[nt][2] = s[nt][3] = 0.f;
            const uint32_t* kr = Kt + (8 * nt + g) * FPAD;
            #pragma unroll
            for (int ks = 0; ks < 8; ks++) {
                const uint32_t b0 = kr[8 * ks + t];
                const uint32_t b1 = kr[8 * ks + t + 4];
                mma8(s[nt], qhi[ks], b0, b1);
                mma8(s[nt], qlo[ks], b0, b1);
            }
        }

        // ---- causal mask (diagonal tile only) ----
        if (jt == qi) {
            #pragma unroll
            for (int nt = 0; nt < 8; nt++) {
                const int col = kb + 8 * nt + 2 * t;
                if (col > rg0)     s[nt][0] = -1e30f;
                if (col + 1 > rg0) s[nt][1] = -1e30f;
                if (col > rg1)     s[nt][2] = -1e30f;
                if (col + 1 > rg1) s[nt][3] = -1e30f;
            }
        }

        // ---- online softmax (raw scores; scale folded into CLOG) ----
        float sm0 = -1e30f, sm1 = -1e30f;
        #pragma unroll
        for (int nt = 0; nt < 8; nt++) {
            sm0 = fmaxf(sm0, fmaxf(s[nt][0], s[nt][1]));
            sm1 = fmaxf(sm1, fmaxf(s[nt][2], s[nt][3]));
        }
        sm0 = fmaxf(sm0, __shfl_xor_sync(0xffffffffu, sm0, 1));
        sm0 = fmaxf(sm0, __shfl_xor_sync(0xffffffffu, sm0, 2));
        sm1 = fmaxf(sm1, __shfl_xor_sync(0xffffffffu, sm1, 1));
        sm1 = fmaxf(sm1, __shfl_xor_sync(0xffffffffu, sm1, 2));

        const float nm0 = fmaxf(mx0, sm0), nm1 = fmaxf(mx1, sm1);
        const float f0 = exp2p((mx0 - nm0) * CLOG);
        const float f1 = exp2p((mx1 - nm1) * CLOG);
        mx0 = nm0; mx1 = nm1;
        l0 *= f0; l1 *= f1;
        #pragma unroll
        for (int nt = 0; nt < 8; nt++) {
            o[nt][0] *= f0; o[nt][1] *= f0;
            o[nt][2] *= f1; o[nt][3] *= f1;
        }

        float* Pw = Pb + w * 16 * FPAD;
        #pragma unroll
        for (int nt = 0; nt < 8; nt++) {
            const float p0 = exp2p((s[nt][0] - mx0) * CLOG);
            const float p1 = exp2p((s[nt][1] - mx0) * CLOG);
            const float p2 = exp2p((s[nt][2] - mx1) * CLOG);
            const float p3 = exp2p((s[nt][3] - mx1) * CLOG);
            l0 += p0 + p1;
            l1 += p2 + p3;
            *reinterpret_cast<float2*>(Pw + g * FPAD + 8 * nt + 2 * t) =
                make_float2(p0, p1);
            *reinterpret_cast<float2*>(Pw + (g + 8) * FPAD + 8 * nt + 2 * t) =
                make_float2(p2, p3);
        }
        __syncwarp();

        // ---- O += P V  (split-P: 2 MMAs share b-frags) ----
        #pragma unroll
        for (int kk = 0; kk < 8; kk++) {
            uint32_t ahi[4], alo[4];
            const int c0 = 8 * kk + t, c1 = c0 + 4;
            split_tf(Pw[g * FPAD + c0],       ahi[0], alo[0]);
            split_tf(Pw[(g + 8) * FPAD + c0], ahi[1], alo[1]);
            split_tf(Pw[g * FPAD + c1],       ahi[2], alo[2]);
            split_tf(Pw[(g + 8) * FPAD + c1], ahi[3], alo[3]);
            #pragma unroll
            for (int nt = 0; nt < 8; nt++) {
                const uint32_t* vr = VT + (8 * nt + g) * FPAD;
                const uint32_t b0 = vr[8 * kk + t];
                const uint32_t b1 = vr[8 * kk + t + 4];
                mma8(o[nt], ahi, b0, b1);
                mma8(o[nt], alo, b0, b1);
            }
        }
        __syncwarp();
    }

    // ---- finalize ----
    l0 += __shfl_xor_sync(0xffffffffu, l0, 1);
    l0 += __shfl_xor_sync(0xffffffffu, l0, 2);
    l1 += __shfl_xor_sync(0xffffffffu, l1, 1);
    l1 += __shfl_xor_sync(0xffffffffu, l1, 2);
    const float i0 = 1.f / l0, i1 = 1.f / l1;

    float* o0p = oh + hoff + (size_t)rg0 * HDIM;
    float* o1p = oh + hoff + (size_t)rg1 * HDIM;
    #pragma unroll
    for (int nt = 0; nt < 8; nt++) {
        const int d = 8 * nt + 2 * t;
        *reinterpret_cast<float2*>(o0p + d) = make_float2(o[nt][0] * i0, o[nt][1] * i0);
        *reinterpret_cast<float2*>(o1p + d) = make_float2(o[nt][2] * i1, o[nt][3] * i1);
    }
}

// ---------------------------------------------------------------------------
// kernel_launch
// Inputs: 0=q 1=k 2=v 3=mask 4=Wq 5=bq 6=Wk 7=bk 8=Wv 9=bv 10=Wo 11=bo
// Output: [out (B,S,D)] [kh (B,H,S,HD)] [vh (B,H,S,HD)]
// ---------------------------------------------------------------------------
extern "C" void kernel_launch(void* const* d_in, const int* in_sizes, int n_in,
                              void* d_out, int out_size)
{
    const float* q  = (const float*)d_in[0];
    const float* k  = (const float*)d_in[1];
    const float* v  = (const float*)d_in[2];
    const float* Wq = (const float*)d_in[4];
    const float* bq = (const float*)d_in[5];
    const float* Wk = (const float*)d_in[6];
    const float* bk = (const float*)d_in[7];
    const float* Wv = (const float*)d_in[8];
    const float* bv = (const float*)d_in[9];
    const float* Wo = (const float*)d_in[10];
    const float* bo = (const float*)d_in[11];

    float* out = (float*)d_out;
    float* khp = out + HEADTOT;
    float* vhp = khp + HEADTOT;

    float *qh_p = nullptr, *att_p = nullptr, *vt_p = nullptr;
    cudaGetSymbolAddress((void**)&qh_p, g_qh);
    cudaGetSymbolAddress((void**)&att_p, g_att);
    cudaGetSymbolAddress((void**)&vt_p, g_vt);

    cudaFuncSetAttribute(gemm_mma<false, true, false>,
                         cudaFuncAttributeMaxDynamicSharedMemorySize, GSMEM_BYTES);
    cudaFuncSetAttribute(gemm_mma<false, true, true>,
                         cudaFuncAttributeMaxDynamicSharedMemorySize, GSMEM_BYTES);
    cudaFuncSetAttribute(gemm_mma<true, false, false>,
                         cudaFuncAttributeMaxDynamicSharedMemorySize, GSMEM_BYTES);
    cudaFuncSetAttribute(flash_tc,
                         cudaFuncAttributeMaxDynamicSharedMemorySize, FSMEM_BYTES);

    dim3 grd(DD / 128, MTOT / 128);   // (8, 64)

    gemm_mma<false, true, false><<<grd, 256, GSMEM_BYTES>>>(q, Wq, bq, qh_p, nullptr);
    gemm_mma<false, true, false><<<grd, 256, GSMEM_BYTES>>>(k, Wk, bk, khp, nullptr);
    gemm_mma<false, true, true ><<<grd, 256, GSMEM_BYTES>>>(v, Wv, bv, vhp, vt_p);

    flash_tc<<<dim3(32, HH, BB), 128, FSMEM_BYTES>>>(qh_p, khp, vt_p, att_p);

    gemm_mma<true, false, false><<<grd, 256, GSMEM_BYTES>>>(att_p, Wo, bo, out, nullptr);
}

// round 6
// speedup vs baseline: 3.9763x; 1.0621x over previous
#include <cuda_runtime.h>
#include <math.h>
#include <stdint.h>

// Problem constants
#define BB 4
#define SS 2048
#define DD 1024
#define HH 16
#define HDIM 64
#define MTOT (BB * SS)                          // 8192
#define HEADTOT ((size_t)BB * HH * SS * HDIM)   // 8,388,608

// Scratch
__device__ float g_qh[BB * HH * SS * HDIM];
__device__ float g_att[BB * HH * SS * HDIM];
__device__ float g_vt[BB * HH * HDIM * SS];     // V transposed: [b][h][d][s]

__device__ __forceinline__ uint32_t smem_u32(const void* p) {
    uint32_t a;
    asm("{ .reg .u64 t; cvta.to.shared.u64 t, %1; cvt.u32.u64 %0, t; }"
        : "=r"(a) : "l"(p));
    return a;
}

__device__ __forceinline__ uint32_t f2tf(float f) {
    uint32_t u;
    asm("cvt.rna.tf32.f32 %0, %1;" : "=r"(u) : "f"(f));
    return u;
}

__device__ __forceinline__ void split_tf(float v, uint32_t& hi, uint32_t& lo) {
    hi = f2tf(v);
    lo = f2tf(v - __uint_as_float(hi));
}

__device__ __forceinline__ void mma8(float* c, const uint32_t* a,
                                     uint32_t b0, uint32_t b1) {
    asm volatile(
        "mma.sync.aligned.m16n8k8.row.col.f32.tf32.tf32.f32 "
        "{%0,%1,%2,%3}, {%4,%5,%6,%7}, {%8,%9}, {%0,%1,%2,%3};"
        : "+f"(c[0]), "+f"(c[1]), "+f"(c[2]), "+f"(c[3])
        : "r"(a[0]), "r"(a[1]), "r"(a[2]), "r"(a[3]), "r"(b0), "r"(b1));
}

// exp2(z) for z <= 0, FMA-pipe only (no MUFU). ~5e-5 rel err.
__device__ __forceinline__ float exp2p(float z) {
    z = fmaxf(z, -100.f);
    float k = z + 12582912.f;            // 1.5*2^23: round-to-nearest-int
    int nb = __float_as_int(k);
    float f = z - (k - 12582912.f);      // f in [-0.5, 0.5]
    float p = 0.00961813f;
    p = fmaf(p, f, 0.05550410f);
    p = fmaf(p, f, 0.24022651f);
    p = fmaf(p, f, 0.69314718f);
    p = fmaf(p, f, 1.0f);
    return p * __int_as_float((nb << 23) + 0x3F800000);
}

// ---------------------------------------------------------------------------
// Tensor-core GEMM (mma.sync tf32): Y = X @ W^T + bias. (+ optional
// transposed copy YT[b][h][d][s] for the V projection.)
// ---------------------------------------------------------------------------
#define GSTRIDE 36
#define GTILEF (128 * GSTRIDE)
#define GSMEM_BYTES (2 * 2 * GTILEF * 4)   // 73728

template <bool IN_HEADS, bool OUT_HEADS, bool HAS_YT>
__global__ void __launch_bounds__(256) gemm_mma(
    const float* __restrict__ X, const float* __restrict__ W,
    const float* __restrict__ bias, float* __restrict__ Y,
    float* __restrict__ YT)
{
    extern __shared__ float sm[];
    const int tid = threadIdx.x;
    const int wid = tid >> 5, lane = tid & 31;
    const int g = lane >> 2, t = lane & 3;
    const int m0 = blockIdx.y * 128, n0 = blockIdx.x * 128;
    const int wm0 = (wid >> 1) * 32, wn0 = (wid & 1) * 64;

    float c[2][8][4];
    #pragma unroll
    for (int i = 0; i < 2; i++)
        #pragma unroll
        for (int j = 0; j < 8; j++)
            #pragma unroll
            for (int r = 0; r < 4; r++) c[i][j][r] = 0.f;

    auto issue_loads = [&](int k0, int s) {
        float* As = sm + s * 2 * GTILEF;
        float* Bs = As + GTILEF;
        #pragma unroll
        for (int it = 0; it < 4; it++) {
            const int idx = it * 256 + tid;
            const int row = idx >> 3;
            const int c4  = idx & 7;
            const int gk  = k0 + c4 * 4;
            const float* pa;
            if (IN_HEADS) {
                const int gm = m0 + row;
                const int bb_ = gm >> 11;
                const int ss_ = gm & (SS - 1);
                pa = X + ((((size_t)bb_ * HH + (gk >> 6)) * SS + ss_) << 6) + (gk & 63);
            } else {
                pa = X + (size_t)(m0 + row) * DD + gk;
            }
            const uint32_t da = smem_u32(As + row * GSTRIDE + c4 * 4);
            asm volatile("cp.async.cg.shared.global [%0], [%1], 16;"
                         :: "r"(da), "l"(pa));
            const float* pb = W + (size_t)(n0 + row) * DD + gk;
            const uint32_t db = smem_u32(Bs + row * GSTRIDE + c4 * 4);
            asm volatile("cp.async.cg.shared.global [%0], [%1], 16;"
                         :: "r"(db), "l"(pb));
        }
        asm volatile("cp.async.commit_group;" ::: "memory");
    };

    issue_loads(0, 0);
    const int NK = DD / 32;
    for (int ck = 0; ck < NK; ck++) {
        asm volatile("cp.async.wait_group 0;" ::: "memory");
        __syncthreads();
        if (ck + 1 < NK) issue_loads((ck + 1) * 32, (ck + 1) & 1);

        const float* As = sm + (ck & 1) * 2 * GTILEF;
        const float* Bs = As + GTILEF;

        #pragma unroll
        for (int ks = 0; ks < 4; ks++) {
            const int k0 = ks * 8;
            uint32_t a[2][4], b[8][2];
            #pragma unroll
            for (int i = 0; i < 2; i++) {
                const int r = wm0 + 16 * i + g;
                a[i][0] = f2tf(As[r * GSTRIDE + k0 + t]);
                a[i][1] = f2tf(As[(r + 8) * GSTRIDE + k0 + t]);
                a[i][2] = f2tf(As[r * GSTRIDE + k0 + t + 4]);
                a[i][3] = f2tf(As[(r + 8) * GSTRIDE + k0 + t + 4]);
            }
            #pragma unroll
            for (int j = 0; j < 8; j++) {
                const int cn = wn0 + 8 * j + g;
                b[j][0] = f2tf(Bs[cn * GSTRIDE + k0 + t]);
                b[j][1] = f2tf(Bs[cn * GSTRIDE + k0 + t + 4]);
            }
            #pragma unroll
            for (int i = 0; i < 2; i++)
                #pragma unroll
                for (int j = 0; j < 8; j++)
                    mma8(c[i][j], a[i], b[j][0], b[j][1]);
        }
        __syncthreads();
    }

    #pragma unroll
    for (int i = 0; i < 2; i++) {
        const int r0 = m0 + wm0 + 16 * i + g;
        const int r1 = r0 + 8;
        #pragma unroll
        for (int j = 0; j < 8; j++) {
            const int gn = n0 + wn0 + 8 * j + 2 * t;
            const float bx = __ldg(bias + gn);
            const float by = __ldg(bias + gn + 1);
            float2 o0 = make_float2(c[i][j][0] + bx, c[i][j][1] + by);
            float2 o1 = make_float2(c[i][j][2] + bx, c[i][j][3] + by);
            if (OUT_HEADS) {
                const int hb = gn >> 6, hc = gn & 63;
                const int b0_ = r0 >> 11, s0_ = r0 & (SS - 1);
                const int b1_ = r1 >> 11, s1_ = r1 & (SS - 1);
                *reinterpret_cast<float2*>(
                    Y + ((((size_t)b0_ * HH + hb) * SS + s0_) << 6) + hc) = o0;
                *reinterpret_cast<float2*>(
                    Y + ((((size_t)b1_ * HH + hb) * SS + s1_) << 6) + hc) = o1;
                if (HAS_YT) {
                    float* yt0 = YT + (((size_t)b0_ * HH + hb) * HDIM + hc) * SS + s0_;
                    float* yt1 = YT + (((size_t)b1_ * HH + hb) * HDIM + hc) * SS + s1_;
                    yt0[0] = o0.x; yt0[SS] = o0.y;
                    yt1[0] = o1.x; yt1[SS] = o1.y;
                }
            } else {
                *reinterpret_cast<float2*>(Y + (size_t)r0 * DD + gn) = o0;
                *reinterpret_cast<float2*>(Y + (size_t)r1 * DD + gn) = o1;
            }
        }
    }
}

// ---------------------------------------------------------------------------
// Tensor-core causal flash attention, cp.async double-buffered K/V staging.
// Block 128 thr = 4 warps; q-tile 64 rows (warp = 16 rows), key-tiles of 64.
// K/V^T staged RAW fp32 via cp.async (tensor core truncates to tf32 in HW).
// QK: A = Q (RNA hi+lo split in regs). PV: A = P (RNA hi+lo split via smem).
// ---------------------------------------------------------------------------
#define FPAD 68
#define FTILE (64 * FPAD)
#define FSMEM_BYTES (5 * FTILE * 4)   // Kb[2] + Vb[2] + Pb = 87040

__global__ void __launch_bounds__(128, 2) flash_tc(
    const float* __restrict__ qh, const float* __restrict__ kh,
    const float* __restrict__ vt, float* __restrict__ oh)
{
    extern __shared__ float fsm[];
    float* Kb = fsm;                    // [2][64][FPAD] raw fp32 K[key][d]
    float* Vb = fsm + 2 * FTILE;        // [2][64][FPAD] raw fp32 V^T[d][key]
    float* Pb = fsm + 4 * FTILE;        // [64][FPAD]

    const int tid = threadIdx.x;
    const int w = tid >> 5, lane = tid & 31;
    const int g = lane >> 2, t = lane & 3;
    const int qi = 31 - (int)blockIdx.x;      // biggest blocks first
    const int h = blockIdx.y, b = blockIdx.z;
    const size_t hoff = ((size_t)b * HH + h) * SS * HDIM;
    const float* vtb = vt + ((size_t)b * HH + h) * HDIM * SS;
    const int q0 = qi * 64;
    const float CLOG = 0.18033688011112042f;  // 0.125 * log2(e)

    // Per-thread staging coords: 8 x 16B per tile per array.
    const int sr = tid >> 4;            // base row (0..7), step 8
    const int sc = (tid & 15) * 4;      // 16B column group

    auto issue_tile = [&](int jt, int buf) {
        float* kd = Kb + buf * FTILE;
        float* vd = Vb + buf * FTILE;
        const int kb = jt * 64;
        #pragma unroll
        for (int i = 0; i < 8; i++) {
            const int r = sr + i * 8;
            const float* ks = kh + hoff + (size_t)(kb + r) * HDIM + sc;
            const float* vs = vtb + (size_t)r * SS + kb + sc;
            asm volatile("cp.async.cg.shared.global [%0], [%1], 16;"
                         :: "r"(smem_u32(kd + r * FPAD + sc)), "l"(ks));
            asm volatile("cp.async.cg.shared.global [%0], [%1], 16;"
                         :: "r"(smem_u32(vd + r * FPAD + sc)), "l"(vs));
        }
        asm volatile("cp.async.commit_group;" ::: "memory");
    };

    issue_tile(0, 0);   // prefetch tile 0 before anything else

    // ---- stage Q tile into Pb, pull A-fragments (hi/lo) into registers ----
    #pragma unroll
    for (int i = 0; i < 8; i++) {
        const int idx = i * 128 + tid;
        const int r = idx >> 4, c4 = idx & 15;
        float4 qv = *reinterpret_cast<const float4*>(
            qh + hoff + (size_t)(q0 + r) * HDIM + c4 * 4);
        *reinterpret_cast<float4*>(Pb + r * FPAD + c4 * 4) = qv;
    }
    __syncthreads();

    uint32_t qhi[8][4], qlo[8][4];
    const int row0 = w * 16 + g;
    #pragma unroll
    for (int ks = 0; ks < 8; ks++) {
        const int c0 = 8 * ks + t, c1 = c0 + 4;
        split_tf(Pb[row0 * FPAD + c0],       qhi[ks][0], qlo[ks][0]);
        split_tf(Pb[(row0 + 8) * FPAD + c0], qhi[ks][1], qlo[ks][1]);
        split_tf(Pb[row0 * FPAD + c1],       qhi[ks][2], qlo[ks][2]);
        split_tf(Pb[(row0 + 8) * FPAD + c1], qhi[ks][3], qlo[ks][3]);
    }

    float o[8][4];
    #pragma unroll
    for (int nt = 0; nt < 8; nt++)
        #pragma unroll
        for (int r = 0; r < 4; r++) o[nt][r] = 0.f;
    float mx0 = -1e30f, mx1 = -1e30f, l0 = 0.f, l1 = 0.f;

    const int rg0 = q0 + row0;          // global row for c0/c1
    const int rg1 = rg0 + 8;            // global row for c2/c3

    for (int jt = 0; jt <= qi; jt++) {
        const int kb = jt * 64;
        const int buf = jt & 1;

        // Prefetch next tile into the other buffer, then wait for current.
        if (jt < qi) {
            issue_tile(jt + 1, buf ^ 1);
            asm volatile("cp.async.wait_group 1;" ::: "memory");
        } else {
            asm volatile("cp.async.wait_group 0;" ::: "memory");
        }
        __syncthreads();

        const uint32_t* Kt = reinterpret_cast<const uint32_t*>(Kb + buf * FTILE);
        const uint32_t* VT = reinterpret_cast<const uint32_t*>(Vb + buf * FTILE);

        // ---- scores S = Q K^T (split-Q: 2 MMAs share raw-fp32 b-frags) ----
        float s[8][4];
        #pragma unroll
        for (int nt = 0; nt < 8; nt++) {
            s[nt][0] = s[nt][1] = s[nt][2] = s[nt][3] = 0.f;
            const uint32_t* kr = Kt + (8 * nt + g) * FPAD;
            #pragma unroll
            for (int ks = 0; ks < 8; ks++) {
                const uint32_t b0 = kr[8 * ks + t];
                const uint32_t b1 = kr[8 * ks + t + 4];
                mma8(s[nt], qhi[ks], b0, b1);
                mma8(s[nt], qlo[ks], b0, b1);
            }
        }

        // ---- causal mask (diagonal tile only) ----
        if (jt == qi) {
            #pragma unroll
            for (int nt = 0; nt < 8; nt++) {
                const int col = kb + 8 * nt + 2 * t;
                if (col > rg0)     s[nt][0] = -1e30f;
                if (col + 1 > rg0) s[nt][1] = -1e30f;
                if (col > rg1)     s[nt][2] = -1e30f;
                if (col + 1 > rg1) s[nt][3] = -1e30f;
            }
        }

        // ---- online softmax ----
        float sm0 = -1e30f, sm1 = -1e30f;
        #pragma unroll
        for (int nt = 0; nt < 8; nt++) {
            sm0 = fmaxf(sm0, fmaxf(s[nt][0], s[nt][1]));
            sm1 = fmaxf(sm1, fmaxf(s[nt][2], s[nt][3]));
        }
        sm0 = fmaxf(sm0, __shfl_xor_sync(0xffffffffu, sm0, 1));
        sm0 = fmaxf(sm0, __shfl_xor_sync(0xffffffffu, sm0, 2));
        sm1 = fmaxf(sm1, __shfl_xor_sync(0xffffffffu, sm1, 1));
        sm1 = fmaxf(sm1, __shfl_xor_sync(0xffffffffu, sm1, 2));

        const float nm0 = fmaxf(mx0, sm0), nm1 = fmaxf(mx1, sm1);
        const float f0 = exp2p((mx0 - nm0) * CLOG);
        const float f1 = exp2p((mx1 - nm1) * CLOG);
        mx0 = nm0; mx1 = nm1;
        l0 *= f0; l1 *= f1;
        #pragma unroll
        for (int nt = 0; nt < 8; nt++) {
            o[nt][0] *= f0; o[nt][1] *= f0;
            o[nt][2] *= f1; o[nt][3] *= f1;
        }

        float* Pw = Pb + w * 16 * FPAD;
        #pragma unroll
        for (int nt = 0; nt < 8; nt++) {
            const float p0 = exp2p((s[nt][0] - mx0) * CLOG);
            const float p1 = exp2p((s[nt][1] - mx0) * CLOG);
            const float p2 = exp2p((s[nt][2] - mx1) * CLOG);
            const float p3 = exp2p((s[nt][3] - mx1) * CLOG);
            l0 += p0 + p1;
            l1 += p2 + p3;
            *reinterpret_cast<float2*>(Pw + g * FPAD + 8 * nt + 2 * t) =
                make_float2(p0, p1);
            *reinterpret_cast<float2*>(Pw + (g + 8) * FPAD + 8 * nt + 2 * t) =
                make_float2(p2, p3);
        }
        __syncwarp();

        // ---- O += P V  (split-P: 2 MMAs share raw-fp32 b-frags) ----
        #pragma unroll
        for (int kk = 0; kk < 8; kk++) {
            uint32_t ahi[4], alo[4];
            const int c0 = 8 * kk + t, c1 = c0 + 4;
            split_tf(Pw[g * FPAD + c0],       ahi[0], alo[0]);
            split_tf(Pw[(g + 8) * FPAD + c0], ahi[1], alo[1]);
            split_tf(Pw[g * FPAD + c1],       ahi[2], alo[2]);
            split_tf(Pw[(g + 8) * FPAD + c1], ahi[3], alo[3]);
            #pragma unroll
            for (int nt = 0; nt < 8; nt++) {
                const uint32_t* vr = VT + (8 * nt + g) * FPAD;
                const uint32_t b0 = vr[8 * kk + t];
                const uint32_t b1 = vr[8 * kk + t + 4];
                mma8(o[nt], ahi, b0, b1);
                mma8(o[nt], alo, b0, b1);
            }
        }
        __syncthreads();   // all warps done reading this buffer before reuse
    }

    // ---- finalize ----
    l0 += __shfl_xor_sync(0xffffffffu, l0, 1);
    l0 += __shfl_xor_sync(0xffffffffu, l0, 2);
    l1 += __shfl_xor_sync(0xffffffffu, l1, 1);
    l1 += __shfl_xor_sync(0xffffffffu, l1, 2);
    const float i0 = 1.f / l0, i1 = 1.f / l1;

    float* o0p = oh + hoff + (size_t)rg0 * HDIM;
    float* o1p = oh + hoff + (size_t)rg1 * HDIM;
    #pragma unroll
    for (int nt = 0; nt < 8; nt++) {
        const int d = 8 * nt + 2 * t;
        *reinterpret_cast<float2*>(o0p + d) = make_float2(o[nt][0] * i0, o[nt][1] * i0);
        *reinterpret_cast<float2*>(o1p + d) = make_float2(o[nt][2] * i1, o[nt][3] * i1);
    }
}

// ---------------------------------------------------------------------------
// kernel_launch
// Inputs: 0=q 1=k 2=v 3=mask 4=Wq 5=bq 6=Wk 7=bk 8=Wv 9=bv 10=Wo 11=bo
// Output: [out (B,S,D)] [kh (B,H,S,HD)] [vh (B,H,S,HD)]
// ---------------------------------------------------------------------------
extern "C" void kernel_launch(void* const* d_in, const int* in_sizes, int n_in,
                              void* d_out, int out_size)
{
    const float* q  = (const float*)d_in[0];
    const float* k  = (const float*)d_in[1];
    const float* v  = (const float*)d_in[2];
    const float* Wq = (const float*)d_in[4];
    const float* bq = (const float*)d_in[5];
    const float* Wk = (const float*)d_in[6];
    const float* bk = (const float*)d_in[7];
    const float* Wv = (const float*)d_in[8];
    const float* bv = (const float*)d_in[9];
    const float* Wo = (const float*)d_in[10];
    const float* bo = (const float*)d_in[11];

    float* out = (float*)d_out;
    float* khp = out + HEADTOT;
    float* vhp = khp + HEADTOT;

    float *qh_p = nullptr, *att_p = nullptr, *vt_p = nullptr;
    cudaGetSymbolAddress((void**)&qh_p, g_qh);
    cudaGetSymbolAddress((void**)&att_p, g_att);
    cudaGetSymbolAddress((void**)&vt_p, g_vt);

    cudaFuncSetAttribute(gemm_mma<false, true, false>,
                         cudaFuncAttributeMaxDynamicSharedMemorySize, GSMEM_BYTES);
    cudaFuncSetAttribute(gemm_mma<false, true, true>,
                         cudaFuncAttributeMaxDynamicSharedMemorySize, GSMEM_BYTES);
    cudaFuncSetAttribute(gemm_mma<true, false, false>,
                         cudaFuncAttributeMaxDynamicSharedMemorySize, GSMEM_BYTES);
    cudaFuncSetAttribute(flash_tc,
                         cudaFuncAttributeMaxDynamicSharedMemorySize, FSMEM_BYTES);

    dim3 grd(DD / 128, MTOT / 128);   // (8, 64)

    gemm_mma<false, true, false><<<grd, 256, GSMEM_BYTES>>>(q, Wq, bq, qh_p, nullptr);
    gemm_mma<false, true, false><<<grd, 256, GSMEM_BYTES>>>(k, Wk, bk, khp, nullptr);
    gemm_mma<false, true, true ><<<grd, 256, GSMEM_BYTES>>>(v, Wv, bv, vhp, vt_p);

    flash_tc<<<dim3(32, HH, BB), 128, FSMEM_BYTES>>>(qh_p, khp, vt_p, att_p);

    gemm_mma<true, false, false><<<grd, 256, GSMEM_BYTES>>>(att_p, Wo, bo, out, nullptr);
}

// round 7
// speedup vs baseline: 4.2355x; 1.0652x over previous
#include <cuda_runtime.h>
#include <math.h>
#include <stdint.h>

// Problem constants
#define BB 4
#define SS 2048
#define DD 1024
#define HH 16
#define HDIM 64
#define MTOT (BB * SS)                          // 8192
#define HEADTOT ((size_t)BB * HH * SS * HDIM)   // 8,388,608

// Scratch
__device__ float g_qh[BB * HH * SS * HDIM];
__device__ float g_att[BB * HH * SS * HDIM];
__device__ float g_kt[BB * HH * SS * HDIM];     // K head-layout, RNA tf32 pre-rounded
__device__ float g_vt[BB * HH * HDIM * SS];     // V transposed [b][h][d][s], pre-rounded

__device__ __forceinline__ uint32_t smem_u32(const void* p) {
    uint32_t a;
    asm("{ .reg .u64 t; cvta.to.shared.u64 t, %1; cvt.u32.u64 %0, t; }"
        : "=r"(a) : "l"(p));
    return a;
}

__device__ __forceinline__ uint32_t f2tf(float f) {
    uint32_t u;
    asm("cvt.rna.tf32.f32 %0, %1;" : "=r"(u) : "f"(f));
    return u;
}

__device__ __forceinline__ float rnd_tf(float f) {
    return __uint_as_float(f2tf(f));
}

__device__ __forceinline__ void split_tf(float v, uint32_t& hi, uint32_t& lo) {
    hi = f2tf(v);
    lo = f2tf(v - __uint_as_float(hi));
}

__device__ __forceinline__ void mma8(float* c, const uint32_t* a,
                                     uint32_t b0, uint32_t b1) {
    asm volatile(
        "mma.sync.aligned.m16n8k8.row.col.f32.tf32.tf32.f32 "
        "{%0,%1,%2,%3}, {%4,%5,%6,%7}, {%8,%9}, {%0,%1,%2,%3};"
        : "+f"(c[0]), "+f"(c[1]), "+f"(c[2]), "+f"(c[3])
        : "r"(a[0]), "r"(a[1]), "r"(a[2]), "r"(a[3]), "r"(b0), "r"(b1));
}

// exp2(z) for z <= 0, FMA-pipe only (no MUFU). ~5e-5 rel err.
__device__ __forceinline__ float exp2p(float z) {
    z = fmaxf(z, -100.f);
    float k = z + 12582912.f;            // 1.5*2^23: round-to-nearest-int
    int nb = __float_as_int(k);
    float f = z - (k - 12582912.f);      // f in [-0.5, 0.5]
    float p = 0.00961813f;
    p = fmaf(p, f, 0.05550410f);
    p = fmaf(p, f, 0.24022651f);
    p = fmaf(p, f, 0.69314718f);
    p = fmaf(p, f, 1.0f);
    return p * __int_as_float((nb << 23) + 0x3F800000);
}

// ---------------------------------------------------------------------------
// Tensor-core GEMM (mma.sync tf32): Y = X @ W^T + bias.
// YT_MODE: 0 = none; 1 = transposed RNA-rounded copy [b][h][d][s] (V);
//          2 = head-layout RNA-rounded copy (K).
// ---------------------------------------------------------------------------
#define GSTRIDE 36
#define GTILEF (128 * GSTRIDE)
#define GSMEM_BYTES (2 * 2 * GTILEF * 4)   // 73728

template <bool IN_HEADS, bool OUT_HEADS, int YT_MODE>
__global__ void __launch_bounds__(256) gemm_mma(
    const float* __restrict__ X, const float* __restrict__ W,
    const float* __restrict__ bias, float* __restrict__ Y,
    float* __restrict__ YT)
{
    extern __shared__ float sm[];
    const int tid = threadIdx.x;
    const int wid = tid >> 5, lane = tid & 31;
    const int g = lane >> 2, t = lane & 3;
    const int m0 = blockIdx.y * 128, n0 = blockIdx.x * 128;
    const int wm0 = (wid >> 1) * 32, wn0 = (wid & 1) * 64;

    float c[2][8][4];
    #pragma unroll
    for (int i = 0; i < 2; i++)
        #pragma unroll
        for (int j = 0; j < 8; j++)
            #pragma unroll
            for (int r = 0; r < 4; r++) c[i][j][r] = 0.f;

    auto issue_loads = [&](int k0, int s) {
        float* As = sm + s * 2 * GTILEF;
        float* Bs = As + GTILEF;
        #pragma unroll
        for (int it = 0; it < 4; it++) {
            const int idx = it * 256 + tid;
            const int row = idx >> 3;
            const int c4  = idx & 7;
            const int gk  = k0 + c4 * 4;
            const float* pa;
            if (IN_HEADS) {
                const int gm = m0 + row;
                const int bb_ = gm >> 11;
                const int ss_ = gm & (SS - 1);
                pa = X + ((((size_t)bb_ * HH + (gk >> 6)) * SS + ss_) << 6) + (gk & 63);
            } else {
                pa = X + (size_t)(m0 + row) * DD + gk;
            }
            const uint32_t da = smem_u32(As + row * GSTRIDE + c4 * 4);
            asm volatile("cp.async.cg.shared.global [%0], [%1], 16;"
                         :: "r"(da), "l"(pa));
            const float* pb = W + (size_t)(n0 + row) * DD + gk;
            const uint32_t db = smem_u32(Bs + row * GSTRIDE + c4 * 4);
            asm volatile("cp.async.cg.shared.global [%0], [%1], 16;"
                         :: "r"(db), "l"(pb));
        }
        asm volatile("cp.async.commit_group;" ::: "memory");
    };

    issue_loads(0, 0);
    const int NK = DD / 32;
    for (int ck = 0; ck < NK; ck++) {
        asm volatile("cp.async.wait_group 0;" ::: "memory");
        __syncthreads();
        if (ck + 1 < NK) issue_loads((ck + 1) * 32, (ck + 1) & 1);

        const float* As = sm + (ck & 1) * 2 * GTILEF;
        const float* Bs = As + GTILEF;

        #pragma unroll
        for (int ks = 0; ks < 4; ks++) {
            const int k0 = ks * 8;
            uint32_t a[2][4], b[8][2];
            #pragma unroll
            for (int i = 0; i < 2; i++) {
                const int r = wm0 + 16 * i + g;
                a[i][0] = f2tf(As[r * GSTRIDE + k0 + t]);
                a[i][1] = f2tf(As[(r + 8) * GSTRIDE + k0 + t]);
                a[i][2] = f2tf(As[r * GSTRIDE + k0 + t + 4]);
                a[i][3] = f2tf(As[(r + 8) * GSTRIDE + k0 + t + 4]);
            }
            #pragma unroll
            for (int j = 0; j < 8; j++) {
                const int cn = wn0 + 8 * j + g;
                b[j][0] = f2tf(Bs[cn * GSTRIDE + k0 + t]);
                b[j][1] = f2tf(Bs[cn * GSTRIDE + k0 + t + 4]);
            }
            #pragma unroll
            for (int i = 0; i < 2; i++)
                #pragma unroll
                for (int j = 0; j < 8; j++)
                    mma8(c[i][j], a[i], b[j][0], b[j][1]);
        }
        __syncthreads();
    }

    #pragma unroll
    for (int i = 0; i < 2; i++) {
        const int r0 = m0 + wm0 + 16 * i + g;
        const int r1 = r0 + 8;
        #pragma unroll
        for (int j = 0; j < 8; j++) {
            const int gn = n0 + wn0 + 8 * j + 2 * t;
            const float bx = __ldg(bias + gn);
            const float by = __ldg(bias + gn + 1);
            float2 o0 = make_float2(c[i][j][0] + bx, c[i][j][1] + by);
            float2 o1 = make_float2(c[i][j][2] + bx, c[i][j][3] + by);
            if (OUT_HEADS) {
                const int hb = gn >> 6, hc = gn & 63;
                const int b0_ = r0 >> 11, s0_ = r0 & (SS - 1);
                const int b1_ = r1 >> 11, s1_ = r1 & (SS - 1);
                const size_t y0 = ((((size_t)b0_ * HH + hb) * SS + s0_) << 6) + hc;
                const size_t y1 = ((((size_t)b1_ * HH + hb) * SS + s1_) << 6) + hc;
                *reinterpret_cast<float2*>(Y + y0) = o0;
                *reinterpret_cast<float2*>(Y + y1) = o1;
                if (YT_MODE == 1) {
                    // transposed, pre-rounded (flash V operand)
                    float* yt0 = YT + (((size_t)b0_ * HH + hb) * HDIM + hc) * SS + s0_;
                    float* yt1 = YT + (((size_t)b1_ * HH + hb) * HDIM + hc) * SS + s1_;
                    yt0[0] = rnd_tf(o0.x); yt0[SS] = rnd_tf(o0.y);
                    yt1[0] = rnd_tf(o1.x); yt1[SS] = rnd_tf(o1.y);
                } else if (YT_MODE == 2) {
                    // same head layout, pre-rounded (flash K operand)
                    *reinterpret_cast<float2*>(YT + y0) =
                        make_float2(rnd_tf(o0.x), rnd_tf(o0.y));
                    *reinterpret_cast<float2*>(YT + y1) =
                        make_float2(rnd_tf(o1.x), rnd_tf(o1.y));
                }
            } else {
                *reinterpret_cast<float2*>(Y + (size_t)r0 * DD + gn) = o0;
                *reinterpret_cast<float2*>(Y + (size_t)r1 * DD + gn) = o1;
            }
        }
    }
}

// ---------------------------------------------------------------------------
// Tensor-core causal flash attention, cp.async double-buffered K/V staging.
// K/V^T operands are PRE-ROUNDED (RNA tf32) by the projection epilogues, so
// raw-bit staging == RNA precision. QK uses split-Q (hi+lo); PV single tf32.
// ---------------------------------------------------------------------------
#define FPAD 68
#define FTILE (64 * FPAD)
#define FSMEM_BYTES (5 * FTILE * 4)   // Kb[2] + Vb[2] + Pb = 87040

__global__ void __launch_bounds__(128, 2) flash_tc(
    const float* __restrict__ qh, const float* __restrict__ kt,
    const float* __restrict__ vt, float* __restrict__ oh)
{
    extern __shared__ float fsm[];
    float* Kb = fsm;                    // [2][64][FPAD] prerounded K[key][d]
    float* Vb = fsm + 2 * FTILE;        // [2][64][FPAD] prerounded V^T[d][key]
    float* Pb = fsm + 4 * FTILE;        // [64][FPAD]

    const int tid = threadIdx.x;
    const int w = tid >> 5, lane = tid & 31;
    const int g = lane >> 2, t = lane & 3;
    const int qi = 31 - (int)blockIdx.x;      // biggest blocks first
    const int h = blockIdx.y, b = blockIdx.z;
    const size_t hoff = ((size_t)b * HH + h) * SS * HDIM;
    const float* vtb = vt + ((size_t)b * HH + h) * HDIM * SS;
    const int q0 = qi * 64;
    const float CLOG = 0.18033688011112042f;  // 0.125 * log2(e)

    const int sr = tid >> 4;            // staging base row (0..7), step 8
    const int sc = (tid & 15) * 4;      // 16B column group

    auto issue_tile = [&](int jt, int buf) {
        float* kd = Kb + buf * FTILE;
        float* vd = Vb + buf * FTILE;
        const int kb = jt * 64;
        #pragma unroll
        for (int i = 0; i < 8; i++) {
            const int r = sr + i * 8;
            const float* ks = kt + hoff + (size_t)(kb + r) * HDIM + sc;
            const float* vs = vtb + (size_t)r * SS + kb + sc;
            asm volatile("cp.async.cg.shared.global [%0], [%1], 16;"
                         :: "r"(smem_u32(kd + r * FPAD + sc)), "l"(ks));
            asm volatile("cp.async.cg.shared.global [%0], [%1], 16;"
                         :: "r"(smem_u32(vd + r * FPAD + sc)), "l"(vs));
        }
        asm volatile("cp.async.commit_group;" ::: "memory");
    };

    issue_tile(0, 0);   // prefetch tile 0 before anything else

    // ---- stage Q tile into Pb, pull A-fragments (hi/lo) into registers ----
    #pragma unroll
    for (int i = 0; i < 8; i++) {
        const int idx = i * 128 + tid;
        const int r = idx >> 4, c4 = idx & 15;
        float4 qv = *reinterpret_cast<const float4*>(
            qh + hoff + (size_t)(q0 + r) * HDIM + c4 * 4);
        *reinterpret_cast<float4*>(Pb + r * FPAD + c4 * 4) = qv;
    }
    __syncthreads();

    uint32_t qhi[8][4], qlo[8][4];
    const int row0 = w * 16 + g;
    #pragma unroll
    for (int ks = 0; ks < 8; ks++) {
        const int c0 = 8 * ks + t, c1 = c0 + 4;
        split_tf(Pb[row0 * FPAD + c0],       qhi[ks][0], qlo[ks][0]);
        split_tf(Pb[(row0 + 8) * FPAD + c0], qhi[ks][1], qlo[ks][1]);
        split_tf(Pb[row0 * FPAD + c1],       qhi[ks][2], qlo[ks][2]);
        split_tf(Pb[(row0 + 8) * FPAD + c1], qhi[ks][3], qlo[ks][3]);
    }

    float o[8][4];
    #pragma unroll
    for (int nt = 0; nt < 8; nt++)
        #pragma unroll
        for (int r = 0; r < 4; r++) o[nt][r] = 0.f;
    float mx0 = -1e30f, mx1 = -1e30f, l0 = 0.f, l1 = 0.f;

    const int rg0 = q0 + row0;          // global row for c0/c1
    const int rg1 = rg0 + 8;            // global row for c2/c3

    for (int jt = 0; jt <= qi; jt++) {
        const int kb = jt * 64;
        const int buf = jt & 1;

        if (jt < qi) {
            issue_tile(jt + 1, buf ^ 1);
            asm volatile("cp.async.wait_group 1;" ::: "memory");
        } else {
            asm volatile("cp.async.wait_group 0;" ::: "memory");
        }
        __syncthreads();

        const uint32_t* Kt = reinterpret_cast<const uint32_t*>(Kb + buf * FTILE);
        const uint32_t* VT = reinterpret_cast<const uint32_t*>(Vb + buf * FTILE);

        // ---- scores S = Q K^T (split-Q: 2 MMAs share b-frags) ----
        float s[8][4];
        #pragma unroll
        for (int nt = 0; nt < 8; nt++) {
            s[nt][0] = s[nt][1] = s[nt][2] = s[nt][3] = 0.f;
            const uint32_t* kr = Kt + (8 * nt + g) * FPAD;
            #pragma unroll
            for (int ks = 0; ks < 8; ks++) {
                const uint32_t b0 = kr[8 * ks + t];
                const uint32_t b1 = kr[8 * ks + t + 4];
                mma8(s[nt], qhi[ks], b0, b1);
                mma8(s[nt], qlo[ks], b0, b1);
            }
        }

        // ---- causal mask (diagonal tile only) ----
        if (jt == qi) {
            #pragma unroll
            for (int nt = 0; nt < 8; nt++) {
                const int col = kb + 8 * nt + 2 * t;
                if (col > rg0)     s[nt][0] = -1e30f;
                if (col + 1 > rg0) s[nt][1] = -1e30f;
                if (col > rg1)     s[nt][2] = -1e30f;
                if (col + 1 > rg1) s[nt][3] = -1e30f;
            }
        }

        // ---- online softmax ----
        float sm0 = -1e30f, sm1 = -1e30f;
        #pragma unroll
        for (int nt = 0; nt < 8; nt++) {
            sm0 = fmaxf(sm0, fmaxf(s[nt][0], s[nt][1]));
            sm1 = fmaxf(sm1, fmaxf(s[nt][2], s[nt][3]));
        }
        sm0 = fmaxf(sm0, __shfl_xor_sync(0xffffffffu, sm0, 1));
        sm0 = fmaxf(sm0, __shfl_xor_sync(0xffffffffu, sm0, 2));
        sm1 = fmaxf(sm1, __shfl_xor_sync(0xffffffffu, sm1, 1));
        sm1 = fmaxf(sm1, __shfl_xor_sync(0xffffffffu, sm1, 2));

        const float nm0 = fmaxf(mx0, sm0), nm1 = fmaxf(mx1, sm1);
        const float f0 = exp2p((mx0 - nm0) * CLOG);
        const float f1 = exp2p((mx1 - nm1) * CLOG);
        mx0 = nm0; mx1 = nm1;
        l0 *= f0; l1 *= f1;
        #pragma unroll
        for (int nt = 0; nt < 8; nt++) {
            o[nt][0] *= f0; o[nt][1] *= f0;
            o[nt][2] *= f1; o[nt][3] *= f1;
        }

        float* Pw = Pb + w * 16 * FPAD;
        #pragma unroll
        for (int nt = 0; nt < 8; nt++) {
            const float p0 = exp2p((s[nt][0] - mx0) * CLOG);
            const float p1 = exp2p((s[nt][1] - mx0) * CLOG);
            const float p2 = exp2p((s[nt][2] - mx1) * CLOG);
            const float p3 = exp2p((s[nt][3] - mx1) * CLOG);
            l0 += p0 + p1;
            l1 += p2 + p3;
            *reinterpret_cast<float2*>(Pw + g * FPAD + 8 * nt + 2 * t) =
                make_float2(p0, p1);
            *reinterpret_cast<float2*>(Pw + (g + 8) * FPAD + 8 * nt + 2 * t) =
                make_float2(p2, p3);
        }
        __syncwarp();

        // ---- O += P V  (single tf32 MMA; P rounded RNA at fragment load) ----
        #pragma unroll
        for (int kk = 0; kk < 8; kk++) {
            uint32_t ap[4];
            const int c0 = 8 * kk + t, c1 = c0 + 4;
            ap[0] = f2tf(Pw[g * FPAD + c0]);
            ap[1] = f2tf(Pw[(g + 8) * FPAD + c0]);
            ap[2] = f2tf(Pw[g * FPAD + c1]);
            ap[3] = f2tf(Pw[(g + 8) * FPAD + c1]);
            #pragma unroll
            for (int nt = 0; nt < 8; nt++) {
                const uint32_t* vr = VT + (8 * nt + g) * FPAD;
                mma8(o[nt], ap, vr[8 * kk + t], vr[8 * kk + t + 4]);
            }
        }
        __syncthreads();   // all warps done reading this buffer before reuse
    }

    // ---- finalize ----
    l0 += __shfl_xor_sync(0xffffffffu, l0, 1);
    l0 += __shfl_xor_sync(0xffffffffu, l0, 2);
    l1 += __shfl_xor_sync(0xffffffffu, l1, 1);
    l1 += __shfl_xor_sync(0xffffffffu, l1, 2);
    const float i0 = 1.f / l0, i1 = 1.f / l1;

    float* o0p = oh + hoff + (size_t)rg0 * HDIM;
    float* o1p = oh + hoff + (size_t)rg1 * HDIM;
    #pragma unroll
    for (int nt = 0; nt < 8; nt++) {
        const int d = 8 * nt + 2 * t;
        *reinterpret_cast<float2*>(o0p + d) = make_float2(o[nt][0] * i0, o[nt][1] * i0);
        *reinterpret_cast<float2*>(o1p + d) = make_float2(o[nt][2] * i1, o[nt][3] * i1);
    }
}

// ---------------------------------------------------------------------------
// kernel_launch
// Inputs: 0=q 1=k 2=v 3=mask 4=Wq 5=bq 6=Wk 7=bk 8=Wv 9=bv 10=Wo 11=bo
// Output: [out (B,S,D)] [kh (B,H,S,HD)] [vh (B,H,S,HD)]
// ---------------------------------------------------------------------------
extern "C" void kernel_launch(void* const* d_in, const int* in_sizes, int n_in,
                              void* d_out, int out_size)
{
    const float* q  = (const float*)d_in[0];
    const float* k  = (const float*)d_in[1];
    const float* v  = (const float*)d_in[2];
    const float* Wq = (const float*)d_in[4];
    const float* bq = (const float*)d_in[5];
    const float* Wk = (const float*)d_in[6];
    const float* bk = (const float*)d_in[7];
    const float* Wv = (const float*)d_in[8];
    const float* bv = (const float*)d_in[9];
    const float* Wo = (const float*)d_in[10];
    const float* bo = (const float*)d_in[11];

    float* out = (float*)d_out;
    float* khp = out + HEADTOT;
    float* vhp = khp + HEADTOT;

    float *qh_p = nullptr, *att_p = nullptr, *kt_p = nullptr, *vt_p = nullptr;
    cudaGetSymbolAddress((void**)&qh_p, g_qh);
    cudaGetSymbolAddress((void**)&att_p, g_att);
    cudaGetSymbolAddress((void**)&kt_p, g_kt);
    cudaGetSymbolAddress((void**)&vt_p, g_vt);

    cudaFuncSetAttribute(gemm_mma<false, true, 0>,
                         cudaFuncAttributeMaxDynamicSharedMemorySize, GSMEM_BYTES);
    cudaFuncSetAttribute(gemm_mma<false, true, 1>,
                         cudaFuncAttributeMaxDynamicSharedMemorySize, GSMEM_BYTES);
    cudaFuncSetAttribute(gemm_mma<false, true, 2>,
                         cudaFuncAttributeMaxDynamicSharedMemorySize, GSMEM_BYTES);
    cudaFuncSetAttribute(gemm_mma<true, false, 0>,
                         cudaFuncAttributeMaxDynamicSharedMemorySize, GSMEM_BYTES);
    cudaFuncSetAttribute(flash_tc,
                         cudaFuncAttributeMaxDynamicSharedMemorySize, FSMEM_BYTES);

    dim3 grd(DD / 128, MTOT / 128);   // (8, 64)

    gemm_mma<false, true, 0><<<grd, 256, GSMEM_BYTES>>>(q, Wq, bq, qh_p, nullptr);
    gemm_mma<false, true, 2><<<grd, 256, GSMEM_BYTES>>>(k, Wk, bk, khp, kt_p);
    gemm_mma<false, true, 1><<<grd, 256, GSMEM_BYTES>>>(v, Wv, bv, vhp, vt_p);

    flash_tc<<<dim3(32, HH, BB), 128, FSMEM_BYTES>>>(qh_p, kt_p, vt_p, att_p);

    gemm_mma<true, false, 0><<<grd, 256, GSMEM_BYTES>>>(att_p, Wo, bo, out, nullptr);
}

// round 8
// speedup vs baseline: 4.6855x; 1.1063x over previous
#include <cuda_runtime.h>
#include <math.h>
#include <stdint.h>

// Problem constants
#define BB 4
#define SS 2048
#define DD 1024
#define HH 16
#define HDIM 64
#define MTOT (BB * SS)                          // 8192
#define HEADTOT ((size_t)BB * HH * SS * HDIM)   // 8,388,608

// Scratch
__device__ float g_qh[BB * HH * SS * HDIM];
__device__ float g_att[BB * HH * SS * HDIM];
__device__ float g_kt[BB * HH * SS * HDIM];     // K head-layout, RNA-rounded, d-permuted
__device__ float g_vt[BB * HH * HDIM * SS];     // V^T [b][h][d][s], RNA-rounded, s-permuted

__device__ __forceinline__ uint32_t smem_u32(const void* p) {
    uint32_t a;
    asm("{ .reg .u64 t; cvta.to.shared.u64 t, %1; cvt.u32.u64 %0, t; }"
        : "=r"(a) : "l"(p));
    return a;
}

__device__ __forceinline__ uint32_t f2tf(float f) {
    uint32_t u;
    asm("cvt.rna.tf32.f32 %0, %1;" : "=r"(u) : "f"(f));
    return u;
}

__device__ __forceinline__ float rnd_tf(float f) {
    return __uint_as_float(f2tf(f));
}

__device__ __forceinline__ void split_tf(float v, uint32_t& hi, uint32_t& lo) {
    hi = f2tf(v);
    lo = f2tf(v - __uint_as_float(hi));
}

// k-slot pairing permutation within 8-groups: p(j) = (j&3)*2 + (j>>2).
// Slots (t, t+4) land at adjacent positions (2t, 2t+1) -> LDS.64 b-fragments.
__device__ __forceinline__ int kperm(int j) { return ((j & 3) << 1) | (j >> 2); }

__device__ __forceinline__ void mma8(float* c, const uint32_t* a,
                                     uint32_t b0, uint32_t b1) {
    asm volatile(
        "mma.sync.aligned.m16n8k8.row.col.f32.tf32.tf32.f32 "
        "{%0,%1,%2,%3}, {%4,%5,%6,%7}, {%8,%9}, {%0,%1,%2,%3};"
        : "+f"(c[0]), "+f"(c[1]), "+f"(c[2]), "+f"(c[3])
        : "r"(a[0]), "r"(a[1]), "r"(a[2]), "r"(a[3]), "r"(b0), "r"(b1));
}

// exp2(z) for z <= 0, FMA-pipe only (no MUFU). ~5e-5 rel err.
__device__ __forceinline__ float exp2p(float z) {
    z = fmaxf(z, -100.f);
    float k = z + 12582912.f;            // 1.5*2^23: round-to-nearest-int
    int nb = __float_as_int(k);
    float f = z - (k - 12582912.f);      // f in [-0.5, 0.5]
    float p = 0.00961813f;
    p = fmaf(p, f, 0.05550410f);
    p = fmaf(p, f, 0.24022651f);
    p = fmaf(p, f, 0.69314718f);
    p = fmaf(p, f, 1.0f);
    return p * __int_as_float((nb << 23) + 0x3F800000);
}

// ---------------------------------------------------------------------------
// Tensor-core GEMM (mma.sync tf32): Y = X @ W^T + bias.
// 128x128 CTA tile, 128 threads = 4 warps of 64x64 (LDS/mma = 1.0).
// YT_MODE: 0 none; 1 = V: transposed RNA copy [b][h][d][s], s-permuted;
//          2 = K: head-layout RNA copy, d-permuted.
// ---------------------------------------------------------------------------
#define GSTRIDE 36
#define GTILEF (128 * GSTRIDE)
#define GSMEM_BYTES (2 * 2 * GTILEF * 4)   // 73728

template <bool IN_HEADS, bool OUT_HEADS, int YT_MODE>
__global__ void __launch_bounds__(128) gemm_mma(
    const float* __restrict__ X, const float* __restrict__ W,
    const float* __restrict__ bias, float* __restrict__ Y,
    float* __restrict__ YT)
{
    extern __shared__ float sm[];
    const int tid = threadIdx.x;
    const int wid = tid >> 5, lane = tid & 31;
    const int g = lane >> 2, t = lane & 3;
    const int m0 = blockIdx.y * 128, n0 = blockIdx.x * 128;
    const int wm0 = (wid >> 1) * 64, wn0 = (wid & 1) * 64;

    float c[4][8][4];
    #pragma unroll
    for (int i = 0; i < 4; i++)
        #pragma unroll
        for (int j = 0; j < 8; j++)
            #pragma unroll
            for (int r = 0; r < 4; r++) c[i][j][r] = 0.f;

    auto issue_loads = [&](int k0, int s) {
        float* As = sm + s * 2 * GTILEF;
        float* Bs = As + GTILEF;
        #pragma unroll
        for (int it = 0; it < 8; it++) {
            const int idx = it * 128 + tid;
            const int row = idx >> 3;
            const int c4  = idx & 7;
            const int gk  = k0 + c4 * 4;
            const float* pa;
            if (IN_HEADS) {
                const int gm = m0 + row;
                const int bb_ = gm >> 11;
                const int ss_ = gm & (SS - 1);
                pa = X + ((((size_t)bb_ * HH + (gk >> 6)) * SS + ss_) << 6) + (gk & 63);
            } else {
                pa = X + (size_t)(m0 + row) * DD + gk;
            }
            const uint32_t da = smem_u32(As + row * GSTRIDE + c4 * 4);
            asm volatile("cp.async.cg.shared.global [%0], [%1], 16;"
                         :: "r"(da), "l"(pa));
            const float* pb = W + (size_t)(n0 + row) * DD + gk;
            const uint32_t db = smem_u32(Bs + row * GSTRIDE + c4 * 4);
            asm volatile("cp.async.cg.shared.global [%0], [%1], 16;"
                         :: "r"(db), "l"(pb));
        }
        asm volatile("cp.async.commit_group;" ::: "memory");
    };

    issue_loads(0, 0);
    const int NK = DD / 32;
    for (int ck = 0; ck < NK; ck++) {
        asm volatile("cp.async.wait_group 0;" ::: "memory");
        __syncthreads();
        if (ck + 1 < NK) issue_loads((ck + 1) * 32, (ck + 1) & 1);

        const float* As = sm + (ck & 1) * 2 * GTILEF;
        const float* Bs = As + GTILEF;

        #pragma unroll
        for (int ks = 0; ks < 4; ks++) {
            const int k0 = ks * 8;
            uint32_t a[4][4], b[8][2];
            #pragma unroll
            for (int i = 0; i < 4; i++) {
                const int r = wm0 + 16 * i + g;
                a[i][0] = f2tf(As[r * GSTRIDE + k0 + t]);
                a[i][1] = f2tf(As[(r + 8) * GSTRIDE + k0 + t]);
                a[i][2] = f2tf(As[r * GSTRIDE + k0 + t + 4]);
                a[i][3] = f2tf(As[(r + 8) * GSTRIDE + k0 + t + 4]);
            }
            #pragma unroll
            for (int j = 0; j < 8; j++) {
                const int cn = wn0 + 8 * j + g;
                b[j][0] = f2tf(Bs[cn * GSTRIDE + k0 + t]);
                b[j][1] = f2tf(Bs[cn * GSTRIDE + k0 + t + 4]);
            }
            #pragma unroll
            for (int i = 0; i < 4; i++)
                #pragma unroll
                for (int j = 0; j < 8; j++)
                    mma8(c[i][j], a[i], b[j][0], b[j][1]);
        }
        __syncthreads();
    }

    // per-thread permuted positions for YT writes
    const int px = kperm(2 * t);        // position of col offset 2t within 8-group
    const int py = kperm(2 * t + 1);
    const int pg = kperm(g);            // position of s offset g within 8-group

    #pragma unroll
    for (int i = 0; i < 4; i++) {
        const int r0 = m0 + wm0 + 16 * i + g;
        const int r1 = r0 + 8;
        #pragma unroll
        for (int j = 0; j < 8; j++) {
            const int gn = n0 + wn0 + 8 * j + 2 * t;
            const float bx = __ldg(bias + gn);
            const float by = __ldg(bias + gn + 1);
            float2 o0 = make_float2(c[i][j][0] + bx, c[i][j][1] + by);
            float2 o1 = make_float2(c[i][j][2] + bx, c[i][j][3] + by);
            if (OUT_HEADS) {
                const int hb = gn >> 6, hc = gn & 63;
                const int b0_ = r0 >> 11, s0_ = r0 & (SS - 1);
                const int b1_ = r1 >> 11, s1_ = r1 & (SS - 1);
                const size_t y0 = ((((size_t)b0_ * HH + hb) * SS + s0_) << 6) + hc;
                const size_t y1 = ((((size_t)b1_ * HH + hb) * SS + s1_) << 6) + hc;
                *reinterpret_cast<float2*>(Y + y0) = o0;
                *reinterpret_cast<float2*>(Y + y1) = o1;
                if (YT_MODE == 1) {
                    // V^T copy, pre-rounded, s permuted within 8-groups
                    const int s0p = (s0_ & ~7) | pg;
                    const int s1p = (s1_ & ~7) | pg;
                    float* yt0 = YT + (((size_t)b0_ * HH + hb) * HDIM + hc) * SS + s0p;
                    float* yt1 = YT + (((size_t)b1_ * HH + hb) * HDIM + hc) * SS + s1p;
                    yt0[0] = rnd_tf(o0.x); yt0[SS] = rnd_tf(o0.y);
                    yt1[0] = rnd_tf(o1.x); yt1[SS] = rnd_tf(o1.y);
                } else if (YT_MODE == 2) {
                    // K copy, pre-rounded, d permuted within 8-groups
                    const size_t base0 = y0 - (hc & 7);   // hc&7 == 2t
                    const size_t base1 = y1 - (hc & 7);
                    YT[base0 + px] = rnd_tf(o0.x);
                    YT[base0 + py] = rnd_tf(o0.y);
                    YT[base1 + px] = rnd_tf(o1.x);
                    YT[base1 + py] = rnd_tf(o1.y);
                }
            } else {
                *reinterpret_cast<float2*>(Y + (size_t)r0 * DD + gn) = o0;
                *reinterpret_cast<float2*>(Y + (size_t)r1 * DD + gn) = o1;
            }
        }
    }
}

// ---------------------------------------------------------------------------
// Tensor-core causal flash attention, cp.async double-buffered K/V staging.
// K (d-permuted) and V^T (s-permuted) are pre-rounded by projection epilogues;
// the permutation makes every b-fragment a single LDS.64.
// QK uses split-Q (hi+lo); PV single tf32 (P rounded RNA at fragment load).
// ---------------------------------------------------------------------------
#define KVPAD 72
#define KVTILE (64 * KVPAD)
#define PPAD 68
#define FSMEM_BYTES ((4 * KVTILE + 64 * PPAD) * 4)   // 91136

__global__ void __launch_bounds__(128, 2) flash_tc(
    const float* __restrict__ qh, const float* __restrict__ kt,
    const float* __restrict__ vt, float* __restrict__ oh)
{
    extern __shared__ float fsm[];
    float* Kb = fsm;                    // [2][64][KVPAD] K[key][d_perm]
    float* Vb = fsm + 2 * KVTILE;       // [2][64][KVPAD] V^T[d][key_perm]
    float* Pb = fsm + 4 * KVTILE;       // [64][PPAD]

    const int tid = threadIdx.x;
    const int w = tid >> 5, lane = tid & 31;
    const int g = lane >> 2, t = lane & 3;
    const int qi = 31 - (int)blockIdx.x;      // biggest blocks first
    const int h = blockIdx.y, b = blockIdx.z;
    const size_t hoff = ((size_t)b * HH + h) * SS * HDIM;
    const float* vtb = vt + ((size_t)b * HH + h) * HDIM * SS;
    const int q0 = qi * 64;
    const float CLOG = 0.18033688011112042f;  // 0.125 * log2(e)

    const int sr = tid >> 4;            // staging base row (0..7), step 8
    const int sc = (tid & 15) * 4;      // 16B column group

    auto issue_tile = [&](int jt, int buf) {
        float* kd = Kb + buf * KVTILE;
        float* vd = Vb + buf * KVTILE;
        const int kb = jt * 64;
        #pragma unroll
        for (int i = 0; i < 8; i++) {
            const int r = sr + i * 8;
            const float* ks = kt + hoff + (size_t)(kb + r) * HDIM + sc;
            const float* vs = vtb + (size_t)r * SS + kb + sc;
            asm volatile("cp.async.cg.shared.global [%0], [%1], 16;"
                         :: "r"(smem_u32(kd + r * KVPAD + sc)), "l"(ks));
            asm volatile("cp.async.cg.shared.global [%0], [%1], 16;"
                         :: "r"(smem_u32(vd + r * KVPAD + sc)), "l"(vs));
        }
        asm volatile("cp.async.commit_group;" ::: "memory");
    };

    issue_tile(0, 0);   // prefetch tile 0 before anything else

    // ---- stage Q tile into Pb, pull A-fragments (hi/lo) into registers ----
    #pragma unroll
    for (int i = 0; i < 8; i++) {
        const int idx = i * 128 + tid;
        const int r = idx >> 4, c4 = idx & 15;
        float4 qv = *reinterpret_cast<const float4*>(
            qh + hoff + (size_t)(q0 + r) * HDIM + c4 * 4);
        *reinterpret_cast<float4*>(Pb + r * PPAD + c4 * 4) = qv;
    }
    __syncthreads();

    uint32_t qhi[8][4], qlo[8][4];
    const int row0 = w * 16 + g;
    #pragma unroll
    for (int ks = 0; ks < 8; ks++) {
        const int c0 = 8 * ks + t, c1 = c0 + 4;
        split_tf(Pb[row0 * PPAD + c0],       qhi[ks][0], qlo[ks][0]);
        split_tf(Pb[(row0 + 8) * PPAD + c0], qhi[ks][1], qlo[ks][1]);
        split_tf(Pb[row0 * PPAD + c1],       qhi[ks][2], qlo[ks][2]);
        split_tf(Pb[(row0 + 8) * PPAD + c1], qhi[ks][3], qlo[ks][3]);
    }

    float o[8][4];
    #pragma unroll
    for (int nt = 0; nt < 8; nt++)
        #pragma unroll
        for (int r = 0; r < 4; r++) o[nt][r] = 0.f;
    float mx0 = -1e30f, mx1 = -1e30f, l0 = 0.f, l1 = 0.f;

    const int rg0 = q0 + row0;          // global row for c0/c1
    const int rg1 = rg0 + 8;            // global row for c2/c3

    for (int jt = 0; jt <= qi; jt++) {
        const int kb = jt * 64;
        const int buf = jt & 1;

        if (jt < qi) {
            issue_tile(jt + 1, buf ^ 1);
            asm volatile("cp.async.wait_group 1;" ::: "memory");
        } else {
            asm volatile("cp.async.wait_group 0;" ::: "memory");
        }
        __syncthreads();

        const uint32_t* Kt = reinterpret_cast<const uint32_t*>(Kb + buf * KVTILE);
        const uint32_t* VT = reinterpret_cast<const uint32_t*>(Vb + buf * KVTILE);

        // ---- scores S = Q K^T (split-Q; b-frags are LDS.64 pairs) ----
        float s[8][4];
        #pragma unroll
        for (int nt = 0; nt < 8; nt++) {
            s[nt][0] = s[nt][1] = s[nt][2] = s[nt][3] = 0.f;
            const uint32_t* kr = Kt + (8 * nt + g) * KVPAD;
            #pragma unroll
            for (int ks = 0; ks < 8; ks++) {
                const uint2 kb2 = *reinterpret_cast<const uint2*>(kr + 8 * ks + 2 * t);
                mma8(s[nt], qhi[ks], kb2.x, kb2.y);
                mma8(s[nt], qlo[ks], kb2.x, kb2.y);
            }
        }

        // ---- causal mask (diagonal tile only) ----
        if (jt == qi) {
            #pragma unroll
            for (int nt = 0; nt < 8; nt++) {
                const int col = kb + 8 * nt + 2 * t;
                if (col > rg0)     s[nt][0] = -1e30f;
                if (col + 1 > rg0) s[nt][1] = -1e30f;
                if (col > rg1)     s[nt][2] = -1e30f;
                if (col + 1 > rg1) s[nt][3] = -1e30f;
            }
        }

        // ---- online softmax ----
        float sm0 = -1e30f, sm1 = -1e30f;
        #pragma unroll
        for (int nt = 0; nt < 8; nt++) {
            sm0 = fmaxf(sm0, fmaxf(s[nt][0], s[nt][1]));
            sm1 = fmaxf(sm1, fmaxf(s[nt][2], s[nt][3]));
        }
        sm0 = fmaxf(sm0, __shfl_xor_sync(0xffffffffu, sm0, 1));
        sm0 = fmaxf(sm0, __shfl_xor_sync(0xffffffffu, sm0, 2));
        sm1 = fmaxf(sm1, __shfl_xor_sync(0xffffffffu, sm1, 1));
        sm1 = fmaxf(sm1, __shfl_xor_sync(0xffffffffu, sm1, 2));

        const float nm0 = fmaxf(mx0, sm0), nm1 = fmaxf(mx1, sm1);
        const float f0 = exp2p((mx0 - nm0) * CLOG);
        const float f1 = exp2p((mx1 - nm1) * CLOG);
        mx0 = nm0; mx1 = nm1;
        l0 *= f0; l1 *= f1;
        #pragma unroll
        for (int nt = 0; nt < 8; nt++) {
            o[nt][0] *= f0; o[nt][1] *= f0;
            o[nt][2] *= f1; o[nt][3] *= f1;
        }

        float* Pw = Pb + w * 16 * PPAD;
        #pragma unroll
        for (int nt = 0; nt < 8; nt++) {
            const float p0 = exp2p((s[nt][0] - mx0) * CLOG);
            const float p1 = exp2p((s[nt][1] - mx0) * CLOG);
            const float p2 = exp2p((s[nt][2] - mx1) * CLOG);
            const float p3 = exp2p((s[nt][3] - mx1) * CLOG);
            l0 += p0 + p1;
            l1 += p2 + p3;
            *reinterpret_cast<float2*>(Pw + g * PPAD + 8 * nt + 2 * t) =
                make_float2(p0, p1);
            *reinterpret_cast<float2*>(Pw + (g + 8) * PPAD + 8 * nt + 2 * t) =
                make_float2(p2, p3);
        }
        __syncwarp();

        // ---- O += P V  (V b-frags are LDS.64 pairs via s-permutation) ----
        #pragma unroll
        for (int kk = 0; kk < 8; kk++) {
            uint32_t ap[4];
            const int c0 = 8 * kk + t, c1 = c0 + 4;
            ap[0] = f2tf(Pw[g * PPAD + c0]);
            ap[1] = f2tf(Pw[(g + 8) * PPAD + c0]);
            ap[2] = f2tf(Pw[g * PPAD + c1]);
            ap[3] = f2tf(Pw[(g + 8) * PPAD + c1]);
            #pragma unroll
            for (int nt = 0; nt < 8; nt++) {
                const uint32_t* vr = VT + (8 * nt + g) * KVPAD;
                const uint2 vv = *reinterpret_cast<const uint2*>(vr + 8 * kk + 2 * t);
                mma8(o[nt], ap, vv.x, vv.y);
            }
        }
        __syncthreads();   // all warps done reading this buffer before reuse
    }

    // ---- finalize ----
    l0 += __shfl_xor_sync(0xffffffffu, l0, 1);
    l0 += __shfl_xor_sync(0xffffffffu, l0, 2);
    l1 += __shfl_xor_sync(0xffffffffu, l1, 1);
    l1 += __shfl_xor_sync(0xffffffffu, l1, 2);
    const float i0 = 1.f / l0, i1 = 1.f / l1;

    float* o0p = oh + hoff + (size_t)rg0 * HDIM;
    float* o1p = oh + hoff + (size_t)rg1 * HDIM;
    #pragma unroll
    for (int nt = 0; nt < 8; nt++) {
        const int d = 8 * nt + 2 * t;
        *reinterpret_cast<float2*>(o0p + d) = make_float2(o[nt][0] * i0, o[nt][1] * i0);
        *reinterpret_cast<float2*>(o1p + d) = make_float2(o[nt][2] * i1, o[nt][3] * i1);
    }
}

// ---------------------------------------------------------------------------
// kernel_launch
// Inputs: 0=q 1=k 2=v 3=mask 4=Wq 5=bq 6=Wk 7=bk 8=Wv 9=bv 10=Wo 11=bo
// Output: [out (B,S,D)] [kh (B,H,S,HD)] [vh (B,H,S,HD)]
// ---------------------------------------------------------------------------
extern "C" void kernel_launch(void* const* d_in, const int* in_sizes, int n_in,
                              void* d_out, int out_size)
{
    const float* q  = (const float*)d_in[0];
    const float* k  = (const float*)d_in[1];
    const float* v  = (const float*)d_in[2];
    const float* Wq = (const float*)d_in[4];
    const float* bq = (const float*)d_in[5];
    const float* Wk = (const float*)d_in[6];
    const float* bk = (const float*)d_in[7];
    const float* Wv = (const float*)d_in[8];
    const float* bv = (const float*)d_in[9];
    const float* Wo = (const float*)d_in[10];
    const float* bo = (const float*)d_in[11];

    float* out = (float*)d_out;
    float* khp = out + HEADTOT;
    float* vhp = khp + HEADTOT;

    float *qh_p = nullptr, *att_p = nullptr, *kt_p = nullptr, *vt_p = nullptr;
    cudaGetSymbolAddress((void**)&qh_p, g_qh);
    cudaGetSymbolAddress((void**)&att_p, g_att);
    cudaGetSymbolAddress((void**)&kt_p, g_kt);
    cudaGetSymbolAddress((void**)&vt_p, g_vt);

    cudaFuncSetAttribute(gemm_mma<false, true, 0>,
                         cudaFuncAttributeMaxDynamicSharedMemorySize, GSMEM_BYTES);
    cudaFuncSetAttribute(gemm_mma<false, true, 1>,
                         cudaFuncAttributeMaxDynamicSharedMemorySize, GSMEM_BYTES);
    cudaFuncSetAttribute(gemm_mma<false, true, 2>,
                         cudaFuncAttributeMaxDynamicSharedMemorySize, GSMEM_BYTES);
    cudaFuncSetAttribute(gemm_mma<true, false, 0>,
                         cudaFuncAttributeMaxDynamicSharedMemorySize, GSMEM_BYTES);
    cudaFuncSetAttribute(flash_tc,
                         cudaFuncAttributeMaxDynamicSharedMemorySize, FSMEM_BYTES);

    dim3 grd(DD / 128, MTOT / 128);   // (8, 64)

    gemm_mma<false, true, 0><<<grd, 128, GSMEM_BYTES>>>(q, Wq, bq, qh_p, nullptr);
    gemm_mma<false, true, 2><<<grd, 128, GSMEM_BYTES>>>(k, Wk, bk, khp, kt_p);
    gemm_mma<false, true, 1><<<grd, 128, GSMEM_BYTES>>>(v, Wv, bv, vhp, vt_p);

    flash_tc<<<dim3(32, HH, BB), 128, FSMEM_BYTES>>>(qh_p, kt_p, vt_p, att_p);

    gemm_mma<true, false, 0><<<grd, 128, GSMEM_BYTES>>>(att_p, Wo, bo, out, nullptr);
}

// round 9
// speedup vs baseline: 4.9629x; 1.0592x over previous
#include <cuda_runtime.h>
#include <math.h>
#include <stdint.h>

// Problem constants
#define BB 4
#define SS 2048
#define DD 1024
#define HH 16
#define HDIM 64
#define MTOT (BB * SS)                          // 8192
#define HEADTOT ((size_t)BB * HH * SS * HDIM)   // 8,388,608

// Scratch
__device__ float g_qh[BB * HH * SS * HDIM];
__device__ float g_att[BB * HH * SS * HDIM];
__device__ float g_kt[BB * HH * SS * HDIM];     // K head-layout, RNA-rounded, d-permuted
__device__ float g_vt[BB * HH * HDIM * SS];     // V^T [b][h][d][s], RNA-rounded, s-permuted

__device__ __forceinline__ uint32_t smem_u32(const void* p) {
    uint32_t a;
    asm("{ .reg .u64 t; cvta.to.shared.u64 t, %1; cvt.u32.u64 %0, t; }"
        : "=r"(a) : "l"(p));
    return a;
}

__device__ __forceinline__ uint32_t f2tf(float f) {
    uint32_t u;
    asm("cvt.rna.tf32.f32 %0, %1;" : "=r"(u) : "f"(f));
    return u;
}

__device__ __forceinline__ float rnd_tf(float f) {
    return __uint_as_float(f2tf(f));
}

// k-slot pairing permutation within 8-groups: p(j) = (j&3)*2 + (j>>2).
// Slots (t, t+4) land at adjacent positions (2t, 2t+1) -> LDS.64 b-fragments.
__device__ __forceinline__ int kperm(int j) { return ((j & 3) << 1) | (j >> 2); }

__device__ __forceinline__ void mma8(float* c, const uint32_t* a,
                                     uint32_t b0, uint32_t b1) {
    asm volatile(
        "mma.sync.aligned.m16n8k8.row.col.f32.tf32.tf32.f32 "
        "{%0,%1,%2,%3}, {%4,%5,%6,%7}, {%8,%9}, {%0,%1,%2,%3};"
        : "+f"(c[0]), "+f"(c[1]), "+f"(c[2]), "+f"(c[3])
        : "r"(a[0]), "r"(a[1]), "r"(a[2]), "r"(a[3]), "r"(b0), "r"(b1));
}

// exp2(z) for z <= 0, FMA-pipe only (no MUFU). ~5e-5 rel err.
__device__ __forceinline__ float exp2p(float z) {
    z = fmaxf(z, -100.f);
    float k = z + 12582912.f;            // 1.5*2^23: round-to-nearest-int
    int nb = __float_as_int(k);
    float f = z - (k - 12582912.f);      // f in [-0.5, 0.5]
    float p = 0.00961813f;
    p = fmaf(p, f, 0.05550410f);
    p = fmaf(p, f, 0.24022651f);
    p = fmaf(p, f, 0.69314718f);
    p = fmaf(p, f, 1.0f);
    return p * __int_as_float((nb << 23) + 0x3F800000);
}

// ---------------------------------------------------------------------------
// Tensor-core GEMM (mma.sync tf32): Y = X @ W^T + bias.
// 128x128 CTA tile, 4 warps of 64x64; 3-stage cp.async pipeline (wait_group 1).
// YT_MODE: 0 none; 1 = V: transposed RNA copy [b][h][d][s], s-permuted;
//          2 = K: head-layout RNA copy, d-permuted.
// ---------------------------------------------------------------------------
#define GSTRIDE 36
#define GTILEF (128 * GSTRIDE)
#define GSMEM_BYTES (3 * 2 * GTILEF * 4)   // 110592

template <bool IN_HEADS, bool OUT_HEADS, int YT_MODE>
__global__ void __launch_bounds__(128, 2) gemm_mma(
    const float* __restrict__ X, const float* __restrict__ W,
    const float* __restrict__ bias, float* __restrict__ Y,
    float* __restrict__ YT)
{
    extern __shared__ float sm[];
    const int tid = threadIdx.x;
    const int wid = tid >> 5, lane = tid & 31;
    const int g = lane >> 2, t = lane & 3;
    const int m0 = blockIdx.y * 128, n0 = blockIdx.x * 128;
    const int wm0 = (wid >> 1) * 64, wn0 = (wid & 1) * 64;

    float c[4][8][4];
    #pragma unroll
    for (int i = 0; i < 4; i++)
        #pragma unroll
        for (int j = 0; j < 8; j++)
            #pragma unroll
            for (int r = 0; r < 4; r++) c[i][j][r] = 0.f;

    auto issue_loads = [&](int k0, int s) {
        float* As = sm + s * 2 * GTILEF;
        float* Bs = As + GTILEF;
        #pragma unroll
        for (int it = 0; it < 8; it++) {
            const int idx = it * 128 + tid;
            const int row = idx >> 3;
            const int c4  = idx & 7;
            const int gk  = k0 + c4 * 4;
            const float* pa;
            if (IN_HEADS) {
                const int gm = m0 + row;
                const int bb_ = gm >> 11;
                const int ss_ = gm & (SS - 1);
                pa = X + ((((size_t)bb_ * HH + (gk >> 6)) * SS + ss_) << 6) + (gk & 63);
            } else {
                pa = X + (size_t)(m0 + row) * DD + gk;
            }
            const uint32_t da = smem_u32(As + row * GSTRIDE + c4 * 4);
            asm volatile("cp.async.cg.shared.global [%0], [%1], 16;"
                         :: "r"(da), "l"(pa));
            const float* pb = W + (size_t)(n0 + row) * DD + gk;
            const uint32_t db = smem_u32(Bs + row * GSTRIDE + c4 * 4);
            asm volatile("cp.async.cg.shared.global [%0], [%1], 16;"
                         :: "r"(db), "l"(pb));
        }
        asm volatile("cp.async.commit_group;" ::: "memory");
    };

    const int NK = DD / 32;   // 32 chunks
    issue_loads(0, 0);
    issue_loads(32, 1);
    int stage = 0;
    for (int ck = 0; ck < NK; ck++) {
        if (ck < NK - 1) {
            asm volatile("cp.async.wait_group 1;" ::: "memory");
        } else {
            asm volatile("cp.async.wait_group 0;" ::: "memory");
        }
        __syncthreads();
        if (ck + 2 < NK) {
            int ns = stage + 2; if (ns >= 3) ns -= 3;
            issue_loads((ck + 2) * 32, ns);
        }

        const float* As = sm + stage * 2 * GTILEF;
        const float* Bs = As + GTILEF;

        #pragma unroll
        for (int ks = 0; ks < 4; ks++) {
            const int k0 = ks * 8;
            uint32_t a[4][4], b[8][2];
            #pragma unroll
            for (int i = 0; i < 4; i++) {
                const int r = wm0 + 16 * i + g;
                a[i][0] = f2tf(As[r * GSTRIDE + k0 + t]);
                a[i][1] = f2tf(As[(r + 8) * GSTRIDE + k0 + t]);
                a[i][2] = f2tf(As[r * GSTRIDE + k0 + t + 4]);
                a[i][3] = f2tf(As[(r + 8) * GSTRIDE + k0 + t + 4]);
            }
            #pragma unroll
            for (int j = 0; j < 8; j++) {
                const int cn = wn0 + 8 * j + g;
                b[j][0] = f2tf(Bs[cn * GSTRIDE + k0 + t]);
                b[j][1] = f2tf(Bs[cn * GSTRIDE + k0 + t + 4]);
            }
            #pragma unroll
            for (int i = 0; i < 4; i++)
                #pragma unroll
                for (int j = 0; j < 8; j++)
                    mma8(c[i][j], a[i], b[j][0], b[j][1]);
        }
        __syncthreads();
        if (++stage == 3) stage = 0;
    }

    // per-thread permuted positions for YT writes
    const int px = kperm(2 * t);        // position of col offset 2t within 8-group
    const int py = kperm(2 * t + 1);
    const int pg = kperm(g);            // position of s offset g within 8-group

    #pragma unroll
    for (int i = 0; i < 4; i++) {
        const int r0 = m0 + wm0 + 16 * i + g;
        const int r1 = r0 + 8;
        #pragma unroll
        for (int j = 0; j < 8; j++) {
            const int gn = n0 + wn0 + 8 * j + 2 * t;
            const float bx = __ldg(bias + gn);
            const float by = __ldg(bias + gn + 1);
            float2 o0 = make_float2(c[i][j][0] + bx, c[i][j][1] + by);
            float2 o1 = make_float2(c[i][j][2] + bx, c[i][j][3] + by);
            if (OUT_HEADS) {
                const int hb = gn >> 6, hc = gn & 63;
                const int b0_ = r0 >> 11, s0_ = r0 & (SS - 1);
                const int b1_ = r1 >> 11, s1_ = r1 & (SS - 1);
                const size_t y0 = ((((size_t)b0_ * HH + hb) * SS + s0_) << 6) + hc;
                const size_t y1 = ((((size_t)b1_ * HH + hb) * SS + s1_) << 6) + hc;
                *reinterpret_cast<float2*>(Y + y0) = o0;
                *reinterpret_cast<float2*>(Y + y1) = o1;
                if (YT_MODE == 1) {
                    const int s0p = (s0_ & ~7) | pg;
                    const int s1p = (s1_ & ~7) | pg;
                    float* yt0 = YT + (((size_t)b0_ * HH + hb) * HDIM + hc) * SS + s0p;
                    float* yt1 = YT + (((size_t)b1_ * HH + hb) * HDIM + hc) * SS + s1p;
                    yt0[0] = rnd_tf(o0.x); yt0[SS] = rnd_tf(o0.y);
                    yt1[0] = rnd_tf(o1.x); yt1[SS] = rnd_tf(o1.y);
                } else if (YT_MODE == 2) {
                    const size_t base0 = y0 - (hc & 7);   // hc&7 == 2t
                    const size_t base1 = y1 - (hc & 7);
                    YT[base0 + px] = rnd_tf(o0.x);
                    YT[base0 + py] = rnd_tf(o0.y);
                    YT[base1 + px] = rnd_tf(o1.x);
                    YT[base1 + py] = rnd_tf(o1.y);
                }
            } else {
                *reinterpret_cast<float2*>(Y + (size_t)r0 * DD + gn) = o0;
                *reinterpret_cast<float2*>(Y + (size_t)r1 * DD + gn) = o1;
            }
        }
    }
}

// ---------------------------------------------------------------------------
// Tensor-core causal flash attention v3.
// Single RNA-tf32 Q (a-frags loaded straight from gmem); P exchanged via
// quad-lane shuffles (no P smem buffer); K/V double-buffered cp.async.
// smem 73728 B, 3 CTAs/SM target.
// ---------------------------------------------------------------------------
#define KVPAD 72
#define KVTILE (64 * KVPAD)
#define FSMEM_BYTES (4 * KVTILE * 4)   // 73728

__global__ void __launch_bounds__(128, 3) flash_tc(
    const float* __restrict__ qh, const float* __restrict__ kt,
    const float* __restrict__ vt, float* __restrict__ oh)
{
    extern __shared__ float fsm[];
    float* Kb = fsm;                    // [2][64][KVPAD] K[key][d_perm]
    float* Vb = fsm + 2 * KVTILE;       // [2][64][KVPAD] V^T[d][key_perm]

    const int tid = threadIdx.x;
    const int w = tid >> 5, lane = tid & 31;
    const int g = lane >> 2, t = lane & 3;
    const int qi = 31 - (int)blockIdx.x;      // biggest blocks first
    const int h = blockIdx.y, b = blockIdx.z;
    const size_t hoff = ((size_t)b * HH + h) * SS * HDIM;
    const float* vtb = vt + ((size_t)b * HH + h) * HDIM * SS;
    const int q0 = qi * 64;
    const float CLOG = 0.18033688011112042f;  // 0.125 * log2(e)

    const int sr = tid >> 4;            // staging base row (0..7), step 8
    const int sc = (tid & 15) * 4;      // 16B column group

    auto issue_tile = [&](int jt, int buf) {
        float* kd = Kb + buf * KVTILE;
        float* vd = Vb + buf * KVTILE;
        const int kb = jt * 64;
        #pragma unroll
        for (int i = 0; i < 8; i++) {
            const int r = sr + i * 8;
            const float* ks = kt + hoff + (size_t)(kb + r) * HDIM + sc;
            const float* vs = vtb + (size_t)r * SS + kb + sc;
            asm volatile("cp.async.cg.shared.global [%0], [%1], 16;"
                         :: "r"(smem_u32(kd + r * KVPAD + sc)), "l"(ks));
            asm volatile("cp.async.cg.shared.global [%0], [%1], 16;"
                         :: "r"(smem_u32(vd + r * KVPAD + sc)), "l"(vs));
        }
        asm volatile("cp.async.commit_group;" ::: "memory");
    };

    issue_tile(0, 0);   // prefetch tile 0 immediately

    const int rg0 = q0 + w * 16 + g;    // global q row for c0/c1
    const int rg1 = rg0 + 8;            // global q row for c2/c3

    // ---- Q a-frags straight from gmem (single RNA tf32) ----
    uint32_t qf[8][4];
    {
        const float* q0p = qh + hoff + (size_t)rg0 * HDIM;
        const float* q1p = qh + hoff + (size_t)rg1 * HDIM;
        #pragma unroll
        for (int ks = 0; ks < 8; ks++) {
            qf[ks][0] = f2tf(q0p[8 * ks + t]);
            qf[ks][1] = f2tf(q1p[8 * ks + t]);
            qf[ks][2] = f2tf(q0p[8 * ks + t + 4]);
            qf[ks][3] = f2tf(q1p[8 * ks + t + 4]);
        }
    }

    float o[8][4];
    #pragma unroll
    for (int nt = 0; nt < 8; nt++)
        #pragma unroll
        for (int r = 0; r < 4; r++) o[nt][r] = 0.f;
    float mx0 = -1e30f, mx1 = -1e30f, l0 = 0.f, l1 = 0.f;

    const int srcA = 4 * g + (t >> 1);  // P-exchange source lanes (quad)
    const int srcB = srcA + 2;
    const bool c1 = (t & 1);

    for (int jt = 0; jt <= qi; jt++) {
        const int kb = jt * 64;
        const int buf = jt & 1;

        if (jt < qi) {
            issue_tile(jt + 1, buf ^ 1);
            asm volatile("cp.async.wait_group 1;" ::: "memory");
        } else {
            asm volatile("cp.async.wait_group 0;" ::: "memory");
        }
        __syncthreads();

        const uint32_t* Kt = reinterpret_cast<const uint32_t*>(Kb + buf * KVTILE);
        const uint32_t* VT = reinterpret_cast<const uint32_t*>(Vb + buf * KVTILE);

        // ---- scores S = Q K^T (single tf32; b-frags LDS.64 pairs) ----
        float s[8][4];
        #pragma unroll
        for (int nt = 0; nt < 8; nt++) {
            s[nt][0] = s[nt][1] = s[nt][2] = s[nt][3] = 0.f;
            const uint32_t* kr = Kt + (8 * nt + g) * KVPAD;
            #pragma unroll
            for (int ks = 0; ks < 8; ks++) {
                const uint2 kb2 = *reinterpret_cast<const uint2*>(kr + 8 * ks + 2 * t);
                mma8(s[nt], qf[ks], kb2.x, kb2.y);
            }
        }

        // ---- causal mask (diagonal tile only) ----
        if (jt == qi) {
            #pragma unroll
            for (int nt = 0; nt < 8; nt++) {
                const int col = kb + 8 * nt + 2 * t;
                if (col > rg0)     s[nt][0] = -1e30f;
                if (col + 1 > rg0) s[nt][1] = -1e30f;
                if (col > rg1)     s[nt][2] = -1e30f;
                if (col + 1 > rg1) s[nt][3] = -1e30f;
            }
        }

        // ---- online softmax (in place: s -> p) ----
        float sm0 = -1e30f, sm1 = -1e30f;
        #pragma unroll
        for (int nt = 0; nt < 8; nt++) {
            sm0 = fmaxf(sm0, fmaxf(s[nt][0], s[nt][1]));
            sm1 = fmaxf(sm1, fmaxf(s[nt][2], s[nt][3]));
        }
        sm0 = fmaxf(sm0, __shfl_xor_sync(0xffffffffu, sm0, 1));
        sm0 = fmaxf(sm0, __shfl_xor_sync(0xffffffffu, sm0, 2));
        sm1 = fmaxf(sm1, __shfl_xor_sync(0xffffffffu, sm1, 1));
        sm1 = fmaxf(sm1, __shfl_xor_sync(0xffffffffu, sm1, 2));

        const float nm0 = fmaxf(mx0, sm0), nm1 = fmaxf(mx1, sm1);
        const float f0 = exp2p((mx0 - nm0) * CLOG);
        const float f1 = exp2p((mx1 - nm1) * CLOG);
        mx0 = nm0; mx1 = nm1;
        l0 *= f0; l1 *= f1;
        #pragma unroll
        for (int nt = 0; nt < 8; nt++) {
            o[nt][0] *= f0; o[nt][1] *= f0;
            o[nt][2] *= f1; o[nt][3] *= f1;
        }

        #pragma unroll
        for (int nt = 0; nt < 8; nt++) {
            s[nt][0] = exp2p((s[nt][0] - mx0) * CLOG);
            s[nt][1] = exp2p((s[nt][1] - mx0) * CLOG);
            s[nt][2] = exp2p((s[nt][2] - mx1) * CLOG);
            s[nt][3] = exp2p((s[nt][3] - mx1) * CLOG);
            l0 += s[nt][0] + s[nt][1];
            l1 += s[nt][2] + s[nt][3];
        }

        // ---- O += P V : a-frags via quad shuffles of register P ----
        #pragma unroll
        for (int kk = 0; kk < 8; kk++) {
            const float x0 = __shfl_sync(0xffffffffu, s[kk][0], srcA);
            const float x1 = __shfl_sync(0xffffffffu, s[kk][1], srcA);
            const float y0 = __shfl_sync(0xffffffffu, s[kk][2], srcA);
            const float y1 = __shfl_sync(0xffffffffu, s[kk][3], srcA);
            const float z0 = __shfl_sync(0xffffffffu, s[kk][0], srcB);
            const float z1 = __shfl_sync(0xffffffffu, s[kk][1], srcB);
            const float u0 = __shfl_sync(0xffffffffu, s[kk][2], srcB);
            const float u1 = __shfl_sync(0xffffffffu, s[kk][3], srcB);
            uint32_t ap[4];
            ap[0] = f2tf(c1 ? x1 : x0);
            ap[1] = f2tf(c1 ? y1 : y0);
            ap[2] = f2tf(c1 ? z1 : z0);
            ap[3] = f2tf(c1 ? u1 : u0);
            #pragma unroll
            for (int nt = 0; nt < 8; nt++) {
                const uint32_t* vr = VT + (8 * nt + g) * KVPAD;
                const uint2 vv = *reinterpret_cast<const uint2*>(vr + 8 * kk + 2 * t);
                mma8(o[nt], ap, vv.x, vv.y);
            }
        }
        __syncthreads();   // all warps done reading this buffer before reuse
    }

    // ---- finalize ----
    l0 += __shfl_xor_sync(0xffffffffu, l0, 1);
    l0 += __shfl_xor_sync(0xffffffffu, l0, 2);
    l1 += __shfl_xor_sync(0xffffffffu, l1, 1);
    l1 += __shfl_xor_sync(0xffffffffu, l1, 2);
    const float i0 = 1.f / l0, i1 = 1.f / l1;

    float* o0p = oh + hoff + (size_t)rg0 * HDIM;
    float* o1p = oh + hoff + (size_t)rg1 * HDIM;
    #pragma unroll
    for (int nt = 0; nt < 8; nt++) {
        const int d = 8 * nt + 2 * t;
        *reinterpret_cast<float2*>(o0p + d) = make_float2(o[nt][0] * i0, o[nt][1] * i0);
        *reinterpret_cast<float2*>(o1p + d) = make_float2(o[nt][2] * i1, o[nt][3] * i1);
    }
}

// ---------------------------------------------------------------------------
// kernel_launch
// Inputs: 0=q 1=k 2=v 3=mask 4=Wq 5=bq 6=Wk 7=bk 8=Wv 9=bv 10=Wo 11=bo
// Output: [out (B,S,D)] [kh (B,H,S,HD)] [vh (B,H,S,HD)]
// ---------------------------------------------------------------------------
extern "C" void kernel_launch(void* const* d_in, const int* in_sizes, int n_in,
                              void* d_out, int out_size)
{
    const float* q  = (const float*)d_in[0];
    const float* k  = (const float*)d_in[1];
    const float* v  = (const float*)d_in[2];
    const float* Wq = (const float*)d_in[4];
    const float* bq = (const float*)d_in[5];
    const float* Wk = (const float*)d_in[6];
    const float* bk = (const float*)d_in[7];
    const float* Wv = (const float*)d_in[8];
    const float* bv = (const float*)d_in[9];
    const float* Wo = (const float*)d_in[10];
    const float* bo = (const float*)d_in[11];

    float* out = (float*)d_out;
    float* khp = out + HEADTOT;
    float* vhp = khp + HEADTOT;

    float *qh_p = nullptr, *att_p = nullptr, *kt_p = nullptr, *vt_p = nullptr;
    cudaGetSymbolAddress((void**)&qh_p, g_qh);
    cudaGetSymbolAddress((void**)&att_p, g_att);
    cudaGetSymbolAddress((void**)&kt_p, g_kt);
    cudaGetSymbolAddress((void**)&vt_p, g_vt);

    cudaFuncSetAttribute(gemm_mma<false, true, 0>,
                         cudaFuncAttributeMaxDynamicSharedMemorySize, GSMEM_BYTES);
    cudaFuncSetAttribute(gemm_mma<false, true, 1>,
                         cudaFuncAttributeMaxDynamicSharedMemorySize, GSMEM_BYTES);
    cudaFuncSetAttribute(gemm_mma<false, true, 2>,
                         cudaFuncAttributeMaxDynamicSharedMemorySize, GSMEM_BYTES);
    cudaFuncSetAttribute(gemm_mma<true, false, 0>,
                         cudaFuncAttributeMaxDynamicSharedMemorySize, GSMEM_BYTES);
    cudaFuncSetAttribute(flash_tc,
                         cudaFuncAttributeMaxDynamicSharedMemorySize, FSMEM_BYTES);

    dim3 grd(DD / 128, MTOT / 128);   // (8, 64)

    gemm_mma<false, true, 0><<<grd, 128, GSMEM_BYTES>>>(q, Wq, bq, qh_p, nullptr);
    gemm_mma<false, true, 2><<<grd, 128, GSMEM_BYTES>>>(k, Wk, bk, khp, kt_p);
    gemm_mma<false, true, 1><<<grd, 128, GSMEM_BYTES>>>(v, Wv, bv, vhp, vt_p);

    flash_tc<<<dim3(32, HH, BB), 128, FSMEM_BYTES>>>(qh_p, kt_p, vt_p, att_p);

    gemm_mma<true, false, 0><<<grd, 128, GSMEM_BYTES>>>(att_p, Wo, bo, out, nullptr);
}

// round 10
// speedup vs baseline: 5.3353x; 1.0750x over previous
#include <cuda_runtime.h>
#include <math.h>
#include <stdint.h>

// Problem constants
#define BB 4
#define SS 2048
#define DD 1024
#define HH 16
#define HDIM 64
#define MTOT (BB * SS)                          // 8192
#define HEADTOT ((size_t)BB * HH * SS * HDIM)   // 8,388,608

// Scratch
__device__ float g_qh[BB * HH * SS * HDIM];
__device__ float g_att[BB * HH * SS * HDIM];
__device__ float g_kt[BB * HH * SS * HDIM];     // K head-layout, RNA-rounded, d-permuted
__device__ float g_vt[BB * HH * HDIM * SS];     // V^T [b][h][d][s], RNA-rounded, s-permuted

__device__ __forceinline__ uint32_t smem_u32(const void* p) {
    uint32_t a;
    asm("{ .reg .u64 t; cvta.to.shared.u64 t, %1; cvt.u32.u64 %0, t; }"
        : "=r"(a) : "l"(p));
    return a;
}

__device__ __forceinline__ uint32_t f2tf(float f) {
    uint32_t u;
    asm("cvt.rna.tf32.f32 %0, %1;" : "=r"(u) : "f"(f));
    return u;
}

__device__ __forceinline__ float rnd_tf(float f) {
    return __uint_as_float(f2tf(f));
}

// k-slot pairing permutation within 8-groups: p(j) = (j&3)*2 + (j>>2).
__device__ __forceinline__ int kperm(int j) { return ((j & 3) << 1) | (j >> 2); }

__device__ __forceinline__ void mma8(float* c, const uint32_t* a,
                                     uint32_t b0, uint32_t b1) {
    asm volatile(
        "mma.sync.aligned.m16n8k8.row.col.f32.tf32.tf32.f32 "
        "{%0,%1,%2,%3}, {%4,%5,%6,%7}, {%8,%9}, {%0,%1,%2,%3};"
        : "+f"(c[0]), "+f"(c[1]), "+f"(c[2]), "+f"(c[3])
        : "r"(a[0]), "r"(a[1]), "r"(a[2]), "r"(a[3]), "r"(b0), "r"(b1));
}

// ldmatrix x4: raw 32-bit moves; for tf32 data lane l of matrix m receives
// element (row l>>2, col l&3) of the 8x4-tf32 block == the mma tf32 frag layout.
__device__ __forceinline__ void ldsm4(uint32_t& d0, uint32_t& d1,
                                      uint32_t& d2, uint32_t& d3, uint32_t addr) {
    asm volatile(
        "ldmatrix.sync.aligned.m8n8.x4.shared.b16 {%0,%1,%2,%3}, [%4];"
        : "=r"(d0), "=r"(d1), "=r"(d2), "=r"(d3) : "r"(addr));
}

// exp2(z) for z <= 0, FMA-pipe only (no MUFU). ~5e-5 rel err.
__device__ __forceinline__ float exp2p(float z) {
    z = fmaxf(z, -100.f);
    float k = z + 12582912.f;            // 1.5*2^23: round-to-nearest-int
    int nb = __float_as_int(k);
    float f = z - (k - 12582912.f);      // f in [-0.5, 0.5]
    float p = 0.00961813f;
    p = fmaf(p, f, 0.05550410f);
    p = fmaf(p, f, 0.24022651f);
    p = fmaf(p, f, 0.69314718f);
    p = fmaf(p, f, 1.0f);
    return p * __int_as_float((nb << 23) + 0x3F800000);
}

// ---------------------------------------------------------------------------
// Tensor-core GEMM (mma.sync tf32): Y = X @ W^T + bias.
// 128x128 CTA tile, 4 warps of 64x64; 2-stage cp.async pipeline;
// fragment gather via ldmatrix.x4 (4 frags per instruction).
// YT_MODE: 0 none; 1 = V: transposed RNA copy [b][h][d][s], s-permuted;
//          2 = K: head-layout RNA copy, d-permuted.
// ---------------------------------------------------------------------------
#define GSTRIDE 36
#define GTILEF (128 * GSTRIDE)
#define GSMEM_BYTES (2 * 2 * GTILEF * 4)   // 73728

template <bool IN_HEADS, bool OUT_HEADS, int YT_MODE>
__global__ void __launch_bounds__(128) gemm_mma(
    const float* __restrict__ X, const float* __restrict__ W,
    const float* __restrict__ bias, float* __restrict__ Y,
    float* __restrict__ YT)
{
    extern __shared__ float sm[];
    const int tid = threadIdx.x;
    const int wid = tid >> 5, lane = tid & 31;
    const int g = lane >> 2, t = lane & 3;
    const int m0 = blockIdx.y * 128, n0 = blockIdx.x * 128;
    const int wm0 = (wid >> 1) * 64, wn0 = (wid & 1) * 64;

    float c[4][8][4];
    #pragma unroll
    for (int i = 0; i < 4; i++)
        #pragma unroll
        for (int j = 0; j < 8; j++)
            #pragma unroll
            for (int r = 0; r < 4; r++) c[i][j][r] = 0.f;

    auto issue_loads = [&](int k0, int s) {
        float* As = sm + s * 2 * GTILEF;
        float* Bs = As + GTILEF;
        #pragma unroll
        for (int it = 0; it < 8; it++) {
            const int idx = it * 128 + tid;
            const int row = idx >> 3;
            const int c4  = idx & 7;
            const int gk  = k0 + c4 * 4;
            const float* pa;
            if (IN_HEADS) {
                const int gm = m0 + row;
                const int bb_ = gm >> 11;
                const int ss_ = gm & (SS - 1);
                pa = X + ((((size_t)bb_ * HH + (gk >> 6)) * SS + ss_) << 6) + (gk & 63);
            } else {
                pa = X + (size_t)(m0 + row) * DD + gk;
            }
            const uint32_t da = smem_u32(As + row * GSTRIDE + c4 * 4);
            asm volatile("cp.async.cg.shared.global [%0], [%1], 16;"
                         :: "r"(da), "l"(pa));
            const float* pb = W + (size_t)(n0 + row) * DD + gk;
            const uint32_t db = smem_u32(Bs + row * GSTRIDE + c4 * 4);
            asm volatile("cp.async.cg.shared.global [%0], [%1], 16;"
                         :: "r"(db), "l"(pb));
        }
        asm volatile("cp.async.commit_group;" ::: "memory");
    };

    // per-lane ldmatrix row addresses: lane supplies row (lane&7) of matrix (lane>>3)
    const uint32_t smbase = smem_u32(sm);
    const int mx = lane >> 3, r8 = lane & 7;
    // A matrices per x4: (rowblk = mx&1, colblk = mx>>1)
    const uint32_t aoff = ((wm0 + (mx & 1) * 8 + r8) * GSTRIDE + (mx >> 1) * 4) * 4;
    // B matrices per x4: (jblk = mx>>1, colblk = mx&1)
    const uint32_t boff = ((wn0 + (mx >> 1) * 8 + r8) * GSTRIDE + (mx & 1) * 4) * 4;

    issue_loads(0, 0);
    const int NK = DD / 32;
    for (int ck = 0; ck < NK; ck++) {
        asm volatile("cp.async.wait_group 0;" ::: "memory");
        __syncthreads();
        if (ck + 1 < NK) issue_loads((ck + 1) * 32, (ck + 1) & 1);

        const uint32_t As = smbase + (uint32_t)((ck & 1) * 2 * GTILEF * 4);
        const uint32_t Bs = As + GTILEF * 4;

        #pragma unroll
        for (int ks = 0; ks < 4; ks++) {
            uint32_t a[4][4], b[8][2];
            #pragma unroll
            for (int i = 0; i < 4; i++) {
                ldsm4(a[i][0], a[i][1], a[i][2], a[i][3],
                      As + aoff + (uint32_t)((i * 16 * GSTRIDE + ks * 8) * 4));
                a[i][0] = f2tf(__uint_as_float(a[i][0]));
                a[i][1] = f2tf(__uint_as_float(a[i][1]));
                a[i][2] = f2tf(__uint_as_float(a[i][2]));
                a[i][3] = f2tf(__uint_as_float(a[i][3]));
            }
            #pragma unroll
            for (int jp = 0; jp < 4; jp++) {
                ldsm4(b[2 * jp][0], b[2 * jp][1], b[2 * jp + 1][0], b[2 * jp + 1][1],
                      Bs + boff + (uint32_t)((jp * 16 * GSTRIDE + ks * 8) * 4));
                b[2 * jp][0]     = f2tf(__uint_as_float(b[2 * jp][0]));
                b[2 * jp][1]     = f2tf(__uint_as_float(b[2 * jp][1]));
                b[2 * jp + 1][0] = f2tf(__uint_as_float(b[2 * jp + 1][0]));
                b[2 * jp + 1][1] = f2tf(__uint_as_float(b[2 * jp + 1][1]));
            }
            #pragma unroll
            for (int i = 0; i < 4; i++)
                #pragma unroll
                for (int j = 0; j < 8; j++)
                    mma8(c[i][j], a[i], b[j][0], b[j][1]);
        }
        __syncthreads();
    }

    // per-thread permuted positions for YT writes
    const int px = kperm(2 * t);
    const int py = kperm(2 * t + 1);
    const int pg = kperm(g);

    #pragma unroll
    for (int i = 0; i < 4; i++) {
        const int r0 = m0 + wm0 + 16 * i + g;
        const int r1 = r0 + 8;
        #pragma unroll
        for (int j = 0; j < 8; j++) {
            const int gn = n0 + wn0 + 8 * j + 2 * t;
            const float bx = __ldg(bias + gn);
            const float by = __ldg(bias + gn + 1);
            float2 o0 = make_float2(c[i][j][0] + bx, c[i][j][1] + by);
            float2 o1 = make_float2(c[i][j][2] + bx, c[i][j][3] + by);
            if (OUT_HEADS) {
                const int hb = gn >> 6, hc = gn & 63;
                const int b0_ = r0 >> 11, s0_ = r0 & (SS - 1);
                const int b1_ = r1 >> 11, s1_ = r1 & (SS - 1);
                const size_t y0 = ((((size_t)b0_ * HH + hb) * SS + s0_) << 6) + hc;
                const size_t y1 = ((((size_t)b1_ * HH + hb) * SS + s1_) << 6) + hc;
                *reinterpret_cast<float2*>(Y + y0) = o0;
                *reinterpret_cast<float2*>(Y + y1) = o1;
                if (YT_MODE == 1) {
                    const int s0p = (s0_ & ~7) | pg;
                    const int s1p = (s1_ & ~7) | pg;
                    float* yt0 = YT + (((size_t)b0_ * HH + hb) * HDIM + hc) * SS + s0p;
                    float* yt1 = YT + (((size_t)b1_ * HH + hb) * HDIM + hc) * SS + s1p;
                    yt0[0] = rnd_tf(o0.x); yt0[SS] = rnd_tf(o0.y);
                    yt1[0] = rnd_tf(o1.x); yt1[SS] = rnd_tf(o1.y);
                } else if (YT_MODE == 2) {
                    const size_t base0 = y0 - (hc & 7);   // hc&7 == 2t
                    const size_t base1 = y1 - (hc & 7);
                    YT[base0 + px] = rnd_tf(o0.x);
                    YT[base0 + py] = rnd_tf(o0.y);
                    YT[base1 + px] = rnd_tf(o1.x);
                    YT[base1 + py] = rnd_tf(o1.y);
                }
            } else {
                *reinterpret_cast<float2*>(Y + (size_t)r0 * DD + gn) = o0;
                *reinterpret_cast<float2*>(Y + (size_t)r1 * DD + gn) = o1;
            }
        }
    }
}

// ---------------------------------------------------------------------------
// Tensor-core causal flash attention v3 (unchanged from R9).
// Single RNA-tf32 Q (a-frags from gmem); P exchanged via quad shuffles;
// K/V double-buffered cp.async; 3 CTAs/SM.
// ---------------------------------------------------------------------------
#define KVPAD 72
#define KVTILE (64 * KVPAD)
#define FSMEM_BYTES (4 * KVTILE * 4)   // 73728

__global__ void __launch_bounds__(128, 3) flash_tc(
    const float* __restrict__ qh, const float* __restrict__ kt,
    const float* __restrict__ vt, float* __restrict__ oh)
{
    extern __shared__ float fsm[];
    float* Kb = fsm;                    // [2][64][KVPAD] K[key][d_perm]
    float* Vb = fsm + 2 * KVTILE;       // [2][64][KVPAD] V^T[d][key_perm]

    const int tid = threadIdx.x;
    const int w = tid >> 5, lane = tid & 31;
    const int g = lane >> 2, t = lane & 3;
    const int qi = 31 - (int)blockIdx.x;      // biggest blocks first
    const int h = blockIdx.y, b = blockIdx.z;
    const size_t hoff = ((size_t)b * HH + h) * SS * HDIM;
    const float* vtb = vt + ((size_t)b * HH + h) * HDIM * SS;
    const int q0 = qi * 64;
    const float CLOG = 0.18033688011112042f;  // 0.125 * log2(e)

    const int sr = tid >> 4;            // staging base row (0..7), step 8
    const int sc = (tid & 15) * 4;      // 16B column group

    auto issue_tile = [&](int jt, int buf) {
        float* kd = Kb + buf * KVTILE;
        float* vd = Vb + buf * KVTILE;
        const int kb = jt * 64;
        #pragma unroll
        for (int i = 0; i < 8; i++) {
            const int r = sr + i * 8;
            const float* ks = kt + hoff + (size_t)(kb + r) * HDIM + sc;
            const float* vs = vtb + (size_t)r * SS + kb + sc;
            asm volatile("cp.async.cg.shared.global [%0], [%1], 16;"
                         :: "r"(smem_u32(kd + r * KVPAD + sc)), "l"(ks));
            asm volatile("cp.async.cg.shared.global [%0], [%1], 16;"
                         :: "r"(smem_u32(vd + r * KVPAD + sc)), "l"(vs));
        }
        asm volatile("cp.async.commit_group;" ::: "memory");
    };

    issue_tile(0, 0);   // prefetch tile 0 immediately

    const int rg0 = q0 + w * 16 + g;    // global q row for c0/c1
    const int rg1 = rg0 + 8;            // global q row for c2/c3

    // ---- Q a-frags straight from gmem (single RNA tf32) ----
    uint32_t qf[8][4];
    {
        const float* q0p = qh + hoff + (size_t)rg0 * HDIM;
        const float* q1p = qh + hoff + (size_t)rg1 * HDIM;
        #pragma unroll
        for (int ks = 0; ks < 8; ks++) {
            qf[ks][0] = f2tf(q0p[8 * ks + t]);
            qf[ks][1] = f2tf(q1p[8 * ks + t]);
            qf[ks][2] = f2tf(q0p[8 * ks + t + 4]);
            qf[ks][3] = f2tf(q1p[8 * ks + t + 4]);
        }
    }

    float o[8][4];
    #pragma unroll
    for (int nt = 0; nt < 8; nt++)
        #pragma unroll
        for (int r = 0; r < 4; r++) o[nt][r] = 0.f;
    float mx0 = -1e30f, mx1 = -1e30f, l0 = 0.f, l1 = 0.f;

    const int srcA = 4 * g + (t >> 1);  // P-exchange source lanes (quad)
    const int srcB = srcA + 2;
    const bool c1 = (t & 1);

    for (int jt = 0; jt <= qi; jt++) {
        const int kb = jt * 64;
        const int buf = jt & 1;

        if (jt < qi) {
            issue_tile(jt + 1, buf ^ 1);
            asm volatile("cp.async.wait_group 1;" ::: "memory");
        } else {
            asm volatile("cp.async.wait_group 0;" ::: "memory");
        }
        __syncthreads();

        const uint32_t* Kt = reinterpret_cast<const uint32_t*>(Kb + buf * KVTILE);
        const uint32_t* VT = reinterpret_cast<const uint32_t*>(Vb + buf * KVTILE);

        // ---- scores S = Q K^T (single tf32; b-frags LDS.64 pairs) ----
        float s[8][4];
        #pragma unroll
        for (int nt = 0; nt < 8; nt++) {
            s[nt][0] = s[nt][1] = s[nt][2] = s[nt][3] = 0.f;
            const uint32_t* kr = Kt + (8 * nt + g) * KVPAD;
            #pragma unroll
            for (int ks = 0; ks < 8; ks++) {
                const uint2 kb2 = *reinterpret_cast<const uint2*>(kr + 8 * ks + 2 * t);
                mma8(s[nt], qf[ks], kb2.x, kb2.y);
            }
        }

        // ---- causal mask (diagonal tile only) ----
        if (jt == qi) {
            #pragma unroll
            for (int nt = 0; nt < 8; nt++) {
                const int col = kb + 8 * nt + 2 * t;
                if (col > rg0)     s[nt][0] = -1e30f;
                if (col + 1 > rg0) s[nt][1] = -1e30f;
                if (col > rg1)     s[nt][2] = -1e30f;
                if (col + 1 > rg1) s[nt][3] = -1e30f;
            }
        }

        // ---- online softmax (in place: s -> p) ----
        float sm0 = -1e30f, sm1 = -1e30f;
        #pragma unroll
        for (int nt = 0; nt < 8; nt++) {
            sm0 = fmaxf(sm0, fmaxf(s[nt][0], s[nt][1]));
            sm1 = fmaxf(sm1, fmaxf(s[nt][2], s[nt][3]));
        }
        sm0 = fmaxf(sm0, __shfl_xor_sync(0xffffffffu, sm0, 1));
        sm0 = fmaxf(sm0, __shfl_xor_sync(0xffffffffu, sm0, 2));
        sm1 = fmaxf(sm1, __shfl_xor_sync(0xffffffffu, sm1, 1));
        sm1 = fmaxf(sm1, __shfl_xor_sync(0xffffffffu, sm1, 2));

        const float nm0 = fmaxf(mx0, sm0), nm1 = fmaxf(mx1, sm1);
        const float f0 = exp2p((mx0 - nm0) * CLOG);
        const float f1 = exp2p((mx1 - nm1) * CLOG);
        mx0 = nm0; mx1 = nm1;
        l0 *= f0; l1 *= f1;
        #pragma unroll
        for (int nt = 0; nt < 8; nt++) {
            o[nt][0] *= f0; o[nt][1] *= f0;
            o[nt][2] *= f1; o[nt][3] *= f1;
        }

        #pragma unroll
        for (int nt = 0; nt < 8; nt++) {
            s[nt][0] = exp2p((s[nt][0] - mx0) * CLOG);
            s[nt][1] = exp2p((s[nt][1] - mx0) * CLOG);
            s[nt][2] = exp2p((s[nt][2] - mx1) * CLOG);
            s[nt][3] = exp2p((s[nt][3] - mx1) * CLOG);
            l0 += s[nt][0] + s[nt][1];
            l1 += s[nt][2] + s[nt][3];
        }

        // ---- O += P V : a-frags via quad shuffles of register P ----
        #pragma unroll
        for (int kk = 0; kk < 8; kk++) {
            const float x0 = __shfl_sync(0xffffffffu, s[kk][0], srcA);
            const float x1 = __shfl_sync(0xffffffffu, s[kk][1], srcA);
            const float y0 = __shfl_sync(0xffffffffu, s[kk][2], srcA);
            const float y1 = __shfl_sync(0xffffffffu, s[kk][3], srcA);
            const float z0 = __shfl_sync(0xffffffffu, s[kk][0], srcB);
            const float z1 = __shfl_sync(0xffffffffu, s[kk][1], srcB);
            const float u0 = __shfl_sync(0xffffffffu, s[kk][2], srcB);
            const float u1 = __shfl_sync(0xffffffffu, s[kk][3], srcB);
            uint32_t ap[4];
            ap[0] = f2tf(c1 ? x1 : x0);
            ap[1] = f2tf(c1 ? y1 : y0);
            ap[2] = f2tf(c1 ? z1 : z0);
            ap[3] = f2tf(c1 ? u1 : u0);
            #pragma unroll
            for (int nt = 0; nt < 8; nt++) {
                const uint32_t* vr = VT + (8 * nt + g) * KVPAD;
                const uint2 vv = *reinterpret_cast<const uint2*>(vr + 8 * kk + 2 * t);
                mma8(o[nt], ap, vv.x, vv.y);
            }
        }
        __syncthreads();   // all warps done reading this buffer before reuse
    }

    // ---- finalize ----
    l0 += __shfl_xor_sync(0xffffffffu, l0, 1);
    l0 += __shfl_xor_sync(0xffffffffu, l0, 2);
    l1 += __shfl_xor_sync(0xffffffffu, l1, 1);
    l1 += __shfl_xor_sync(0xffffffffu, l1, 2);
    const float i0 = 1.f / l0, i1 = 1.f / l1;

    float* o0p = oh + hoff + (size_t)rg0 * HDIM;
    float* o1p = oh + hoff + (size_t)rg1 * HDIM;
    #pragma unroll
    for (int nt = 0; nt < 8; nt++) {
        const int d = 8 * nt + 2 * t;
        *reinterpret_cast<float2*>(o0p + d) = make_float2(o[nt][0] * i0, o[nt][1] * i0);
        *reinterpret_cast<float2*>(o1p + d) = make_float2(o[nt][2] * i1, o[nt][3] * i1);
    }
}

// ---------------------------------------------------------------------------
// kernel_launch
// Inputs: 0=q 1=k 2=v 3=mask 4=Wq 5=bq 6=Wk 7=bk 8=Wv 9=bv 10=Wo 11=bo
// Output: [out (B,S,D)] [kh (B,H,S,HD)] [vh (B,H,S,HD)]
// ---------------------------------------------------------------------------
extern "C" void kernel_launch(void* const* d_in, const int* in_sizes, int n_in,
                              void* d_out, int out_size)
{
    const float* q  = (const float*)d_in[0];
    const float* k  = (const float*)d_in[1];
    const float* v  = (const float*)d_in[2];
    const float* Wq = (const float*)d_in[4];
    const float* bq = (const float*)d_in[5];
    const float* Wk = (const float*)d_in[6];
    const float* bk = (const float*)d_in[7];
    const float* Wv = (const float*)d_in[8];
    const float* bv = (const float*)d_in[9];
    const float* Wo = (const float*)d_in[10];
    const float* bo = (const float*)d_in[11];

    float* out = (float*)d_out;
    float* khp = out + HEADTOT;
    float* vhp = khp + HEADTOT;

    float *qh_p = nullptr, *att_p = nullptr, *kt_p = nullptr, *vt_p = nullptr;
    cudaGetSymbolAddress((void**)&qh_p, g_qh);
    cudaGetSymbolAddress((void**)&att_p, g_att);
    cudaGetSymbolAddress((void**)&kt_p, g_kt);
    cudaGetSymbolAddress((void**)&vt_p, g_vt);

    cudaFuncSetAttribute(gemm_mma<false, true, 0>,
                         cudaFuncAttributeMaxDynamicSharedMemorySize, GSMEM_BYTES);
    cudaFuncSetAttribute(gemm_mma<false, true, 1>,
                         cudaFuncAttributeMaxDynamicSharedMemorySize, GSMEM_BYTES);
    cudaFuncSetAttribute(gemm_mma<false, true, 2>,
                         cudaFuncAttributeMaxDynamicSharedMemorySize, GSMEM_BYTES);
    cudaFuncSetAttribute(gemm_mma<true, false, 0>,
                         cudaFuncAttributeMaxDynamicSharedMemorySize, GSMEM_BYTES);
    cudaFuncSetAttribute(flash_tc,
                         cudaFuncAttributeMaxDynamicSharedMemorySize, FSMEM_BYTES);

    dim3 grd(DD / 128, MTOT / 128);   // (8, 64)

    gemm_mma<false, true, 0><<<grd, 128, GSMEM_BYTES>>>(q, Wq, bq, qh_p, nullptr);
    gemm_mma<false, true, 2><<<grd, 128, GSMEM_BYTES>>>(k, Wk, bk, khp, kt_p);
    gemm_mma<false, true, 1><<<grd, 128, GSMEM_BYTES>>>(v, Wv, bv, vhp, vt_p);

    flash_tc<<<dim3(32, HH, BB), 128, FSMEM_BYTES>>>(qh_p, kt_p, vt_p, att_p);

    gemm_mma<true, false, 0><<<grd, 128, GSMEM_BYTES>>>(att_p, Wo, bo, out, nullptr);
}

// round 11
// speedup vs baseline: 5.3523x; 1.0032x over previous
#include <cuda_runtime.h>
#include <math.h>
#include <stdint.h>

// Problem constants
#define BB 4
#define SS 2048
#define DD 1024
#define HH 16
#define HDIM 64
#define MTOT (BB * SS)                          // 8192
#define HEADTOT ((size_t)BB * HH * SS * HDIM)   // 8,388,608

// Scratch
__device__ float g_qh[BB * HH * SS * HDIM];
__device__ float g_att[BB * HH * SS * HDIM];    // RNA-pre-rounded by flash epilogue
__device__ float g_kt[BB * HH * SS * HDIM];     // K head-layout, RNA-rounded, d-permuted
__device__ float g_vt[BB * HH * HDIM * SS];     // V^T [b][h][d][s], RNA-rounded, s-permuted
__device__ float g_wr[4 * DD * DD];             // Wq,Wk,Wv,Wo RNA-pre-rounded

__device__ __forceinline__ uint32_t smem_u32(const void* p) {
    uint32_t a;
    asm("{ .reg .u64 t; cvta.to.shared.u64 t, %1; cvt.u32.u64 %0, t; }"
        : "=r"(a) : "l"(p));
    return a;
}

__device__ __forceinline__ uint32_t f2tf(float f) {
    uint32_t u;
    asm("cvt.rna.tf32.f32 %0, %1;" : "=r"(u) : "f"(f));
    return u;
}

__device__ __forceinline__ float rnd_tf(float f) {
    return __uint_as_float(f2tf(f));
}

// k-slot pairing permutation within 8-groups: p(j) = (j&3)*2 + (j>>2).
__device__ __forceinline__ int kperm(int j) { return ((j & 3) << 1) | (j >> 2); }

__device__ __forceinline__ void mma8(float* c, const uint32_t* a,
                                     uint32_t b0, uint32_t b1) {
    asm volatile(
        "mma.sync.aligned.m16n8k8.row.col.f32.tf32.tf32.f32 "
        "{%0,%1,%2,%3}, {%4,%5,%6,%7}, {%8,%9}, {%0,%1,%2,%3};"
        : "+f"(c[0]), "+f"(c[1]), "+f"(c[2]), "+f"(c[3])
        : "r"(a[0]), "r"(a[1]), "r"(a[2]), "r"(a[3]), "r"(b0), "r"(b1));
}

__device__ __forceinline__ void ldsm4(uint32_t& d0, uint32_t& d1,
                                      uint32_t& d2, uint32_t& d3, uint32_t addr) {
    asm volatile(
        "ldmatrix.sync.aligned.m8n8.x4.shared.b16 {%0,%1,%2,%3}, [%4];"
        : "=r"(d0), "=r"(d1), "=r"(d2), "=r"(d3) : "r"(addr));
}

// exp2(z) for z <= 0, FMA-pipe only (no MUFU). ~5e-5 rel err.
__device__ __forceinline__ float exp2p(float z) {
    z = fmaxf(z, -100.f);
    float k = z + 12582912.f;            // 1.5*2^23: round-to-nearest-int
    int nb = __float_as_int(k);
    float f = z - (k - 12582912.f);      // f in [-0.5, 0.5]
    float p = 0.00961813f;
    p = fmaf(p, f, 0.05550410f);
    p = fmaf(p, f, 0.24022651f);
    p = fmaf(p, f, 0.69314718f);
    p = fmaf(p, f, 1.0f);
    return p * __int_as_float((nb << 23) + 0x3F800000);
}

// ---------------------------------------------------------------------------
// Pre-round the 4 weight matrices (RNA tf32) into g_wr.
// ---------------------------------------------------------------------------
__global__ void __launch_bounds__(256) round_weights(
    const float* __restrict__ w0, const float* __restrict__ w1,
    const float* __restrict__ w2, const float* __restrict__ w3,
    float* __restrict__ dst)
{
    const int idx = blockIdx.x * 256 + threadIdx.x;   // one float4 each
    const int per = DD * DD / 4;                      // 262144
    const int m = idx / per, off = (idx - m * per) * 4;
    const float* src = (m == 0) ? w0 : (m == 1) ? w1 : (m == 2) ? w2 : w3;
    float4 v = *reinterpret_cast<const float4*>(src + off);
    v.x = rnd_tf(v.x); v.y = rnd_tf(v.y); v.z = rnd_tf(v.z); v.w = rnd_tf(v.w);
    *reinterpret_cast<float4*>(dst + (size_t)m * DD * DD + off) = v;
}

// ---------------------------------------------------------------------------
// Tensor-core GEMM (mma.sync tf32): Y = X @ W^T + bias.
// 128x128 CTA tile, 4 warps of 64x64; 2-stage cp.async; ldmatrix.x4 frags.
// W must be RNA-pre-rounded (b-frags used raw). A_CVT: RNA-cvt a-frags
// (false when X is already pre-rounded, e.g. g_att).
// YT_MODE: 0 none; 1 = V: transposed RNA copy, s-permuted; 2 = K: RNA copy, d-permuted.
// ---------------------------------------------------------------------------
#define GSTRIDE 36
#define GTILEF (128 * GSTRIDE)
#define GSMEM_BYTES (2 * 2 * GTILEF * 4)   // 73728

template <bool IN_HEADS, bool OUT_HEADS, int YT_MODE, bool A_CVT>
__global__ void __launch_bounds__(128, 3) gemm_mma(
    const float* __restrict__ X, const float* __restrict__ W,
    const float* __restrict__ bias, float* __restrict__ Y,
    float* __restrict__ YT)
{
    extern __shared__ float sm[];
    const int tid = threadIdx.x;
    const int wid = tid >> 5, lane = tid & 31;
    const int g = lane >> 2, t = lane & 3;
    const int m0 = blockIdx.y * 128, n0 = blockIdx.x * 128;
    const int wm0 = (wid >> 1) * 64, wn0 = (wid & 1) * 64;

    float c[4][8][4];
    #pragma unroll
    for (int i = 0; i < 4; i++)
        #pragma unroll
        for (int j = 0; j < 8; j++)
            #pragma unroll
            for (int r = 0; r < 4; r++) c[i][j][r] = 0.f;

    auto issue_loads = [&](int k0, int s) {
        float* As = sm + s * 2 * GTILEF;
        float* Bs = As + GTILEF;
        #pragma unroll
        for (int it = 0; it < 8; it++) {
            const int idx = it * 128 + tid;
            const int row = idx >> 3;
            const int c4  = idx & 7;
            const int gk  = k0 + c4 * 4;
            const float* pa;
            if (IN_HEADS) {
                const int gm = m0 + row;
                const int bb_ = gm >> 11;
                const int ss_ = gm & (SS - 1);
                pa = X + ((((size_t)bb_ * HH + (gk >> 6)) * SS + ss_) << 6) + (gk & 63);
            } else {
                pa = X + (size_t)(m0 + row) * DD + gk;
            }
            const uint32_t da = smem_u32(As + row * GSTRIDE + c4 * 4);
            asm volatile("cp.async.cg.shared.global [%0], [%1], 16;"
                         :: "r"(da), "l"(pa));
            const float* pb = W + (size_t)(n0 + row) * DD + gk;
            const uint32_t db = smem_u32(Bs + row * GSTRIDE + c4 * 4);
            asm volatile("cp.async.cg.shared.global [%0], [%1], 16;"
                         :: "r"(db), "l"(pb));
        }
        asm volatile("cp.async.commit_group;" ::: "memory");
    };

    // per-lane ldmatrix row addresses: lane supplies row (lane&7) of matrix (lane>>3)
    const uint32_t smbase = smem_u32(sm);
    const int mx = lane >> 3, r8 = lane & 7;
    const uint32_t aoff = ((wm0 + (mx & 1) * 8 + r8) * GSTRIDE + (mx >> 1) * 4) * 4;
    const uint32_t boff = ((wn0 + (mx >> 1) * 8 + r8) * GSTRIDE + (mx & 1) * 4) * 4;

    issue_loads(0, 0);
    const int NK = DD / 32;
    for (int ck = 0; ck < NK; ck++) {
        asm volatile("cp.async.wait_group 0;" ::: "memory");
        __syncthreads();
        if (ck + 1 < NK) issue_loads((ck + 1) * 32, (ck + 1) & 1);

        const uint32_t As = smbase + (uint32_t)((ck & 1) * 2 * GTILEF * 4);
        const uint32_t Bs = As + GTILEF * 4;

        #pragma unroll
        for (int ks = 0; ks < 4; ks++) {
            uint32_t a[4][4], b[8][2];
            #pragma unroll
            for (int i = 0; i < 4; i++) {
                ldsm4(a[i][0], a[i][1], a[i][2], a[i][3],
                      As + aoff + (uint32_t)((i * 16 * GSTRIDE + ks * 8) * 4));
                if (A_CVT) {
                    a[i][0] = f2tf(__uint_as_float(a[i][0]));
                    a[i][1] = f2tf(__uint_as_float(a[i][1]));
                    a[i][2] = f2tf(__uint_as_float(a[i][2]));
                    a[i][3] = f2tf(__uint_as_float(a[i][3]));
                }
            }
            #pragma unroll
            for (int jp = 0; jp < 4; jp++) {
                ldsm4(b[2 * jp][0], b[2 * jp][1], b[2 * jp + 1][0], b[2 * jp + 1][1],
                      Bs + boff + (uint32_t)((jp * 16 * GSTRIDE + ks * 8) * 4));
                // W pre-rounded: raw bits are tf32-exact
            }
            #pragma unroll
            for (int i = 0; i < 4; i++)
                #pragma unroll
                for (int j = 0; j < 8; j++)
                    mma8(c[i][j], a[i], b[j][0], b[j][1]);
        }
        __syncthreads();
    }

    // per-thread permuted positions for YT writes
    const int px = kperm(2 * t);
    const int py = kperm(2 * t + 1);
    const int pg = kperm(g);

    #pragma unroll
    for (int i = 0; i < 4; i++) {
        const int r0 = m0 + wm0 + 16 * i + g;
        const int r1 = r0 + 8;
        #pragma unroll
        for (int j = 0; j < 8; j++) {
            const int gn = n0 + wn0 + 8 * j + 2 * t;
            const float bx = __ldg(bias + gn);
            const float by = __ldg(bias + gn + 1);
            float2 o0 = make_float2(c[i][j][0] + bx, c[i][j][1] + by);
            float2 o1 = make_float2(c[i][j][2] + bx, c[i][j][3] + by);
            if (OUT_HEADS) {
                const int hb = gn >> 6, hc = gn & 63;
                const int b0_ = r0 >> 11, s0_ = r0 & (SS - 1);
                const int b1_ = r1 >> 11, s1_ = r1 & (SS - 1);
                const size_t y0 = ((((size_t)b0_ * HH + hb) * SS + s0_) << 6) + hc;
                const size_t y1 = ((((size_t)b1_ * HH + hb) * SS + s1_) << 6) + hc;
                *reinterpret_cast<float2*>(Y + y0) = o0;
                *reinterpret_cast<float2*>(Y + y1) = o1;
                if (YT_MODE == 1) {
                    const int s0p = (s0_ & ~7) | pg;
                    const int s1p = (s1_ & ~7) | pg;
                    float* yt0 = YT + (((size_t)b0_ * HH + hb) * HDIM + hc) * SS + s0p;
                    float* yt1 = YT + (((size_t)b1_ * HH + hb) * HDIM + hc) * SS + s1p;
                    yt0[0] = rnd_tf(o0.x); yt0[SS] = rnd_tf(o0.y);
                    yt1[0] = rnd_tf(o1.x); yt1[SS] = rnd_tf(o1.y);
                } else if (YT_MODE == 2) {
                    const size_t base0 = y0 - (hc & 7);   // hc&7 == 2t
                    const size_t base1 = y1 - (hc & 7);
                    YT[base0 + px] = rnd_tf(o0.x);
                    YT[base0 + py] = rnd_tf(o0.y);
                    YT[base1 + px] = rnd_tf(o1.x);
                    YT[base1 + py] = rnd_tf(o1.y);
                }
            } else {
                *reinterpret_cast<float2*>(Y + (size_t)r0 * DD + gn) = o0;
                *reinterpret_cast<float2*>(Y + (size_t)r1 * DD + gn) = o1;
            }
        }
    }
}

// ---------------------------------------------------------------------------
// Tensor-core causal flash attention v3 (R9 structure; epilogue now writes
// RNA-pre-rounded output so the output-proj GEMM can skip a-frag CVTs).
// ---------------------------------------------------------------------------
#define KVPAD 72
#define KVTILE (64 * KVPAD)
#define FSMEM_BYTES (4 * KVTILE * 4)   // 73728

__global__ void __launch_bounds__(128, 3) flash_tc(
    const float* __restrict__ qh, const float* __restrict__ kt,
    const float* __restrict__ vt, float* __restrict__ oh)
{
    extern __shared__ float fsm[];
    float* Kb = fsm;                    // [2][64][KVPAD] K[key][d_perm]
    float* Vb = fsm + 2 * KVTILE;       // [2][64][KVPAD] V^T[d][key_perm]

    const int tid = threadIdx.x;
    const int w = tid >> 5, lane = tid & 31;
    const int g = lane >> 2, t = lane & 3;
    const int qi = 31 - (int)blockIdx.x;      // biggest blocks first
    const int h = blockIdx.y, b = blockIdx.z;
    const size_t hoff = ((size_t)b * HH + h) * SS * HDIM;
    const float* vtb = vt + ((size_t)b * HH + h) * HDIM * SS;
    const int q0 = qi * 64;
    const float CLOG = 0.18033688011112042f;  // 0.125 * log2(e)

    const int sr = tid >> 4;            // staging base row (0..7), step 8
    const int sc = (tid & 15) * 4;      // 16B column group

    auto issue_tile = [&](int jt, int buf) {
        float* kd = Kb + buf * KVTILE;
        float* vd = Vb + buf * KVTILE;
        const int kb = jt * 64;
        #pragma unroll
        for (int i = 0; i < 8; i++) {
            const int r = sr + i * 8;
            const float* ks = kt + hoff + (size_t)(kb + r) * HDIM + sc;
            const float* vs = vtb + (size_t)r * SS + kb + sc;
            asm volatile("cp.async.cg.shared.global [%0], [%1], 16;"
                         :: "r"(smem_u32(kd + r * KVPAD + sc)), "l"(ks));
            asm volatile("cp.async.cg.shared.global [%0], [%1], 16;"
                         :: "r"(smem_u32(vd + r * KVPAD + sc)), "l"(vs));
        }
        asm volatile("cp.async.commit_group;" ::: "memory");
    };

    issue_tile(0, 0);   // prefetch tile 0 immediately

    const int rg0 = q0 + w * 16 + g;    // global q row for c0/c1
    const int rg1 = rg0 + 8;            // global q row for c2/c3

    // ---- Q a-frags straight from gmem (single RNA tf32) ----
    uint32_t qf[8][4];
    {
        const float* q0p = qh + hoff + (size_t)rg0 * HDIM;
        const float* q1p = qh + hoff + (size_t)rg1 * HDIM;
        #pragma unroll
        for (int ks = 0; ks < 8; ks++) {
            qf[ks][0] = f2tf(q0p[8 * ks + t]);
            qf[ks][1] = f2tf(q1p[8 * ks + t]);
            qf[ks][2] = f2tf(q0p[8 * ks + t + 4]);
            qf[ks][3] = f2tf(q1p[8 * ks + t + 4]);
        }
    }

    float o[8][4];
    #pragma unroll
    for (int nt = 0; nt < 8; nt++)
        #pragma unroll
        for (int r = 0; r < 4; r++) o[nt][r] = 0.f;
    float mx0 = -1e30f, mx1 = -1e30f, l0 = 0.f, l1 = 0.f;

    const int srcA = 4 * g + (t >> 1);  // P-exchange source lanes (quad)
    const int srcB = srcA + 2;
    const bool c1 = (t & 1);

    for (int jt = 0; jt <= qi; jt++) {
        const int kb = jt * 64;
        const int buf = jt & 1;

        if (jt < qi) {
            issue_tile(jt + 1, buf ^ 1);
            asm volatile("cp.async.wait_group 1;" ::: "memory");
        } else {
            asm volatile("cp.async.wait_group 0;" ::: "memory");
        }
        __syncthreads();

        const uint32_t* Kt = reinterpret_cast<const uint32_t*>(Kb + buf * KVTILE);
        const uint32_t* VT = reinterpret_cast<const uint32_t*>(Vb + buf * KVTILE);

        // ---- scores S = Q K^T (single tf32; b-frags LDS.64 pairs) ----
        float s[8][4];
        #pragma unroll
        for (int nt = 0; nt < 8; nt++) {
            s[nt][0] = s[nt][1] = s[nt][2] = s[nt][3] = 0.f;
            const uint32_t* kr = Kt + (8 * nt + g) * KVPAD;
            #pragma unroll
            for (int ks = 0; ks < 8; ks++) {
                const uint2 kb2 = *reinterpret_cast<const uint2*>(kr + 8 * ks + 2 * t);
                mma8(s[nt], qf[ks], kb2.x, kb2.y);
            }
        }

        // ---- causal mask (diagonal tile only) ----
        if (jt == qi) {
            #pragma unroll
            for (int nt = 0; nt < 8; nt++) {
                const int col = kb + 8 * nt + 2 * t;
                if (col > rg0)     s[nt][0] = -1e30f;
                if (col + 1 > rg0) s[nt][1] = -1e30f;
                if (col > rg1)     s[nt][2] = -1e30f;
                if (col + 1 > rg1) s[nt][3] = -1e30f;
            }
        }

        // ---- online softmax (in place: s -> p) ----
        float sm0 = -1e30f, sm1 = -1e30f;
        #pragma unroll
        for (int nt = 0; nt < 8; nt++) {
            sm0 = fmaxf(sm0, fmaxf(s[nt][0], s[nt][1]));
            sm1 = fmaxf(sm1, fmaxf(s[nt][2], s[nt][3]));
        }
        sm0 = fmaxf(sm0, __shfl_xor_sync(0xffffffffu, sm0, 1));
        sm0 = fmaxf(sm0, __shfl_xor_sync(0xffffffffu, sm0, 2));
        sm1 = fmaxf(sm1, __shfl_xor_sync(0xffffffffu, sm1, 1));
        sm1 = fmaxf(sm1, __shfl_xor_sync(0xffffffffu, sm1, 2));

        const float nm0 = fmaxf(mx0, sm0), nm1 = fmaxf(mx1, sm1);
        const float f0 = exp2p((mx0 - nm0) * CLOG);
        const float f1 = exp2p((mx1 - nm1) * CLOG);
        mx0 = nm0; mx1 = nm1;
        l0 *= f0; l1 *= f1;
        #pragma unroll
        for (int nt = 0; nt < 8; nt++) {
            o[nt][0] *= f0; o[nt][1] *= f0;
            o[nt][2] *= f1; o[nt][3] *= f1;
        }

        #pragma unroll
        for (int nt = 0; nt < 8; nt++) {
            s[nt][0] = exp2p((s[nt][0] - mx0) * CLOG);
            s[nt][1] = exp2p((s[nt][1] - mx0) * CLOG);
            s[nt][2] = exp2p((s[nt][2] - mx1) * CLOG);
            s[nt][3] = exp2p((s[nt][3] - mx1) * CLOG);
            l0 += s[nt][0] + s[nt][1];
            l1 += s[nt][2] + s[nt][3];
        }

        // ---- O += P V : a-frags via quad shuffles of register P ----
        #pragma unroll
        for (int kk = 0; kk < 8; kk++) {
            const float x0 = __shfl_sync(0xffffffffu, s[kk][0], srcA);
            const float x1 = __shfl_sync(0xffffffffu, s[kk][1], srcA);
            const float y0 = __shfl_sync(0xffffffffu, s[kk][2], srcA);
            const float y1 = __shfl_sync(0xffffffffu, s[kk][3], srcA);
            const float z0 = __shfl_sync(0xffffffffu, s[kk][0], srcB);
            const float z1 = __shfl_sync(0xffffffffu, s[kk][1], srcB);
            const float u0 = __shfl_sync(0xffffffffu, s[kk][2], srcB);
            const float u1 = __shfl_sync(0xffffffffu, s[kk][3], srcB);
            uint32_t ap[4];
            ap[0] = f2tf(c1 ? x1 : x0);
            ap[1] = f2tf(c1 ? y1 : y0);
            ap[2] = f2tf(c1 ? z1 : z0);
            ap[3] = f2tf(c1 ? u1 : u0);
            #pragma unroll
            for (int nt = 0; nt < 8; nt++) {
                const uint32_t* vr = VT + (8 * nt + g) * KVPAD;
                const uint2 vv = *reinterpret_cast<const uint2*>(vr + 8 * kk + 2 * t);
                mma8(o[nt], ap, vv.x, vv.y);
            }
        }
        __syncthreads();   // all warps done reading this buffer before reuse
    }

    // ---- finalize (write RNA-pre-rounded for the output-proj GEMM) ----
    l0 += __shfl_xor_sync(0xffffffffu, l0, 1);
    l0 += __shfl_xor_sync(0xffffffffu, l0, 2);
    l1 += __shfl_xor_sync(0xffffffffu, l1, 1);
    l1 += __shfl_xor_sync(0xffffffffu, l1, 2);
    const float i0 = 1.f / l0, i1 = 1.f / l1;

    float* o0p = oh + hoff + (size_t)rg0 * HDIM;
    float* o1p = oh + hoff + (size_t)rg1 * HDIM;
    #pragma unroll
    for (int nt = 0; nt < 8; nt++) {
        const int d = 8 * nt + 2 * t;
        *reinterpret_cast<float2*>(o0p + d) =
            make_float2(rnd_tf(o[nt][0] * i0), rnd_tf(o[nt][1] * i0));
        *reinterpret_cast<float2*>(o1p + d) =
            make_float2(rnd_tf(o[nt][2] * i1), rnd_tf(o[nt][3] * i1));
    }
}

// ---------------------------------------------------------------------------
// kernel_launch
// Inputs: 0=q 1=k 2=v 3=mask 4=Wq 5=bq 6=Wk 7=bk 8=Wv 9=bv 10=Wo 11=bo
// Output: [out (B,S,D)] [kh (B,H,S,HD)] [vh (B,H,S,HD)]
// ---------------------------------------------------------------------------
extern "C" void kernel_launch(void* const* d_in, const int* in_sizes, int n_in,
                              void* d_out, int out_size)
{
    const float* q  = (const float*)d_in[0];
    const float* k  = (const float*)d_in[1];
    const float* v  = (const float*)d_in[2];
    const float* Wq = (const float*)d_in[4];
    const float* bq = (const float*)d_in[5];
    const float* Wk = (const float*)d_in[6];
    const float* bk = (const float*)d_in[7];
    const float* Wv = (const float*)d_in[8];
    const float* bv = (const float*)d_in[9];
    const float* Wo = (const float*)d_in[10];
    const float* bo = (const float*)d_in[11];

    float* out = (float*)d_out;
    float* khp = out + HEADTOT;
    float* vhp = khp + HEADTOT;

    float *qh_p = nullptr, *att_p = nullptr, *kt_p = nullptr, *vt_p = nullptr, *wr_p = nullptr;
    cudaGetSymbolAddress((void**)&qh_p, g_qh);
    cudaGetSymbolAddress((void**)&att_p, g_att);
    cudaGetSymbolAddress((void**)&kt_p, g_kt);
    cudaGetSymbolAddress((void**)&vt_p, g_vt);
    cudaGetSymbolAddress((void**)&wr_p, g_wr);

    cudaFuncSetAttribute(gemm_mma<false, true, 0, true>,
                         cudaFuncAttributeMaxDynamicSharedMemorySize, GSMEM_BYTES);
    cudaFuncSetAttribute(gemm_mma<false, true, 1, true>,
                         cudaFuncAttributeMaxDynamicSharedMemorySize, GSMEM_BYTES);
    cudaFuncSetAttribute(gemm_mma<false, true, 2, true>,
                         cudaFuncAttributeMaxDynamicSharedMemorySize, GSMEM_BYTES);
    cudaFuncSetAttribute(gemm_mma<true, false, 0, false>,
                         cudaFuncAttributeMaxDynamicSharedMemorySize, GSMEM_BYTES);
    cudaFuncSetAttribute(flash_tc,
                         cudaFuncAttributeMaxDynamicSharedMemorySize, FSMEM_BYTES);

    // Pre-round all 4 weight matrices (RNA tf32) -> g_wr
    round_weights<<<4096, 256>>>(Wq, Wk, Wv, Wo, wr_p);

    dim3 grd(DD / 128, MTOT / 128);   // (8, 64)

    gemm_mma<false, true, 0, true><<<grd, 128, GSMEM_BYTES>>>(
        q, wr_p + 0 * DD * DD, bq, qh_p, nullptr);
    gemm_mma<false, true, 2, true><<<grd, 128, GSMEM_BYTES>>>(
        k, wr_p + 1 * DD * DD, bk, khp, kt_p);
    gemm_mma<false, true, 1, true><<<grd, 128, GSMEM_BYTES>>>(
        v, wr_p + 2 * DD * DD, bv, vhp, vt_p);

    flash_tc<<<dim3(32, HH, BB), 128, FSMEM_BYTES>>>(qh_p, kt_p, vt_p, att_p);

    gemm_mma<true, false, 0, false><<<grd, 128, GSMEM_BYTES>>>(
        att_p, wr_p + 3 * DD * DD, bo, out, nullptr);
}

// round 13
// speedup vs baseline: 5.7607x; 1.0763x over previous
#include <cuda_runtime.h>
#include <math.h>
#include <stdint.h>

// Problem constants
#define BB 4
#define SS 2048
#define DD 1024
#define HH 16
#define HDIM 64
#define MTOT (BB * SS)                          // 8192
#define HEADTOT ((size_t)BB * HH * SS * HDIM)   // 8,388,608

// Scratch
__device__ float g_qh[BB * HH * SS * HDIM];
__device__ float g_att[BB * HH * SS * HDIM];    // RNA-pre-rounded by flash epilogue
__device__ float g_kt[BB * HH * SS * HDIM];     // K head-layout, RNA-rounded, d-permuted
__device__ float g_vt[BB * HH * HDIM * SS];     // V^T [b][h][d][s], RNA-rounded, s-permuted
__device__ float g_wr[4 * DD * DD];             // Wq,Wk,Wv,Wo RNA-pre-rounded

__device__ __forceinline__ uint32_t smem_u32(const void* p) {
    uint32_t a;
    asm("{ .reg .u64 t; cvta.to.shared.u64 t, %1; cvt.u32.u64 %0, t; }"
        : "=r"(a) : "l"(p));
    return a;
}

__device__ __forceinline__ uint32_t f2tf(float f) {
    uint32_t u;
    asm("cvt.rna.tf32.f32 %0, %1;" : "=r"(u) : "f"(f));
    return u;
}

__device__ __forceinline__ float rnd_tf(float f) {
    return __uint_as_float(f2tf(f));
}

// k-slot pairing permutation within 8-groups: p(j) = (j&3)*2 + (j>>2).
__device__ __forceinline__ int kperm(int j) { return ((j & 3) << 1) | (j >> 2); }

__device__ __forceinline__ void mma8(float* c, const uint32_t* a,
                                     uint32_t b0, uint32_t b1) {
    asm volatile(
        "mma.sync.aligned.m16n8k8.row.col.f32.tf32.tf32.f32 "
        "{%0,%1,%2,%3}, {%4,%5,%6,%7}, {%8,%9}, {%0,%1,%2,%3};"
        : "+f"(c[0]), "+f"(c[1]), "+f"(c[2]), "+f"(c[3])
        : "r"(a[0]), "r"(a[1]), "r"(a[2]), "r"(a[3]), "r"(b0), "r"(b1));
}

__device__ __forceinline__ void ldsm4(uint32_t& d0, uint32_t& d1,
                                      uint32_t& d2, uint32_t& d3, uint32_t addr) {
    asm volatile(
        "ldmatrix.sync.aligned.m8n8.x4.shared.b16 {%0,%1,%2,%3}, [%4];"
        : "=r"(d0), "=r"(d1), "=r"(d2), "=r"(d3) : "r"(addr));
}

// exp2(z) for z <= 0, FMA-pipe only (no MUFU). ~5e-5 rel err.
__device__ __forceinline__ float exp2p(float z) {
    z = fmaxf(z, -100.f);
    float k = z + 12582912.f;            // 1.5*2^23: round-to-nearest-int
    int nb = __float_as_int(k);
    float f = z - (k - 12582912.f);      // f in [-0.5, 0.5]
    float p = 0.00961813f;
    p = fmaf(p, f, 0.05550410f);
    p = fmaf(p, f, 0.24022651f);
    p = fmaf(p, f, 0.69314718f);
    p = fmaf(p, f, 1.0f);
    return p * __int_as_float((nb << 23) + 0x3F800000);
}

// ---------------------------------------------------------------------------
// Pre-round the 4 weight matrices (RNA tf32) into g_wr.
// ---------------------------------------------------------------------------
__global__ void __launch_bounds__(256) round_weights(
    const float* __restrict__ w0, const float* __restrict__ w1,
    const float* __restrict__ w2, const float* __restrict__ w3,
    float* __restrict__ dst)
{
    const int idx = blockIdx.x * 256 + threadIdx.x;   // one float4 each
    const int per = DD * DD / 4;                      // 262144
    const int m = idx / per, off = (idx - m * per) * 4;
    const float* src = (m == 0) ? w0 : (m == 1) ? w1 : (m == 2) ? w2 : w3;
    float4 v = *reinterpret_cast<const float4*>(src + off);
    v.x = rnd_tf(v.x); v.y = rnd_tf(v.y); v.z = rnd_tf(v.z); v.w = rnd_tf(v.w);
    *reinterpret_cast<float4*>(dst + (size_t)m * DD * DD + off) = v;
}

// ---------------------------------------------------------------------------
// GEMM core: 128x128 CTA tile, 256 threads = 8 warps of 32x64.
// 2-stage cp.async pipeline; ldmatrix.x4 fragment gather.
// W must be RNA-pre-rounded (b-frags raw). A_CVT: RNA-cvt a-frags.
// ---------------------------------------------------------------------------
#define GSTRIDE 36
#define GTILEF (128 * GSTRIDE)
#define GSMEM_BYTES (2 * 2 * GTILEF * 4)   // 73728

template <bool IN_HEADS, bool A_CVT>
__device__ __forceinline__ void gemm_core(
    const float* __restrict__ X, const float* __restrict__ W,
    float* sm, int m0, int n0, float c[2][8][4])
{
    const int tid = threadIdx.x;
    const int wid = tid >> 5, lane = tid & 31;
    const int wm0 = (wid >> 1) * 32, wn0 = (wid & 1) * 64;

    auto issue_loads = [&](int k0, int s) {
        float* As = sm + s * 2 * GTILEF;
        float* Bs = As + GTILEF;
        #pragma unroll
        for (int it = 0; it < 4; it++) {
            const int idx = it * 256 + tid;
            const int row = idx >> 3;
            const int c4  = idx & 7;
            const int gk  = k0 + c4 * 4;
            const float* pa;
            if (IN_HEADS) {
                const int gm = m0 + row;
                const int bb_ = gm >> 11;
                const int ss_ = gm & (SS - 1);
                pa = X + ((((size_t)bb_ * HH + (gk >> 6)) * SS + ss_) << 6) + (gk & 63);
            } else {
                pa = X + (size_t)(m0 + row) * DD + gk;
            }
            const uint32_t da = smem_u32(As + row * GSTRIDE + c4 * 4);
            asm volatile("cp.async.cg.shared.global [%0], [%1], 16;"
                         :: "r"(da), "l"(pa));
            const float* pb = W + (size_t)(n0 + row) * DD + gk;
            const uint32_t db = smem_u32(Bs + row * GSTRIDE + c4 * 4);
            asm volatile("cp.async.cg.shared.global [%0], [%1], 16;"
                         :: "r"(db), "l"(pb));
        }
        asm volatile("cp.async.commit_group;" ::: "memory");
    };

    // per-lane ldmatrix row addresses: lane supplies row (lane&7) of matrix (lane>>3)
    const uint32_t smbase = smem_u32(sm);
    const int mx = lane >> 3, r8 = lane & 7;
    const uint32_t aoff = ((wm0 + (mx & 1) * 8 + r8) * GSTRIDE + (mx >> 1) * 4) * 4;
    const uint32_t boff = ((wn0 + (mx >> 1) * 8 + r8) * GSTRIDE + (mx & 1) * 4) * 4;

    issue_loads(0, 0);
    const int NK = DD / 32;
    for (int ck = 0; ck < NK; ck++) {
        asm volatile("cp.async.wait_group 0;" ::: "memory");
        __syncthreads();
        if (ck + 1 < NK) issue_loads((ck + 1) * 32, (ck + 1) & 1);

        const uint32_t As = smbase + (uint32_t)((ck & 1) * 2 * GTILEF * 4);
        const uint32_t Bs = As + GTILEF * 4;

        #pragma unroll
        for (int ks = 0; ks < 4; ks++) {
            uint32_t a[2][4], b[8][2];
            #pragma unroll
            for (int i = 0; i < 2; i++) {
                ldsm4(a[i][0], a[i][1], a[i][2], a[i][3],
                      As + aoff + (uint32_t)((i * 16 * GSTRIDE + ks * 8) * 4));
                if (A_CVT) {
                    a[i][0] = f2tf(__uint_as_float(a[i][0]));
                    a[i][1] = f2tf(__uint_as_float(a[i][1]));
                    a[i][2] = f2tf(__uint_as_float(a[i][2]));
                    a[i][3] = f2tf(__uint_as_float(a[i][3]));
                }
            }
            #pragma unroll
            for (int jp = 0; jp < 4; jp++) {
                ldsm4(b[2 * jp][0], b[2 * jp][1], b[2 * jp + 1][0], b[2 * jp + 1][1],
                      Bs + boff + (uint32_t)((jp * 16 * GSTRIDE + ks * 8) * 4));
            }
            #pragma unroll
            for (int i = 0; i < 2; i++)
                #pragma unroll
                for (int j = 0; j < 8; j++)
                    mma8(c[i][j], a[i], b[j][0], b[j][1]);
        }
        __syncthreads();
    }
}

// ---------------------------------------------------------------------------
// Fused Q/K/V projection GEMM: grid.z selects {0:Q, 1:K, 2:V}.
// Head-layout output; K also writes d-permuted RNA copy, V writes transposed
// s-permuted RNA copy.
// ---------------------------------------------------------------------------
__global__ void __launch_bounds__(256, 2) gemm_qkv(
    const float* __restrict__ xq, const float* __restrict__ xk,
    const float* __restrict__ xv, const float* __restrict__ wr,
    const float* __restrict__ bq, const float* __restrict__ bk,
    const float* __restrict__ bv,
    float* __restrict__ yq, float* __restrict__ yk, float* __restrict__ yv,
    float* __restrict__ ktp, float* __restrict__ vtp)
{
    extern __shared__ float sm[];
    const int z = blockIdx.z;
    const int m0 = blockIdx.y * 128, n0 = blockIdx.x * 128;
    const float* X = (z == 0) ? xq : (z == 1) ? xk : xv;
    const float* W = wr + (size_t)z * DD * DD;
    const float* bias = (z == 0) ? bq : (z == 1) ? bk : bv;
    float* Y = (z == 0) ? yq : (z == 1) ? yk : yv;

    float c[2][8][4];
    #pragma unroll
    for (int i = 0; i < 2; i++)
        #pragma unroll
        for (int j = 0; j < 8; j++)
            #pragma unroll
            for (int r = 0; r < 4; r++) c[i][j][r] = 0.f;

    gemm_core<false, true>(X, W, sm, m0, n0, c);

    const int tid = threadIdx.x;
    const int wid = tid >> 5, lane = tid & 31;
    const int g = lane >> 2, t = lane & 3;
    const int wm0 = (wid >> 1) * 32, wn0 = (wid & 1) * 64;

    const int px = kperm(2 * t);
    const int py = kperm(2 * t + 1);
    const int pg = kperm(g);

    #pragma unroll
    for (int i = 0; i < 2; i++) {
        const int r0 = m0 + wm0 + 16 * i + g;
        const int r1 = r0 + 8;
        #pragma unroll
        for (int j = 0; j < 8; j++) {
            const int gn = n0 + wn0 + 8 * j + 2 * t;
            const float bx = __ldg(bias + gn);
            const float by = __ldg(bias + gn + 1);
            float2 o0 = make_float2(c[i][j][0] + bx, c[i][j][1] + by);
            float2 o1 = make_float2(c[i][j][2] + bx, c[i][j][3] + by);
            const int hb = gn >> 6, hc = gn & 63;
            const int b0_ = r0 >> 11, s0_ = r0 & (SS - 1);
            const int b1_ = r1 >> 11, s1_ = r1 & (SS - 1);
            const size_t y0 = ((((size_t)b0_ * HH + hb) * SS + s0_) << 6) + hc;
            const size_t y1 = ((((size_t)b1_ * HH + hb) * SS + s1_) << 6) + hc;
            *reinterpret_cast<float2*>(Y + y0) = o0;
            *reinterpret_cast<float2*>(Y + y1) = o1;
            if (z == 1) {
                // K copy, pre-rounded, d permuted within 8-groups
                const size_t base0 = y0 - (hc & 7);   // hc&7 == 2t
                const size_t base1 = y1 - (hc & 7);
                ktp[base0 + px] = rnd_tf(o0.x);
                ktp[base0 + py] = rnd_tf(o0.y);
                ktp[base1 + px] = rnd_tf(o1.x);
                ktp[base1 + py] = rnd_tf(o1.y);
            } else if (z == 2) {
                // V^T copy, pre-rounded, s permuted within 8-groups
                const int s0p = (s0_ & ~7) | pg;
                const int s1p = (s1_ & ~7) | pg;
                float* yt0 = vtp + (((size_t)b0_ * HH + hb) * HDIM + hc) * SS + s0p;
                float* yt1 = vtp + (((size_t)b1_ * HH + hb) * HDIM + hc) * SS + s1p;
                yt0[0] = rnd_tf(o0.x); yt0[SS] = rnd_tf(o0.y);
                yt1[0] = rnd_tf(o1.x); yt1[SS] = rnd_tf(o1.y);
            }
        }
    }
}

// ---------------------------------------------------------------------------
// Output-projection GEMM: head-layout in (pre-rounded), flat out.
// ---------------------------------------------------------------------------
__global__ void __launch_bounds__(256, 2) gemm_out(
    const float* __restrict__ X, const float* __restrict__ W,
    const float* __restrict__ bias, float* __restrict__ Y)
{
    extern __shared__ float sm[];
    const int m0 = blockIdx.y * 128, n0 = blockIdx.x * 128;

    float c[2][8][4];
    #pragma unroll
    for (int i = 0; i < 2; i++)
        #pragma unroll
        for (int j = 0; j < 8; j++)
            #pragma unroll
            for (int r = 0; r < 4; r++) c[i][j][r] = 0.f;

    gemm_core<true, false>(X, W, sm, m0, n0, c);

    const int tid = threadIdx.x;
    const int wid = tid >> 5, lane = tid & 31;
    const int g = lane >> 2, t = lane & 3;
    const int wm0 = (wid >> 1) * 32, wn0 = (wid & 1) * 64;

    #pragma unroll
    for (int i = 0; i < 2; i++) {
        const int r0 = m0 + wm0 + 16 * i + g;
        const int r1 = r0 + 8;
        #pragma unroll
        for (int j = 0; j < 8; j++) {
            const int gn = n0 + wn0 + 8 * j + 2 * t;
            const float bx = __ldg(bias + gn);
            const float by = __ldg(bias + gn + 1);
            *reinterpret_cast<float2*>(Y + (size_t)r0 * DD + gn) =
                make_float2(c[i][j][0] + bx, c[i][j][1] + by);
            *reinterpret_cast<float2*>(Y + (size_t)r1 * DD + gn) =
                make_float2(c[i][j][2] + bx, c[i][j][3] + by);
        }
    }
}

// ---------------------------------------------------------------------------
// Tensor-core causal flash attention v3 (unchanged from R11).
// ---------------------------------------------------------------------------
#define KVPAD 72
#define KVTILE (64 * KVPAD)
#define FSMEM_BYTES (4 * KVTILE * 4)   // 73728

__global__ void __launch_bounds__(128, 3) flash_tc(
    const float* __restrict__ qh, const float* __restrict__ kt,
    const float* __restrict__ vt, float* __restrict__ oh)
{
    extern __shared__ float fsm[];
    float* Kb = fsm;                    // [2][64][KVPAD] K[key][d_perm]
    float* Vb = fsm + 2 * KVTILE;       // [2][64][KVPAD] V^T[d][key_perm]

    const int tid = threadIdx.x;
    const int w = tid >> 5, lane = tid & 31;
    const int g = lane >> 2, t = lane & 3;
    const int qi = 31 - (int)blockIdx.x;      // biggest blocks first
    const int h = blockIdx.y, b = blockIdx.z;
    const size_t hoff = ((size_t)b * HH + h) * SS * HDIM;
    const float* vtb = vt + ((size_t)b * HH + h) * HDIM * SS;
    const int q0 = qi * 64;
    const float CLOG = 0.18033688011112042f;  // 0.125 * log2(e)

    const int sr = tid >> 4;            // staging base row (0..7), step 8
    const int sc = (tid & 15) * 4;      // 16B column group

    auto issue_tile = [&](int jt, int buf) {
        float* kd = Kb + buf * KVTILE;
        float* vd = Vb + buf * KVTILE;
        const int kb = jt * 64;
        #pragma unroll
        for (int i = 0; i < 8; i++) {
            const int r = sr + i * 8;
            const float* ks = kt + hoff + (size_t)(kb + r) * HDIM + sc;
            const float* vs = vtb + (size_t)r * SS + kb + sc;
            asm volatile("cp.async.cg.shared.global [%0], [%1], 16;"
                         :: "r"(smem_u32(kd + r * KVPAD + sc)), "l"(ks));
            asm volatile("cp.async.cg.shared.global [%0], [%1], 16;"
                         :: "r"(smem_u32(vd + r * KVPAD + sc)), "l"(vs));
        }
        asm volatile("cp.async.commit_group;" ::: "memory");
    };

    issue_tile(0, 0);   // prefetch tile 0 immediately

    const int rg0 = q0 + w * 16 + g;    // global q row for c0/c1
    const int rg1 = rg0 + 8;            // global q row for c2/c3

    // ---- Q a-frags straight from gmem (single RNA tf32) ----
    uint32_t qf[8][4];
    {
        const float* q0p = qh + hoff + (size_t)rg0 * HDIM;
        const float* q1p = qh + hoff + (size_t)rg1 * HDIM;
        #pragma unroll
        for (int ks = 0; ks < 8; ks++) {
            qf[ks][0] = f2tf(q0p[8 * ks + t]);
            qf[ks][1] = f2tf(q1p[8 * ks + t]);
            qf[ks][2] = f2tf(q0p[8 * ks + t + 4]);
            qf[ks][3] = f2tf(q1p[8 * ks + t + 4]);
        }
    }

    float o[8][4];
    #pragma unroll
    for (int nt = 0; nt < 8; nt++)
        #pragma unroll
        for (int r = 0; r < 4; r++) o[nt][r] = 0.f;
    float mx0 = -1e30f, mx1 = -1e30f, l0 = 0.f, l1 = 0.f;

    const int srcA = 4 * g + (t >> 1);  // P-exchange source lanes (quad)
    const int srcB = srcA + 2;
    const bool c1 = (t & 1);

    for (int jt = 0; jt <= qi; jt++) {
        const int kb = jt * 64;
        const int buf = jt & 1;

        if (jt < qi) {
            issue_tile(jt + 1, buf ^ 1);
            asm volatile("cp.async.wait_group 1;" ::: "memory");
        } else {
            asm volatile("cp.async.wait_group 0;" ::: "memory");
        }
        __syncthreads();

        const uint32_t* Kt = reinterpret_cast<const uint32_t*>(Kb + buf * KVTILE);
        const uint32_t* VT = reinterpret_cast<const uint32_t*>(Vb + buf * KVTILE);

        // ---- scores S = Q K^T (single tf32; b-frags LDS.64 pairs) ----
        float s[8][4];
        #pragma unroll
        for (int nt = 0; nt < 8; nt++) {
            s[nt][0] = s[nt][1] = s[nt][2] = s[nt][3] = 0.f;
            const uint32_t* kr = Kt + (8 * nt + g) * KVPAD;
            #pragma unroll
            for (int ks = 0; ks < 8; ks++) {
                const uint2 kb2 = *reinterpret_cast<const uint2*>(kr + 8 * ks + 2 * t);
                mma8(s[nt], qf[ks], kb2.x, kb2.y);
            }
        }

        // ---- causal mask (diagonal tile only) ----
        if (jt == qi) {
            #pragma unroll
            for (int nt = 0; nt < 8; nt++) {
                const int col = kb + 8 * nt + 2 * t;
                if (col > rg0)     s[nt][0] = -1e30f;
                if (col + 1 > rg0) s[nt][1] = -1e30f;
                if (col > rg1)     s[nt][2] = -1e30f;
                if (col + 1 > rg1) s[nt][3] = -1e30f;
            }
        }

        // ---- online softmax (in place: s -> p) ----
        float sm0 = -1e30f, sm1 = -1e30f;
        #pragma unroll
        for (int nt = 0; nt < 8; nt++) {
            sm0 = fmaxf(sm0, fmaxf(s[nt][0], s[nt][1]));
            sm1 = fmaxf(sm1, fmaxf(s[nt][2], s[nt][3]));
        }
        sm0 = fmaxf(sm0, __shfl_xor_sync(0xffffffffu, sm0, 1));
        sm0 = fmaxf(sm0, __shfl_xor_sync(0xffffffffu, sm0, 2));
        sm1 = fmaxf(sm1, __shfl_xor_sync(0xffffffffu, sm1, 1));
        sm1 = fmaxf(sm1, __shfl_xor_sync(0xffffffffu, sm1, 2));

        const float nm0 = fmaxf(mx0, sm0), nm1 = fmaxf(mx1, sm1);
        const float f0 = exp2p((mx0 - nm0) * CLOG);
        const float f1 = exp2p((mx1 - nm1) * CLOG);
        mx0 = nm0; mx1 = nm1;
        l0 *= f0; l1 *= f1;
        #pragma unroll
        for (int nt = 0; nt < 8; nt++) {
            o[nt][0] *= f0; o[nt][1] *= f0;
            o[nt][2] *= f1; o[nt][3] *= f1;
        }

        #pragma unroll
        for (int nt = 0; nt < 8; nt++) {
            s[nt][0] = exp2p((s[nt][0] - mx0) * CLOG);
            s[nt][1] = exp2p((s[nt][1] - mx0) * CLOG);
            s[nt][2] = exp2p((s[nt][2] - mx1) * CLOG);
            s[nt][3] = exp2p((s[nt][3] - mx1) * CLOG);
            l0 += s[nt][0] + s[nt][1];
            l1 += s[nt][2] + s[nt][3];
        }

        // ---- O += P V : a-frags via quad shuffles of register P ----
        #pragma unroll
        for (int kk = 0; kk < 8; kk++) {
            const float x0 = __shfl_sync(0xffffffffu, s[kk][0], srcA);
            const float x1 = __shfl_sync(0xffffffffu, s[kk][1], srcA);
            const float y0 = __shfl_sync(0xffffffffu, s[kk][2], srcA);
            const float y1 = __shfl_sync(0xffffffffu, s[kk][3], srcA);
            const float z0 = __shfl_sync(0xffffffffu, s[kk][0], srcB);
            const float z1 = __shfl_sync(0xffffffffu, s[kk][1], srcB);
            const float u0 = __shfl_sync(0xffffffffu, s[kk][2], srcB);
            const float u1 = __shfl_sync(0xffffffffu, s[kk][3], srcB);
            uint32_t ap[4];
            ap[0] = f2tf(c1 ? x1 : x0);
            ap[1] = f2tf(c1 ? y1 : y0);
            ap[2] = f2tf(c1 ? z1 : z0);
            ap[3] = f2tf(c1 ? u1 : u0);
            #pragma unroll
            for (int nt = 0; nt < 8; nt++) {
                const uint32_t* vr = VT + (8 * nt + g) * KVPAD;
                const uint2 vv = *reinterpret_cast<const uint2*>(vr + 8 * kk + 2 * t);
                mma8(o[nt], ap, vv.x, vv.y);
            }
        }
        __syncthreads();   // all warps done reading this buffer before reuse
    }

    // ---- finalize (write RNA-pre-rounded for the output-proj GEMM) ----
    l0 += __shfl_xor_sync(0xffffffffu, l0, 1);
    l0 += __shfl_xor_sync(0xffffffffu, l0, 2);
    l1 += __shfl_xor_sync(0xffffffffu, l1, 1);
    l1 += __shfl_xor_sync(0xffffffffu, l1, 2);
    const float i0 = 1.f / l0, i1 = 1.f / l1;

    float* o0p = oh + hoff + (size_t)rg0 * HDIM;
    float* o1p = oh + hoff + (size_t)rg1 * HDIM;
    #pragma unroll
    for (int nt = 0; nt < 8; nt++) {
        const int d = 8 * nt + 2 * t;
        *reinterpret_cast<float2*>(o0p + d) =
            make_float2(rnd_tf(o[nt][0] * i0), rnd_tf(o[nt][1] * i0));
        *reinterpret_cast<float2*>(o1p + d) =
            make_float2(rnd_tf(o[nt][2] * i1), rnd_tf(o[nt][3] * i1));
    }
}

// ---------------------------------------------------------------------------
// kernel_launch
// Inputs: 0=q 1=k 2=v 3=mask 4=Wq 5=bq 6=Wk 7=bk 8=Wv 9=bv 10=Wo 11=bo
// Output: [out (B,S,D)] [kh (B,H,S,HD)] [vh (B,H,S,HD)]
// ---------------------------------------------------------------------------
extern "C" void kernel_launch(void* const* d_in, const int* in_sizes, int n_in,
                              void* d_out, int out_size)
{
    const float* q  = (const float*)d_in[0];
    const float* k  = (const float*)d_in[1];
    const float* v  = (const float*)d_in[2];
    const float* Wq = (const float*)d_in[4];
    const float* bq = (const float*)d_in[5];
    const float* Wk = (const float*)d_in[6];
    const float* bk = (const float*)d_in[7];
    const float* Wv = (const float*)d_in[8];
    const float* bv = (const float*)d_in[9];
    const float* Wo = (const float*)d_in[10];
    const float* bo = (const float*)d_in[11];

    float* out = (float*)d_out;
    float* khp = out + HEADTOT;
    float* vhp = khp + HEADTOT;

    float *qh_p = nullptr, *att_p = nullptr, *kt_p = nullptr, *vt_p = nullptr, *wr_p = nullptr;
    cudaGetSymbolAddress((void**)&qh_p, g_qh);
    cudaGetSymbolAddress((void**)&att_p, g_att);
    cudaGetSymbolAddress((void**)&kt_p, g_kt);
    cudaGetSymbolAddress((void**)&vt_p, g_vt);
    cudaGetSymbolAddress((void**)&wr_p, g_wr);

    cudaFuncSetAttribute(gemm_qkv,
                         cudaFuncAttributeMaxDynamicSharedMemorySize, GSMEM_BYTES);
    cudaFuncSetAttribute(gemm_out,
                         cudaFuncAttributeMaxDynamicSharedMemorySize, GSMEM_BYTES);
    cudaFuncSetAttribute(flash_tc,
                         cudaFuncAttributeMaxDynamicSharedMemorySize, FSMEM_BYTES);

    // Pre-round all 4 weight matrices (RNA tf32) -> g_wr
    round_weights<<<4096, 256>>>(Wq, Wk, Wv, Wo, wr_p);

    // Fused Q/K/V projections: grid (8, 64, 3)
    gemm_qkv<<<dim3(DD / 128, MTOT / 128, 3), 256, GSMEM_BYTES>>>(
        q, k, v, wr_p, bq, bk, bv, qh_p, khp, vhp, kt_p, vt_p);

    flash_tc<<<dim3(32, HH, BB), 128, FSMEM_BYTES>>>(qh_p, kt_p, vt_p, att_p);

    gemm_out<<<dim3(DD / 128, MTOT / 128), 256, GSMEM_BYTES>>>(
        att_p, wr_p + 3 * DD * DD, bo, out);
}

// round 16
// speedup vs baseline: 6.5344x; 1.1343x over previous
#include <cuda_runtime.h>
#include <math.h>
#include <stdint.h>

// Problem constants
#define BB 4
#define SS 2048
#define DD 1024
#define HH 16
#define HDIM 64
#define MTOT (BB * SS)                          // 8192
#define HEADTOT ((size_t)BB * HH * SS * HDIM)   // 8,388,608

// Scratch
__device__ float g_qh[BB * HH * SS * HDIM];
__device__ float g_att[BB * HH * SS * HDIM];    // RNA-pre-rounded by flash epilogue
__device__ float g_kt[BB * HH * SS * HDIM];     // K head-layout, RNA-rounded, d-permuted
__device__ float g_vt[BB * HH * HDIM * SS];     // V^T [b][h][d][s], RNA-rounded, s-permuted
__device__ float g_wr[4 * DD * DD];             // Wq,Wk,Wv,Wo RNA-pre-rounded

__device__ __forceinline__ uint32_t smem_u32(const void* p) {
    uint32_t a;
    asm("{ .reg .u64 t; cvta.to.shared.u64 t, %1; cvt.u32.u64 %0, t; }"
        : "=r"(a) : "l"(p));
    return a;
}

__device__ __forceinline__ uint32_t f2tf(float f) {
    uint32_t u;
    asm("cvt.rna.tf32.f32 %0, %1;" : "=r"(u) : "f"(f));
    return u;
}

__device__ __forceinline__ float rnd_tf(float f) {
    return __uint_as_float(f2tf(f));
}

// k-slot pairing permutation within 8-groups: p(j) = (j&3)*2 + (j>>2).
__device__ __forceinline__ int kperm(int j) { return ((j & 3) << 1) | (j >> 2); }

__device__ __forceinline__ void mma8(float* c, const uint32_t* a,
                                     uint32_t b0, uint32_t b1) {
    asm volatile(
        "mma.sync.aligned.m16n8k8.row.col.f32.tf32.tf32.f32 "
        "{%0,%1,%2,%3}, {%4,%5,%6,%7}, {%8,%9}, {%0,%1,%2,%3};"
        : "+f"(c[0]), "+f"(c[1]), "+f"(c[2]), "+f"(c[3])
        : "r"(a[0]), "r"(a[1]), "r"(a[2]), "r"(a[3]), "r"(b0), "r"(b1));
}

__device__ __forceinline__ void ldsm4(uint32_t& d0, uint32_t& d1,
                                      uint32_t& d2, uint32_t& d3, uint32_t addr) {
    asm volatile(
        "ldmatrix.sync.aligned.m8n8.x4.shared.b16 {%0,%1,%2,%3}, [%4];"
        : "=r"(d0), "=r"(d1), "=r"(d2), "=r"(d3) : "r"(addr));
}

// exp2(z) for z <= 0, FMA-pipe only (no MUFU). ~5e-5 rel err.
__device__ __forceinline__ float exp2p(float z) {
    z = fmaxf(z, -100.f);
    float k = z + 12582912.f;            // 1.5*2^23: round-to-nearest-int
    int nb = __float_as_int(k);
    float f = z - (k - 12582912.f);      // f in [-0.5, 0.5]
    float p = 0.00961813f;
    p = fmaf(p, f, 0.05550410f);
    p = fmaf(p, f, 0.24022651f);
    p = fmaf(p, f, 0.69314718f);
    p = fmaf(p, f, 1.0f);
    return p * __int_as_float((nb << 23) + 0x3F800000);
}

// ---------------------------------------------------------------------------
// Pre-round the 4 weight matrices (RNA tf32) into g_wr.
// ---------------------------------------------------------------------------
__global__ void __launch_bounds__(256) round_weights(
    const float* __restrict__ w0, const float* __restrict__ w1,
    const float* __restrict__ w2, const float* __restrict__ w3,
    float* __restrict__ dst)
{
    const int idx = blockIdx.x * 256 + threadIdx.x;   // one float4 each
    const int per = DD * DD / 4;                      // 262144
    const int m = idx / per, off = (idx - m * per) * 4;
    const float* src = (m == 0) ? w0 : (m == 1) ? w1 : (m == 2) ? w2 : w3;
    float4 v = *reinterpret_cast<const float4*>(src + off);
    v.x = rnd_tf(v.x); v.y = rnd_tf(v.y); v.z = rnd_tf(v.z); v.w = rnd_tf(v.w);
    *reinterpret_cast<float4*>(dst + (size_t)m * DD * DD + off) = v;
}

// ---------------------------------------------------------------------------
// GEMM core: 128x128 CTA tile, 256 threads = 8 warps of 32x64.
// 3-stage cp.async pipeline (wait_group 1, 2 chunks of prefetch),
// XOR-swizzled pad-free smem tiles (chunk c of row r at c ^ (r&7)),
// ldmatrix.x4 fragment gather. Mainloop unrolled in groups of 3 so stage
// indices/smem bases/wait counts are compile-time literals.
// W must be RNA-pre-rounded (b-frags raw). A_CVT: RNA-cvt a-frags.
// ---------------------------------------------------------------------------
#define GTILEB 16384                        // one tile: 128 rows * 128 B
#define GSTAGEB (2 * GTILEB)                // A + B per stage = 32768
#define GSMEM_BYTES (3 * GSTAGEB)           // 98304

template <bool IN_HEADS, bool A_CVT>
__device__ __forceinline__ void gemm_core(
    const float* __restrict__ X, const float* __restrict__ W,
    float* sm, int m0, int n0, float c[2][8][4])
{
    const int tid = threadIdx.x;
    const int wid = tid >> 5, lane = tid & 31;
    const int wm0 = (wid >> 1) * 32, wn0 = (wid & 1) * 64;
    const uint32_t smbase = smem_u32(sm);

    auto issue_loads = [&](int k0, int s) {
        const uint32_t As = smbase + (uint32_t)(s * GSTAGEB);
        const uint32_t Bs = As + GTILEB;
        #pragma unroll
        for (int it = 0; it < 4; it++) {
            const int idx = it * 256 + tid;
            const int row = idx >> 3;
            const int c4  = idx & 7;
            const int gk  = k0 + c4 * 4;
            const uint32_t soff = (uint32_t)(row * 128 + ((c4 ^ (row & 7)) << 4));
            const float* pa;
            if (IN_HEADS) {
                const int gm = m0 + row;
                const int bb_ = gm >> 11;
                const int ss_ = gm & (SS - 1);
                pa = X + ((((size_t)bb_ * HH + (gk >> 6)) * SS + ss_) << 6) + (gk & 63);
            } else {
                pa = X + (size_t)(m0 + row) * DD + gk;
            }
            asm volatile("cp.async.cg.shared.global [%0], [%1], 16;"
                         :: "r"(As + soff), "l"(pa));
            const float* pb = W + (size_t)(n0 + row) * DD + gk;
            asm volatile("cp.async.cg.shared.global [%0], [%1], 16;"
                         :: "r"(Bs + soff), "l"(pb));
        }
        asm volatile("cp.async.commit_group;" ::: "memory");
    };

    // per-lane ldmatrix geometry: lane supplies row (lane&7) of matrix (lane>>3)
    const int mx = lane >> 3, r8 = lane & 7;
    const uint32_t arow = (uint32_t)((wm0 + ((mx & 1) << 3) + r8) * 128);
    const uint32_t brow = (uint32_t)((wn0 + ((mx >> 1) << 3) + r8) * 128);
    const int cbA = mx >> 1;          // A colblk (k 16B-chunk sub-index)
    const int cbB = mx & 1;           // B colblk

    auto compute = [&](int s) {
        const uint32_t As = smbase + (uint32_t)(s * GSTAGEB);
        const uint32_t Bs = As + GTILEB;
        #pragma unroll
        for (int ks = 0; ks < 4; ks++) {
            const uint32_t achk = (uint32_t)((((ks * 2 + cbA) ^ r8) << 4));
            const uint32_t bchk = (uint32_t)((((ks * 2 + cbB) ^ r8) << 4));
            uint32_t a[2][4], b[8][2];
            #pragma unroll
            for (int i = 0; i < 2; i++) {
                ldsm4(a[i][0], a[i][1], a[i][2], a[i][3],
                      As + arow + (uint32_t)(i * 2048) + achk);
                if (A_CVT) {
                    a[i][0] = f2tf(__uint_as_float(a[i][0]));
                    a[i][1] = f2tf(__uint_as_float(a[i][1]));
                    a[i][2] = f2tf(__uint_as_float(a[i][2]));
                    a[i][3] = f2tf(__uint_as_float(a[i][3]));
                }
            }
            #pragma unroll
            for (int jp = 0; jp < 4; jp++) {
                ldsm4(b[2 * jp][0], b[2 * jp][1], b[2 * jp + 1][0], b[2 * jp + 1][1],
                      Bs + brow + (uint32_t)(jp * 2048) + bchk);
            }
            #pragma unroll
            for (int i = 0; i < 2; i++)
                #pragma unroll
                for (int j = 0; j < 8; j++)
                    mma8(c[i][j], a[i], b[j][0], b[j][1]);
        }
    };

    // chunk ck lives in stage ck % 3; static stage indices via 3-unroll.
    auto proc = [&](int ck, int s, bool last) {
        if (last) {
            asm volatile("cp.async.wait_group 0;" ::: "memory");
        } else {
            asm volatile("cp.async.wait_group 1;" ::: "memory");
        }
        __syncthreads();
        if (ck + 2 < 32) issue_loads((ck + 2) * 32, (s + 2) % 3);
        compute(s);
    };

    issue_loads(0, 0);
    issue_loads(32, 1);
    for (int cb = 0; cb < 30; cb += 3) {
        proc(cb + 0, 0, false);
        proc(cb + 1, 1, false);
        proc(cb + 2, 2, false);
    }
    proc(30, 0, false);
    proc(31, 1, true);
    __syncthreads();
}

// ---------------------------------------------------------------------------
// Fused Q/K/V projection GEMM: grid.z selects {0:Q, 1:K, 2:V}.
// ---------------------------------------------------------------------------
__global__ void __launch_bounds__(256, 2) gemm_qkv(
    const float* __restrict__ xq, const float* __restrict__ xk,
    const float* __restrict__ xv, const float* __restrict__ wr,
    const float* __restrict__ bq, const float* __restrict__ bk,
    const float* __restrict__ bv,
    float* __restrict__ yq, float* __restrict__ yk, float* __restrict__ yv,
    float* __restrict__ ktp, float* __restrict__ vtp)
{
    extern __shared__ float sm[];
    const int z = blockIdx.z;
    const int m0 = blockIdx.y * 128, n0 = blockIdx.x * 128;
    const float* X = (z == 0) ? xq : (z == 1) ? xk : xv;
    const float* W = wr + (size_t)z * DD * DD;
    const float* bias = (z == 0) ? bq : (z == 1) ? bk : bv;
    float* Y = (z == 0) ? yq : (z == 1) ? yk : yv;

    float c[2][8][4];
    #pragma unroll
    for (int i = 0; i < 2; i++)
        #pragma unroll
        for (int j = 0; j < 8; j++)
            #pragma unroll
            for (int r = 0; r < 4; r++) c[i][j][r] = 0.f;

    gemm_core<false, true>(X, W, sm, m0, n0, c);

    const int tid = threadIdx.x;
    const int wid = tid >> 5, lane = tid & 31;
    const int g = lane >> 2, t = lane & 3;
    const int wm0 = (wid >> 1) * 32, wn0 = (wid & 1) * 64;

    const int px = kperm(2 * t);
    const int py = kperm(2 * t + 1);
    const int pg = kperm(g);

    #pragma unroll
    for (int i = 0; i < 2; i++) {
        const int r0 = m0 + wm0 + 16 * i + g;
        const int r1 = r0 + 8;
        #pragma unroll
        for (int j = 0; j < 8; j++) {
            const int gn = n0 + wn0 + 8 * j + 2 * t;
            const float bx = __ldg(bias + gn);
            const float by = __ldg(bias + gn + 1);
            float2 o0 = make_float2(c[i][j][0] + bx, c[i][j][1] + by);
            float2 o1 = make_float2(c[i][j][2] + bx, c[i][j][3] + by);
            const int hb = gn >> 6, hc = gn & 63;
            const int b0_ = r0 >> 11, s0_ = r0 & (SS - 1);
            const int b1_ = r1 >> 11, s1_ = r1 & (SS - 1);
            const size_t y0 = ((((size_t)b0_ * HH + hb) * SS + s0_) << 6) + hc;
            const size_t y1 = ((((size_t)b1_ * HH + hb) * SS + s1_) << 6) + hc;
            *reinterpret_cast<float2*>(Y + y0) = o0;
            *reinterpret_cast<float2*>(Y + y1) = o1;
            if (z == 1) {
                // K copy, pre-rounded, d permuted within 8-groups
                const size_t base0 = y0 - (hc & 7);   // hc&7 == 2t
                const size_t base1 = y1 - (hc & 7);
                ktp[base0 + px] = rnd_tf(o0.x);
                ktp[base0 + py] = rnd_tf(o0.y);
                ktp[base1 + px] = rnd_tf(o1.x);
                ktp[base1 + py] = rnd_tf(o1.y);
            } else if (z == 2) {
                // V^T copy, pre-rounded, s permuted within 8-groups
                const int s0p = (s0_ & ~7) | pg;
                const int s1p = (s1_ & ~7) | pg;
                float* yt0 = vtp + (((size_t)b0_ * HH + hb) * HDIM + hc) * SS + s0p;
                float* yt1 = vtp + (((size_t)b1_ * HH + hb) * HDIM + hc) * SS + s1p;
                yt0[0] = rnd_tf(o0.x); yt0[SS] = rnd_tf(o0.y);
                yt1[0] = rnd_tf(o1.x); yt1[SS] = rnd_tf(o1.y);
            }
        }
    }
}

// ---------------------------------------------------------------------------
// Output-projection GEMM: head-layout in (pre-rounded), flat out.
// ---------------------------------------------------------------------------
__global__ void __launch_bounds__(256, 2) gemm_out(
    const float* __restrict__ X, const float* __restrict__ W,
    const float* __restrict__ bias, float* __restrict__ Y)
{
    extern __shared__ float sm[];
    const int m0 = blockIdx.y * 128, n0 = blockIdx.x * 128;

    float c[2][8][4];
    #pragma unroll
    for (int i = 0; i < 2; i++)
        #pragma unroll
        for (int j = 0; j < 8; j++)
            #pragma unroll
            for (int r = 0; r < 4; r++) c[i][j][r] = 0.f;

    gemm_core<true, false>(X, W, sm, m0, n0, c);

    const int tid = threadIdx.x;
    const int wid = tid >> 5, lane = tid & 31;
    const int g = lane >> 2, t = lane & 3;
    const int wm0 = (wid >> 1) * 32, wn0 = (wid & 1) * 64;

    #pragma unroll
    for (int i = 0; i < 2; i++) {
        const int r0 = m0 + wm0 + 16 * i + g;
        const int r1 = r0 + 8;
        #pragma unroll
        for (int j = 0; j < 8; j++) {
            const int gn = n0 + wn0 + 8 * j + 2 * t;
            const float bx = __ldg(bias + gn);
            const float by = __ldg(bias + gn + 1);
            *reinterpret_cast<float2*>(Y + (size_t)r0 * DD + gn) =
                make_float2(c[i][j][0] + bx, c[i][j][1] + by);
            *reinterpret_cast<float2*>(Y + (size_t)r1 * DD + gn) =
                make_float2(c[i][j][2] + bx, c[i][j][3] + by);
        }
    }
}

// ---------------------------------------------------------------------------
// Tensor-core causal flash attention v3 (unchanged).
// ---------------------------------------------------------------------------
#define KVPAD 72
#define KVTILE (64 * KVPAD)
#define FSMEM_BYTES (4 * KVTILE * 4)   // 73728

__global__ void __launch_bounds__(128, 3) flash_tc(
    const float* __restrict__ qh, const float* __restrict__ kt,
    const float* __restrict__ vt, float* __restrict__ oh)
{
    extern __shared__ float fsm[];
    float* Kb = fsm;                    // [2][64][KVPAD] K[key][d_perm]
    float* Vb = fsm + 2 * KVTILE;       // [2][64][KVPAD] V^T[d][key_perm]

    const int tid = threadIdx.x;
    const int w = tid >> 5, lane = tid & 31;
    const int g = lane >> 2, t = lane & 3;
    const int qi = 31 - (int)blockIdx.x;      // biggest blocks first
    const int h = blockIdx.y, b = blockIdx.z;
    const size_t hoff = ((size_t)b * HH + h) * SS * HDIM;
    const float* vtb = vt + ((size_t)b * HH + h) * HDIM * SS;
    const int q0 = qi * 64;
    const float CLOG = 0.18033688011112042f;  // 0.125 * log2(e)

    const int sr = tid >> 4;            // staging base row (0..7), step 8
    const int sc = (tid & 15) * 4;      // 16B column group

    auto issue_tile = [&](int jt, int buf) {
        float* kd = Kb + buf * KVTILE;
        float* vd = Vb + buf * KVTILE;
        const int kb = jt * 64;
        #pragma unroll
        for (int i = 0; i < 8; i++) {
            const int r = sr + i * 8;
            const float* ks = kt + hoff + (size_t)(kb + r) * HDIM + sc;
            const float* vs = vtb + (size_t)r * SS + kb + sc;
            asm volatile("cp.async.cg.shared.global [%0], [%1], 16;"
                         :: "r"(smem_u32(kd + r * KVPAD + sc)), "l"(ks));
            asm volatile("cp.async.cg.shared.global [%0], [%1], 16;"
                         :: "r"(smem_u32(vd + r * KVPAD + sc)), "l"(vs));
        }
        asm volatile("cp.async.commit_group;" ::: "memory");
    };

    issue_tile(0, 0);   // prefetch tile 0 immediately

    const int rg0 = q0 + w * 16 + g;    // global q row for c0/c1
    const int rg1 = rg0 + 8;            // global q row for c2/c3

    // ---- Q a-frags straight from gmem (single RNA tf32) ----
    uint32_t qf[8][4];
    {
        const float* q0p = qh + hoff + (size_t)rg0 * HDIM;
        const float* q1p = qh + hoff + (size_t)rg1 * HDIM;
        #pragma unroll
        for (int ks = 0; ks < 8; ks++) {
            qf[ks][0] = f2tf(q0p[8 * ks + t]);
            qf[ks][1] = f2tf(q1p[8 * ks + t]);
            qf[ks][2] = f2tf(q0p[8 * ks + t + 4]);
            qf[ks][3] = f2tf(q1p[8 * ks + t + 4]);
        }
    }

    float o[8][4];
    #pragma unroll
    for (int nt = 0; nt < 8; nt++)
        #pragma unroll
        for (int r = 0; r < 4; r++) o[nt][r] = 0.f;
    float mx0 = -1e30f, mx1 = -1e30f, l0 = 0.f, l1 = 0.f;

    const int srcA = 4 * g + (t >> 1);  // P-exchange source lanes (quad)
    const int srcB = srcA + 2;
    const bool c1 = (t & 1);

    for (int jt = 0; jt <= qi; jt++) {
        const int kb = jt * 64;
        const int buf = jt & 1;

        if (jt < qi) {
            issue_tile(jt + 1, buf ^ 1);
            asm volatile("cp.async.wait_group 1;" ::: "memory");
        } else {
            asm volatile("cp.async.wait_group 0;" ::: "memory");
        }
        __syncthreads();

        const uint32_t* Kt = reinterpret_cast<const uint32_t*>(Kb + buf * KVTILE);
        const uint32_t* VT = reinterpret_cast<const uint32_t*>(Vb + buf * KVTILE);

        // ---- scores S = Q K^T (single tf32; b-frags LDS.64 pairs) ----
        float s[8][4];
        #pragma unroll
        for (int nt = 0; nt < 8; nt++) {
            s[nt][0] = s[nt][1] = s[nt][2] = s[nt][3] = 0.f;
            const uint32_t* kr = Kt + (8 * nt + g) * KVPAD;
            #pragma unroll
            for (int ks = 0; ks < 8; ks++) {
                const uint2 kb2 = *reinterpret_cast<const uint2*>(kr + 8 * ks + 2 * t);
                mma8(s[nt], qf[ks], kb2.x, kb2.y);
            }
        }

        // ---- causal mask (diagonal tile only) ----
        if (jt == qi) {
            #pragma unroll
            for (int nt = 0; nt < 8; nt++) {
                const int col = kb + 8 * nt + 2 * t;
                if (col > rg0)     s[nt][0] = -1e30f;
                if (col + 1 > rg0) s[nt][1] = -1e30f;
                if (col > rg1)     s[nt][2] = -1e30f;
                if (col + 1 > rg1) s[nt][3] = -1e30f;
            }
        }

        // ---- online softmax (in place: s -> p) ----
        float sm0 = -1e30f, sm1 = -1e30f;
        #pragma unroll
        for (int nt = 0; nt < 8; nt++) {
            sm0 = fmaxf(sm0, fmaxf(s[nt][0], s[nt][1]));
            sm1 = fmaxf(sm1, fmaxf(s[nt][2], s[nt][3]));
        }
        sm0 = fmaxf(sm0, __shfl_xor_sync(0xffffffffu, sm0, 1));
        sm0 = fmaxf(sm0, __shfl_xor_sync(0xffffffffu, sm0, 2));
        sm1 = fmaxf(sm1, __shfl_xor_sync(0xffffffffu, sm1, 1));
        sm1 = fmaxf(sm1, __shfl_xor_sync(0xffffffffu, sm1, 2));

        const float nm0 = fmaxf(mx0, sm0), nm1 = fmaxf(mx1, sm1);
        const float f0 = exp2p((mx0 - nm0) * CLOG);
        const float f1 = exp2p((mx1 - nm1) * CLOG);
        mx0 = nm0; mx1 = nm1;
        l0 *= f0; l1 *= f1;
        #pragma unroll
        for (int nt = 0; nt < 8; nt++) {
            o[nt][0] *= f0; o[nt][1] *= f0;
            o[nt][2] *= f1; o[nt][3] *= f1;
        }

        #pragma unroll
        for (int nt = 0; nt < 8; nt++) {
            s[nt][0] = exp2p((s[nt][0] - mx0) * CLOG);
            s[nt][1] = exp2p((s[nt][1] - mx0) * CLOG);
            s[nt][2] = exp2p((s[nt][2] - mx1) * CLOG);
            s[nt][3] = exp2p((s[nt][3] - mx1) * CLOG);
            l0 += s[nt][0] + s[nt][1];
            l1 += s[nt][2] + s[nt][3];
        }

        // ---- O += P V : a-frags via quad shuffles of register P ----
        #pragma unroll
        for (int kk = 0; kk < 8; kk++) {
            const float x0 = __shfl_sync(0xffffffffu, s[kk][0], srcA);
            const float x1 = __shfl_sync(0xffffffffu, s[kk][1], srcA);
            const float y0 = __shfl_sync(0xffffffffu, s[kk][2], srcA);
            const float y1 = __shfl_sync(0xffffffffu, s[kk][3], srcA);
            const float z0 = __shfl_sync(0xffffffffu, s[kk][0], srcB);
            const float z1 = __shfl_sync(0xffffffffu, s[kk][1], srcB);
            const float u0 = __shfl_sync(0xffffffffu, s[kk][2], srcB);
            const float u1 = __shfl_sync(0xffffffffu, s[kk][3], srcB);
            uint32_t ap[4];
            ap[0] = f2tf(c1 ? x1 : x0);
            ap[1] = f2tf(c1 ? y1 : y0);
            ap[2] = f2tf(c1 ? z1 : z0);
            ap[3] = f2tf(c1 ? u1 : u0);
            #pragma unroll
            for (int nt = 0; nt < 8; nt++) {
                const uint32_t* vr = VT + (8 * nt + g) * KVPAD;
                const uint2 vv = *reinterpret_cast<const uint2*>(vr + 8 * kk + 2 * t);
                mma8(o[nt], ap, vv.x, vv.y);
            }
        }
        __syncthreads();   // all warps done reading this buffer before reuse
    }

    // ---- finalize (write RNA-pre-rounded for the output-proj GEMM) ----
    l0 += __shfl_xor_sync(0xffffffffu, l0, 1);
    l0 += __shfl_xor_sync(0xffffffffu, l0, 2);
    l1 += __shfl_xor_sync(0xffffffffu, l1, 1);
    l1 += __shfl_xor_sync(0xffffffffu, l1, 2);
    const float i0 = 1.f / l0, i1 = 1.f / l1;

    float* o0p = oh + hoff + (size_t)rg0 * HDIM;
    float* o1p = oh + hoff + (size_t)rg1 * HDIM;
    #pragma unroll
    for (int nt = 0; nt < 8; nt++) {
        const int d = 8 * nt + 2 * t;
        *reinterpret_cast<float2*>(o0p + d) =
            make_float2(rnd_tf(o[nt][0] * i0), rnd_tf(o[nt][1] * i0));
        *reinterpret_cast<float2*>(o1p + d) =
            make_float2(rnd_tf(o[nt][2] * i1), rnd_tf(o[nt][3] * i1));
    }
}

// ---------------------------------------------------------------------------
// kernel_launch
// Inputs: 0=q 1=k 2=v 3=mask 4=Wq 5=bq 6=Wk 7=bk 8=Wv 9=bv 10=Wo 11=bo
// Output: [out (B,S,D)] [kh (B,H,S,HD)] [vh (B,H,S,HD)]
// ---------------------------------------------------------------------------
extern "C" void kernel_launch(void* const* d_in, const int* in_sizes, int n_in,
                              void* d_out, int out_size)
{
    const float* q  = (const float*)d_in[0];
    const float* k  = (const float*)d_in[1];
    const float* v  = (const float*)d_in[2];
    const float* Wq = (const float*)d_in[4];
    const float* bq = (const float*)d_in[5];
    const float* Wk = (const float*)d_in[6];
    const float* bk = (const float*)d_in[7];
    const float* Wv = (const float*)d_in[8];
    const float* bv = (const float*)d_in[9];
    const float* Wo = (const float*)d_in[10];
    const float* bo = (const float*)d_in[11];

    float* out = (float*)d_out;
    float* khp = out + HEADTOT;
    float* vhp = khp + HEADTOT;

    float *qh_p = nullptr, *att_p = nullptr, *kt_p = nullptr, *vt_p = nullptr, *wr_p = nullptr;
    cudaGetSymbolAddress((void**)&qh_p, g_qh);
    cudaGetSymbolAddress((void**)&att_p, g_att);
    cudaGetSymbolAddress((void**)&kt_p, g_kt);
    cudaGetSymbolAddress((void**)&vt_p, g_vt);
    cudaGetSymbolAddress((void**)&wr_p, g_wr);

    cudaFuncSetAttribute(gemm_qkv,
                         cudaFuncAttributeMaxDynamicSharedMemorySize, GSMEM_BYTES);
    cudaFuncSetAttribute(gemm_out,
                         cudaFuncAttributeMaxDynamicSharedMemorySize, GSMEM_BYTES);
    cudaFuncSetAttribute(flash_tc,
                         cudaFuncAttributeMaxDynamicSharedMemorySize, FSMEM_BYTES);

    // Pre-round all 4 weight matrices (RNA tf32) -> g_wr
    round_weights<<<4096, 256>>>(Wq, Wk, Wv, Wo, wr_p);

    // Fused Q/K/V projections: grid (8, 64, 3)
    gemm_qkv<<<dim3(DD / 128, MTOT / 128, 3), 256, GSMEM_BYTES>>>(
        q, k, v, wr_p, bq, bk, bv, qh_p, khp, vhp, kt_p, vt_p);

    flash_tc<<<dim3(32, HH, BB), 128, FSMEM_BYTES>>>(qh_p, kt_p, vt_p, att_p);

    gemm_out<<<dim3(DD / 128, MTOT / 128), 256, GSMEM_BYTES>>>(
        att_p, wr_p + 3 * DD * DD, bo, out);
}